// round 1
// baseline (speedup 1.0000x reference)
#include <cuda_runtime.h>
#include <math.h>

// ---------------------------------------------------------------------------
// Problem constants
//   B=4096, IN_DIM=1024, D=128, C=10000, H=4, HD=32, EXP=4
//   Attention has seq_len == 1 -> softmax == 1 -> attn == v. q,k are dead.
// Output tuple: (hyp_logits[B,C], euc_logits[B,C], emb[B,D]) concatenated.
// ---------------------------------------------------------------------------

#define NB   4096
#define NIN  1024
#define ND   128
#define NC   10000

// ------------------------- device scratch (no allocs) ----------------------
__device__ float g_t1[NB * 256];   // gelu(x@W1+b1)
__device__ float g_t [NB * ND];    // t = t1@W2+b2
__device__ float g_v [NB * ND];    // v projection
__device__ float g_ao[NB * ND];    // attn out proj
__device__ float g_xs[NB * ND];    // ln1(t+ao)
__device__ float g_h [NB * 512];   // gelu(xs@fw1+fb1)
__device__ float g_f [NB * ND];    // h@fw2+fb2
__device__ float g_t2[NB * ND];    // ln2(xs+f)  (== final t)
__device__ float g_e2[NB];
__device__ float g_de[NB];
__device__ float g_pr[NC * ND];    // scaled prototypes
__device__ float g_p2[NC];
__device__ float g_dp[NC];

// ------------------------------ helpers ------------------------------------
static __device__ __forceinline__ float gelu_exact(float x) {
    return 0.5f * x * (1.0f + erff(x * 0.70710678118654752440f));
}

static __device__ __forceinline__ float block_sum_128(float v) {
    __shared__ float sh[4];
    int lane = threadIdx.x & 31;
    int wid  = threadIdx.x >> 5;
#pragma unroll
    for (int o = 16; o > 0; o >>= 1)
        v += __shfl_down_sync(0xffffffffu, v, o);
    __syncthreads();           // protect sh from previous use
    if (lane == 0) sh[wid] = v;
    __syncthreads();
    return sh[0] + sh[1] + sh[2] + sh[3];
}

static __device__ __forceinline__ void curvature(const float* logc, float& c, float& sc) {
    float cc = expf(logc[0]);
    cc = fminf(fmaxf(cc, 1e-4f), 10.0f);
    cc = fmaxf(fabsf(cc), 1e-6f);
    c  = cc;
    sc = sqrtf(cc);
}

// ----------------------- generic tiled SGEMM + bias (+gelu) ----------------
// C[M,N] = act(A[M,K] @ B[K,N] + bias[N])
// BM=BN=64, BK=32, 256 threads, 4x4 micro-tile. M,N multiples of 64, K of 32.
template <int ACT>
__global__ void __launch_bounds__(256) sgemm_bias(
    const float* __restrict__ A, int lda,
    const float* __restrict__ Bm, int ldb,
    const float* __restrict__ bias,
    float* __restrict__ C, int ldc,
    int K)
{
    __shared__ float As[32][68];   // [k][m], padded
    __shared__ float Bs[32][68];   // [k][n], padded

    const int tid = threadIdx.x;
    const int tx = tid & 15, ty = tid >> 4;
    const int m0 = blockIdx.y * 64, n0 = blockIdx.x * 64;
    const int ar = tid >> 3, ac = tid & 7;    // A loads
    const int bk = tid >> 4, bc = tid & 15;   // B loads

    float acc[4][4] = {};

    for (int k0 = 0; k0 < K; k0 += 32) {
#pragma unroll
        for (int it = 0; it < 2; ++it) {
            int row = ar + it * 32;
            float4 va = *(const float4*)(A + (size_t)(m0 + row) * lda + k0 + ac * 4);
            As[ac * 4 + 0][row] = va.x;
            As[ac * 4 + 1][row] = va.y;
            As[ac * 4 + 2][row] = va.z;
            As[ac * 4 + 3][row] = va.w;
        }
#pragma unroll
        for (int it = 0; it < 2; ++it) {
            int kk = bk + it * 16;
            float4 vb = *(const float4*)(Bm + (size_t)(k0 + kk) * ldb + n0 + bc * 4);
            *(float4*)&Bs[kk][bc * 4] = vb;
        }
        __syncthreads();
#pragma unroll
        for (int kk = 0; kk < 32; ++kk) {
            float4 a = *(const float4*)&As[kk][ty * 4];
            float4 b = *(const float4*)&Bs[kk][tx * 4];
            float av[4] = {a.x, a.y, a.z, a.w};
            float bv[4] = {b.x, b.y, b.z, b.w};
#pragma unroll
            for (int i = 0; i < 4; ++i)
#pragma unroll
                for (int j = 0; j < 4; ++j)
                    acc[i][j] = fmaf(av[i], bv[j], acc[i][j]);
        }
        __syncthreads();
    }

#pragma unroll
    for (int i = 0; i < 4; ++i) {
        int row = m0 + ty * 4 + i;
        float4 o;
        float* op = &o.x;
#pragma unroll
        for (int j = 0; j < 4; ++j) {
            float v = acc[i][j] + bias[n0 + tx * 4 + j];
            if (ACT == 1) v = gelu_exact(v);
            op[j] = v;
        }
        *(float4*)(C + (size_t)row * ldc + n0 + tx * 4) = o;
    }
}

// ------------------------- LayerNorm(residual) ------------------------------
__global__ void ln_res(const float* __restrict__ X, const float* __restrict__ R,
                       const float* __restrict__ g, const float* __restrict__ b,
                       float* __restrict__ out)
{
    int row = blockIdx.x, tid = threadIdx.x;
    float x = X[row * ND + tid] + R[row * ND + tid];
    float m = block_sum_128(x) * (1.0f / 128.0f);
    float d = x - m;
    float v = block_sum_128(d * d) * (1.0f / 128.0f);
    out[row * ND + tid] = d * rsqrtf(v + 1e-5f) * g[tid] + b[tid];
}

// ---------------- LN2 + hyperbolic embedding (per row) ---------------------
__global__ void ln2_emb(const float* __restrict__ xs, const float* __restrict__ f,
                        const float* __restrict__ g, const float* __restrict__ b,
                        const float* __restrict__ logc,
                        float* __restrict__ t2, float* __restrict__ emb,
                        float* __restrict__ e2o, float* __restrict__ deo)
{
    int row = blockIdx.x, tid = threadIdx.x;
    float x = xs[row * ND + tid] + f[row * ND + tid];
    float m = block_sum_128(x) * (1.0f / 128.0f);
    float d = x - m;
    float v = block_sum_128(d * d) * (1.0f / 128.0f);
    float y = d * rsqrtf(v + 1e-5f) * g[tid] + b[tid];
    t2[row * ND + tid] = y;

    float c, sc; curvature(logc, c, sc);

    float n2 = block_sum_128(y * y);
    float vn = fmaxf(sqrtf(n2), 1e-10f);
    float e  = tanhf(sc * vn * 0.5f) * y / (sc * vn);
    float en2 = block_sum_128(e * e);
    float en  = sqrtf(en2);
    float maxn = (1.0f - 1e-5f) / sc;
    float scl  = fminf(maxn / fmaxf(en, 1e-6f), 1.0f);
    e *= scl;
    emb[row * ND + tid] = e;
    if (tid == 0) {
        float e2 = en2 * scl * scl;
        e2o[row] = e2;
        deo[row] = 1.0f - c * fminf(e2, 1.0f - 1e-5f);
    }
}

// ---------------------- prototype scaling (per row) ------------------------
__global__ void proto_prep(const float* __restrict__ P, const float* __restrict__ logc,
                           float* __restrict__ Po, float* __restrict__ p2o,
                           float* __restrict__ dpo)
{
    int row = blockIdx.x, tid = threadIdx.x;
    float p = P[row * ND + tid];
    float n2 = block_sum_128(p * p);
    float c, sc; curvature(logc, c, sc);
    float maxn = (1.0f - 1e-5f) / sc;
    float pn = sqrtf(n2);
    float scl = fminf(maxn / fmaxf(pn, 1e-6f), 1.0f);
    p *= scl;
    Po[row * ND + tid] = p;
    if (tid == 0) {
        float p2 = n2 * scl * scl;
        p2o[row] = p2;
        dpo[row] = 1.0f - c * fminf(p2, 1.0f - 1e-5f);
    }
}

// -------- fused dual GEMM: emb@protosT (-> hyp dist) + t2@euc_w (+bias) ----
__global__ void __launch_bounds__(256) big_dual(
    const float* __restrict__ Aemb, const float* __restrict__ At2,
    const float* __restrict__ Pr,   const float* __restrict__ Ew,
    const float* __restrict__ eb,
    const float* __restrict__ e2v,  const float* __restrict__ dev,
    const float* __restrict__ p2v,  const float* __restrict__ dpv,
    const float* __restrict__ logc,
    float* __restrict__ hyp, float* __restrict__ euc)
{
    __shared__ float Ae[32][68];
    __shared__ float Atile[32][68];
    __shared__ float Bp[32][68];
    __shared__ float Be[32][68];

    const int tid = threadIdx.x;
    const int tx = tid & 15, ty = tid >> 4;
    const int m0 = blockIdx.y * 64, c0 = blockIdx.x * 64;
    const int ar = tid >> 3, ac = tid & 7;
    const int bk = tid >> 4, bc = tid & 15;

    float accp[4][4] = {};
    float acce[4][4] = {};

    for (int k0 = 0; k0 < ND; k0 += 32) {
#pragma unroll
        for (int it = 0; it < 2; ++it) {
            int row = ar + it * 32;
            float4 va = *(const float4*)(Aemb + (size_t)(m0 + row) * ND + k0 + ac * 4);
            Ae[ac * 4 + 0][row] = va.x; Ae[ac * 4 + 1][row] = va.y;
            Ae[ac * 4 + 2][row] = va.z; Ae[ac * 4 + 3][row] = va.w;
            float4 vt = *(const float4*)(At2 + (size_t)(m0 + row) * ND + k0 + ac * 4);
            Atile[ac * 4 + 0][row] = vt.x; Atile[ac * 4 + 1][row] = vt.y;
            Atile[ac * 4 + 2][row] = vt.z; Atile[ac * 4 + 3][row] = vt.w;
            int pc = c0 + row;
            float4 vp = (pc < NC) ? *(const float4*)(Pr + (size_t)pc * ND + k0 + ac * 4)
                                  : make_float4(0.f, 0.f, 0.f, 0.f);
            Bp[ac * 4 + 0][row] = vp.x; Bp[ac * 4 + 1][row] = vp.y;
            Bp[ac * 4 + 2][row] = vp.z; Bp[ac * 4 + 3][row] = vp.w;
        }
#pragma unroll
        for (int it = 0; it < 2; ++it) {
            int kk = bk + it * 16;
            int col = c0 + bc * 4;
            float4 vb = (col < NC) ? *(const float4*)(Ew + (size_t)(k0 + kk) * NC + col)
                                   : make_float4(0.f, 0.f, 0.f, 0.f);
            *(float4*)&Be[kk][bc * 4] = vb;
        }
        __syncthreads();
#pragma unroll
        for (int kk = 0; kk < 32; ++kk) {
            float4 a1 = *(const float4*)&Ae[kk][ty * 4];
            float4 a2 = *(const float4*)&Atile[kk][ty * 4];
            float4 b1 = *(const float4*)&Bp[kk][tx * 4];
            float4 b2 = *(const float4*)&Be[kk][tx * 4];
            float a1v[4] = {a1.x, a1.y, a1.z, a1.w};
            float a2v[4] = {a2.x, a2.y, a2.z, a2.w};
            float b1v[4] = {b1.x, b1.y, b1.z, b1.w};
            float b2v[4] = {b2.x, b2.y, b2.z, b2.w};
#pragma unroll
            for (int i = 0; i < 4; ++i)
#pragma unroll
                for (int j = 0; j < 4; ++j) {
                    accp[i][j] = fmaf(a1v[i], b1v[j], accp[i][j]);
                    acce[i][j] = fmaf(a2v[i], b2v[j], acce[i][j]);
                }
        }
        __syncthreads();
    }

    // ---- epilogue: hyperbolic distance + euclid logits ----
    float c, sc; curvature(logc, c, sc);
    const float two_over_sc = 2.0f / sc;

    const int col4 = c0 + tx * 4;           // NC % 4 == 0: whole float4 valid or not
    if (col4 < NC) {
        float p2c[4], dpc[4], ebc[4];
#pragma unroll
        for (int j = 0; j < 4; ++j) { p2c[j] = p2v[col4 + j]; dpc[j] = dpv[col4 + j]; ebc[j] = eb[col4 + j]; }
#pragma unroll
        for (int i = 0; i < 4; ++i) {
            int row = m0 + ty * 4 + i;
            float e2r = e2v[row], der = dev[row];
            float4 oh, oe;
            float* ohp = &oh.x; float* oep = &oe.x;
#pragma unroll
            for (int j = 0; j < 4; ++j) {
                float diff = fmaxf(e2r + p2c[j] - 2.0f * accp[i][j], 1e-10f);
                float den  = fmaxf(der * dpc[j], 1e-6f);
                float arg  = fmaxf(1.0f + 2.0f * diff / den, 1.0f + 1e-6f);
                ohp[j] = -two_over_sc * acoshf(arg);
                oep[j] = acce[i][j] + ebc[j];
            }
            *(float4*)(hyp + (size_t)row * NC + col4) = oh;
            *(float4*)(euc + (size_t)row * NC + col4) = oe;
        }
    }
}

// ------------------------------- launch -------------------------------------
extern "C" void kernel_launch(void* const* d_in, const int* in_sizes, int n_in,
                              void* d_out, int out_size)
{
    const float* x      = (const float*)d_in[0];
    const float* W1     = (const float*)d_in[1];
    const float* b1     = (const float*)d_in[2];
    const float* W2     = (const float*)d_in[3];
    const float* b2     = (const float*)d_in[4];
    const float* in_w   = (const float*)d_in[5];
    const float* in_b   = (const float*)d_in[6];
    const float* out_w  = (const float*)d_in[7];
    const float* out_b  = (const float*)d_in[8];
    const float* fw1    = (const float*)d_in[9];
    const float* fb1    = (const float*)d_in[10];
    const float* fw2    = (const float*)d_in[11];
    const float* fb2    = (const float*)d_in[12];
    const float* g1     = (const float*)d_in[13];
    const float* bt1    = (const float*)d_in[14];
    const float* g2     = (const float*)d_in[15];
    const float* bt2    = (const float*)d_in[16];
    const float* logc   = (const float*)d_in[17];
    const float* protos = (const float*)d_in[18];
    const float* euc_w  = (const float*)d_in[19];
    const float* euc_b  = (const float*)d_in[20];

    float *t1, *t, *v, *ao, *xs, *h, *f, *t2, *e2, *de, *pr, *p2, *dp;
    cudaGetSymbolAddress((void**)&t1, g_t1);
    cudaGetSymbolAddress((void**)&t,  g_t);
    cudaGetSymbolAddress((void**)&v,  g_v);
    cudaGetSymbolAddress((void**)&ao, g_ao);
    cudaGetSymbolAddress((void**)&xs, g_xs);
    cudaGetSymbolAddress((void**)&h,  g_h);
    cudaGetSymbolAddress((void**)&f,  g_f);
    cudaGetSymbolAddress((void**)&t2, g_t2);
    cudaGetSymbolAddress((void**)&e2, g_e2);
    cudaGetSymbolAddress((void**)&de, g_de);
    cudaGetSymbolAddress((void**)&pr, g_pr);
    cudaGetSymbolAddress((void**)&p2, g_p2);
    cudaGetSymbolAddress((void**)&dp, g_dp);

    float* out = (float*)d_out;
    float* hyp = out;
    float* euc = out + (size_t)NB * NC;
    float* emb = out + (size_t)NB * NC * 2;

    // MLP front-end
    sgemm_bias<1><<<dim3(256 / 64, NB / 64), 256>>>(x, NIN, W1, 256, b1, t1, 256, NIN);
    sgemm_bias<0><<<dim3(ND / 64, NB / 64), 256>>>(t1, 256, W2, ND, b2, t, ND, 256);

    // Attention (seq_len 1 -> attn == v)
    sgemm_bias<0><<<dim3(ND / 64, NB / 64), 256>>>(t, ND, in_w + 2 * ND, 3 * ND,
                                                   in_b + 2 * ND, v, ND, ND);
    sgemm_bias<0><<<dim3(ND / 64, NB / 64), 256>>>(v, ND, out_w, ND, out_b, ao, ND, ND);
    ln_res<<<NB, 128>>>(t, ao, g1, bt1, xs);

    // FFN
    sgemm_bias<1><<<dim3(512 / 64, NB / 64), 256>>>(xs, ND, fw1, 512, fb1, h, 512, ND);
    sgemm_bias<0><<<dim3(ND / 64, NB / 64), 256>>>(h, 512, fw2, ND, fb2, f, ND, 512);

    // LN2 + hyperbolic embedding (emb written straight to output)
    ln2_emb<<<NB, 128>>>(xs, f, g2, bt2, logc, t2, emb, e2, de);

    // Prototype scaling (constant per launch inputs)
    proto_prep<<<NC, 128>>>(protos, logc, pr, p2, dp);

    // Fused dual GEMM + hyperbolic epilogue
    big_dual<<<dim3((NC + 63) / 64, NB / 64), 256>>>(emb, t2, pr, euc_w, euc_b,
                                                     e2, de, p2, dp, logc, hyp, euc);
}

// round 3
// speedup vs baseline: 1.9616x; 1.9616x over previous
#include <cuda_runtime.h>
#include <cuda_bf16.h>
#include <math.h>
#include <stdint.h>

// ---------------------------------------------------------------------------
// B=4096, IN_DIM=1024, D=128, C=10000. seq_len==1 -> attn == v (q,k dead).
// Output: (hyp_logits[B,C], euc_logits[B,C], emb[B,D]) concatenated.
// Big head (2x [4096x128]@[128x10000]) on mma.sync bf16 with hi/lo split K=384.
// Hyperbolic epilogue uses FMA-pipe polynomial log (no MUFU, no division).
// ---------------------------------------------------------------------------

#define NB   4096
#define NIN  1024
#define ND   128
#define NC   10000
#define NC2  10112          // padded to 79*128
#define KEXP 384            // 3 * 128 (hi|lo|hi split)

// ------------------------- device scratch (no allocs) ----------------------
__device__ float g_t1[NB * 256];
__device__ float g_t [NB * ND];
__device__ float g_v [NB * ND];
__device__ float g_ao[NB * ND];
__device__ float g_xs[NB * ND];
__device__ float g_h [NB * 512];
__device__ float g_f [NB * ND];
__device__ float g_e2[NB];
__device__ float g_de[NB];
__device__ uint4 g_A1e[NB  * KEXP / 8];   // emb split, bf16 [NB][KEXP]
__device__ uint4 g_A2e[NB  * KEXP / 8];   // t2  split
__device__ uint4 g_B1e[NC2 * KEXP / 8];   // protos split [NC2][KEXP]
__device__ uint4 g_B2e[NC2 * KEXP / 8];   // euc_w^T split
__device__ float g_p2[NC2];
__device__ float g_dp[NC2];
__device__ float g_eb[NC2];

// ------------------------------ helpers ------------------------------------
static __device__ __forceinline__ uint32_t smem_u32(const void* p) {
    uint32_t a;
    asm("{ .reg .u64 t; cvta.to.shared.u64 t, %1; cvt.u32.u64 %0, t; }" : "=r"(a) : "l"(p));
    return a;
}
static __device__ __forceinline__ void cp_async16(uint32_t s, const void* g) {
    asm volatile("cp.async.cg.shared.global [%0], [%1], 16;" :: "r"(s), "l"(g) : "memory");
}
static __device__ __forceinline__ void ldmx4(uint32_t a, uint32_t& r0, uint32_t& r1,
                                             uint32_t& r2, uint32_t& r3) {
    asm volatile("ldmatrix.sync.aligned.m8n8.x4.shared.b16 {%0,%1,%2,%3}, [%4];"
                 : "=r"(r0), "=r"(r1), "=r"(r2), "=r"(r3) : "r"(a));
}
static __device__ __forceinline__ void mma_bf16(float* d, const uint32_t* a,
                                                uint32_t b0, uint32_t b1) {
    asm volatile("mma.sync.aligned.m16n8k16.row.col.f32.bf16.bf16.f32 "
                 "{%0,%1,%2,%3}, {%4,%5,%6,%7}, {%8,%9}, {%0,%1,%2,%3};"
                 : "+f"(d[0]), "+f"(d[1]), "+f"(d[2]), "+f"(d[3])
                 : "r"(a[0]), "r"(a[1]), "r"(a[2]), "r"(a[3]), "r"(b0), "r"(b1));
}
static __device__ __forceinline__ float gelu_exact(float x) {
    return 0.5f * x * (1.0f + erff(x * 0.70710678118654752440f));
}
static __device__ __forceinline__ float block_sum_128(float v) {
    __shared__ float sh[4];
    int lane = threadIdx.x & 31, wid = threadIdx.x >> 5;
#pragma unroll
    for (int o = 16; o > 0; o >>= 1) v += __shfl_down_sync(0xffffffffu, v, o);
    __syncthreads();
    if (lane == 0) sh[wid] = v;
    __syncthreads();
    return sh[0] + sh[1] + sh[2] + sh[3];
}
static __device__ __forceinline__ void curvature(const float* logc, float& c, float& sc) {
    float cc = expf(logc[0]);
    cc = fminf(fmaxf(cc, 1e-4f), 10.0f);
    cc = fmaxf(fabsf(cc), 1e-6f);
    c = cc; sc = sqrtf(cc);
}
static __device__ __forceinline__ void split_hl(float x, __nv_bfloat16& h, __nv_bfloat16& l) {
    h = __float2bfloat16(x);
    l = __float2bfloat16(x - __bfloat162float(h));
}
// natural log via FMA-pipe polynomial (no MUFU/div). x > 0, normal range.
static __device__ __forceinline__ float plog(float x) {
    int i = __float_as_int(x);
    int e = (i - 0x3f3504f3) >> 23;          // m in [sqrt(1/2), sqrt(2))
    float m = __int_as_float(i - (e << 23));
    float t = m - 1.0f;
    float p = 0.14285715f;
    p = fmaf(p, t, -0.16666667f);
    p = fmaf(p, t, 0.20000000f);
    p = fmaf(p, t, -0.25000000f);
    p = fmaf(p, t, 0.33333334f);
    p = fmaf(p, t, -0.50000000f);
    p = fmaf(p, t, 1.00000000f);
    p = p * t;
    return fmaf((float)e, 0.69314718055994531f, p);
}

// ----------------------- fp32 SGEMM front-end ------------------------------
template <int ACT>
__global__ void __launch_bounds__(256) sgemm_bias(
    const float* __restrict__ A, int lda, const float* __restrict__ Bm, int ldb,
    const float* __restrict__ bias, float* __restrict__ C, int ldc, int K)
{
    __shared__ float As[32][68];
    __shared__ float Bs[32][68];
    const int tid = threadIdx.x;
    const int tx = tid & 15, ty = tid >> 4;
    const int m0 = blockIdx.y * 64, n0 = blockIdx.x * 64;
    const int ar = tid >> 3, ac = tid & 7;
    const int bk = tid >> 4, bc = tid & 15;
    float acc[4][4] = {};
    for (int k0 = 0; k0 < K; k0 += 32) {
#pragma unroll
        for (int it = 0; it < 2; ++it) {
            int row = ar + it * 32;
            float4 va = *(const float4*)(A + (size_t)(m0 + row) * lda + k0 + ac * 4);
            As[ac*4+0][row] = va.x; As[ac*4+1][row] = va.y;
            As[ac*4+2][row] = va.z; As[ac*4+3][row] = va.w;
        }
#pragma unroll
        for (int it = 0; it < 2; ++it) {
            int kk = bk + it * 16;
            float4 vb = *(const float4*)(Bm + (size_t)(k0 + kk) * ldb + n0 + bc * 4);
            *(float4*)&Bs[kk][bc * 4] = vb;
        }
        __syncthreads();
#pragma unroll
        for (int kk = 0; kk < 32; ++kk) {
            float4 a = *(const float4*)&As[kk][ty * 4];
            float4 b = *(const float4*)&Bs[kk][tx * 4];
            float av[4] = {a.x,a.y,a.z,a.w}, bv[4] = {b.x,b.y,b.z,b.w};
#pragma unroll
            for (int i = 0; i < 4; ++i)
#pragma unroll
                for (int j = 0; j < 4; ++j)
                    acc[i][j] = fmaf(av[i], bv[j], acc[i][j]);
        }
        __syncthreads();
    }
#pragma unroll
    for (int i = 0; i < 4; ++i) {
        int row = m0 + ty * 4 + i;
        float4 o; float* op = &o.x;
#pragma unroll
        for (int j = 0; j < 4; ++j) {
            float v = acc[i][j] + bias[n0 + tx * 4 + j];
            if (ACT == 1) v = gelu_exact(v);
            op[j] = v;
        }
        *(float4*)(C + (size_t)row * ldc + n0 + tx * 4) = o;
    }
}

// ------------------------- LayerNorm(residual) ------------------------------
__global__ void ln_res(const float* __restrict__ X, const float* __restrict__ R,
                       const float* __restrict__ g, const float* __restrict__ b,
                       float* __restrict__ out)
{
    int row = blockIdx.x, tid = threadIdx.x;
    float x = X[row * ND + tid] + R[row * ND + tid];
    float m = block_sum_128(x) * (1.0f / 128.0f);
    float d = x - m;
    float v = block_sum_128(d * d) * (1.0f / 128.0f);
    out[row * ND + tid] = d * rsqrtf(v + 1e-5f) * g[tid] + b[tid];
}

// ------- LN2 + hyperbolic embedding + bf16-split operand emission ----------
__global__ void ln2_emb(const float* __restrict__ xs, const float* __restrict__ f,
                        const float* __restrict__ g, const float* __restrict__ b,
                        const float* __restrict__ logc,
                        float* __restrict__ emb,
                        float* __restrict__ e2o, float* __restrict__ deo)
{
    int row = blockIdx.x, tid = threadIdx.x;
    float x = xs[row * ND + tid] + f[row * ND + tid];
    float m = block_sum_128(x) * (1.0f / 128.0f);
    float d = x - m;
    float v = block_sum_128(d * d) * (1.0f / 128.0f);
    float y = d * rsqrtf(v + 1e-5f) * g[tid] + b[tid];

    float c, sc; curvature(logc, c, sc);
    float n2 = block_sum_128(y * y);
    float vn = fmaxf(sqrtf(n2), 1e-10f);
    float e = tanhf(sc * vn * 0.5f) * y / (sc * vn);
    float en2 = block_sum_128(e * e);
    float en = sqrtf(en2);
    float maxn = (1.0f - 1e-5f) / sc;
    float scl = fminf(maxn / fmaxf(en, 1e-6f), 1.0f);
    e *= scl;
    emb[row * ND + tid] = e;

    __nv_bfloat16 *A1 = (__nv_bfloat16*)g_A1e, *A2 = (__nv_bfloat16*)g_A2e;
    __nv_bfloat16 hh, ll;
    split_hl(e, hh, ll);
    A1[(size_t)row * KEXP + tid] = hh;
    A1[(size_t)row * KEXP + 128 + tid] = ll;
    A1[(size_t)row * KEXP + 256 + tid] = hh;
    split_hl(y, hh, ll);
    A2[(size_t)row * KEXP + tid] = hh;
    A2[(size_t)row * KEXP + 128 + tid] = ll;
    A2[(size_t)row * KEXP + 256 + tid] = hh;

    if (tid == 0) {
        float e2 = en2 * scl * scl;
        e2o[row] = e2;
        deo[row] = 1.0f - c * fminf(e2, 1.0f - 1e-5f);
    }
}

// --------------- prototype scaling + split (padded to NC2) -----------------
__global__ void proto_prep(const float* __restrict__ P, const float* __restrict__ logc)
{
    int row = blockIdx.x, tid = threadIdx.x;
    float p = (row < NC) ? P[(size_t)row * ND + tid] : 0.0f;
    float n2 = block_sum_128(p * p);
    float c, sc; curvature(logc, c, sc);
    float maxn = (1.0f - 1e-5f) / sc;
    float scl = fminf(maxn / fmaxf(sqrtf(n2), 1e-6f), 1.0f);
    p *= scl;
    __nv_bfloat16* B1 = (__nv_bfloat16*)g_B1e;
    __nv_bfloat16 hh, ll; split_hl(p, hh, ll);
    B1[(size_t)row * KEXP + tid] = hh;
    B1[(size_t)row * KEXP + 128 + tid] = hh;
    B1[(size_t)row * KEXP + 256 + tid] = ll;
    if (tid == 0) {
        float p2 = n2 * scl * scl;
        g_p2[row] = p2;
        g_dp[row] = 1.0f - c * fminf(p2, 1.0f - 1e-5f);
    }
}

// ----------------- euc_w transpose + split (padded to NC2) -----------------
__global__ void euc_prep(const float* __restrict__ W, const float* __restrict__ bias)
{
    int row = blockIdx.x, tid = threadIdx.x;   // row = class n, tid = k
    float w = (row < NC) ? W[(size_t)tid * NC + row] : 0.0f;
    __nv_bfloat16* B2 = (__nv_bfloat16*)g_B2e;
    __nv_bfloat16 hh, ll; split_hl(w, hh, ll);
    B2[(size_t)row * KEXP + tid] = hh;
    B2[(size_t)row * KEXP + 128 + tid] = hh;
    B2[(size_t)row * KEXP + 256 + tid] = ll;
    if (tid == 0) g_eb[row] = (row < NC) ? bias[row] : 0.0f;
}

// ---------------- mma.sync dual GEMM + fused epilogue ----------------------
// grid (NC2/128, NB/128, 2); z=0: hyp (emb@protos^T), z=1: euc (t2@eucw^T)
#define STAGE_BYTES 32768                  // A 16KB + B 16KB per stage
#define NSTAGE 6                           // KEXP*2B / 128B
#define SMEM_BYTES (128 * 132 * 4)         // 67584 >= 2*STAGE_BYTES

__global__ void __launch_bounds__(256, 2) dual_mma(
    const float* __restrict__ e2v, const float* __restrict__ dev,
    const float* __restrict__ logc,
    float* __restrict__ hyp, float* __restrict__ euc)
{
    extern __shared__ char smem[];
    float* smf = (float*)smem;
    const int tid = threadIdx.x, wid = tid >> 5, lane = tid & 31;
    const int z = blockIdx.z;
    const int m0 = blockIdx.y * 128, n0 = blockIdx.x * 128;
    const char* Ag = (const char*)(z ? g_A2e : g_A1e);
    const char* Bg = (const char*)(z ? g_B2e : g_B1e);
    const uint32_t sbase = smem_u32(smem);

    const int warp_m = wid & 1, warp_n = wid >> 1;
    const int quad = lane >> 3, l8 = lane & 7;

    float acc[4][4][4] = {};

    // ---- async stage loader: 128 rows x 128B for A and B, XOR-swizzled ----
    auto load_stage = [&](int s) {
        const uint32_t sA = sbase + (uint32_t)(s & 1) * STAGE_BYTES;
        const uint32_t sB = sA + 16384;
        const size_t kb = (size_t)s * 128;
#pragma unroll
        for (int j = 0; j < 4; ++j) {
            int idx = tid + 256 * j;
            int row = idx >> 3, ch = idx & 7;
            uint32_t so = row * 128 + ((ch ^ (row & 7)) << 4);
            cp_async16(sA + so, Ag + (size_t)(m0 + row) * (KEXP * 2) + kb + ch * 16);
            cp_async16(sB + so, Bg + (size_t)(n0 + row) * (KEXP * 2) + kb + ch * 16);
        }
        asm volatile("cp.async.commit_group;" ::: "memory");
    };

    load_stage(0);
#pragma unroll 1
    for (int s = 0; s < NSTAGE; ++s) {
        if (s + 1 < NSTAGE) {
            load_stage(s + 1);
            asm volatile("cp.async.wait_group 1;" ::: "memory");
        } else {
            asm volatile("cp.async.wait_group 0;" ::: "memory");
        }
        __syncthreads();

        const uint32_t aB = sbase + (uint32_t)(s & 1) * STAGE_BYTES;
        const uint32_t bB = aB + 16384;
#pragma unroll
        for (int ks = 0; ks < 4; ++ks) {
            uint32_t a[4][4];
#pragma unroll
            for (int mf = 0; mf < 4; ++mf) {
                int mr = warp_m * 64 + mf * 16 + (quad & 1) * 8 + l8;
                int kc = ks * 2 + (quad >> 1);
                ldmx4(aB + mr * 128 + ((kc ^ (mr & 7)) << 4),
                      a[mf][0], a[mf][1], a[mf][2], a[mf][3]);
            }
            uint32_t b[2][4];
#pragma unroll
            for (int nh = 0; nh < 2; ++nh) {
                int nr = warp_n * 32 + nh * 16 + (quad >> 1) * 8 + l8;
                int kc = ks * 2 + (quad & 1);
                ldmx4(bB + nr * 128 + ((kc ^ (nr & 7)) << 4),
                      b[nh][0], b[nh][1], b[nh][2], b[nh][3]);
            }
#pragma unroll
            for (int mf = 0; mf < 4; ++mf)
#pragma unroll
                for (int nf = 0; nf < 4; ++nf)
                    mma_bf16(acc[mf][nf], a[mf], b[nf >> 1][(nf & 1) * 2],
                             b[nf >> 1][(nf & 1) * 2 + 1]);
        }
        __syncthreads();
    }

    // ---- transpose through smem (padded rows of 132 floats) ----
    const int g = lane >> 2, tg = lane & 3;
#pragma unroll
    for (int mf = 0; mf < 4; ++mf)
#pragma unroll
        for (int nf = 0; nf < 4; ++nf) {
            int r0 = warp_m * 64 + mf * 16 + g;
            int col = warp_n * 32 + nf * 8 + tg * 2;
            *(float2*)&smf[r0 * 132 + col]       = make_float2(acc[mf][nf][0], acc[mf][nf][1]);
            *(float2*)&smf[(r0 + 8) * 132 + col] = make_float2(acc[mf][nf][2], acc[mf][nf][3]);
        }
    __syncthreads();

    // ---- epilogue math + coalesced global stores ----
    float inv2sc = 0.f;
    if (z == 0) {
        float c_, sc_; curvature(logc, c_, sc_);
        inv2sc = 2.0f / sc_;
    }
    float* dst = z ? euc : hyp;
    const int gc = n0 + lane * 4;
    const bool ok = gc < NC;

#pragma unroll 1
    for (int it = 0; it < 16; ++it) {
        int r = wid * 16 + it;
        int grow = m0 + r;
        float4 v = *(const float4*)&smf[r * 132 + lane * 4];
        float* vp = &v.x;
        if (z == 0) {
            float e2r = e2v[grow], der = dev[grow];
            float4 p2 = *(const float4*)&g_p2[gc];
            float4 dp = *(const float4*)&g_dp[gc];
            const float* p2p = &p2.x; const float* dpp = &dp.x;
#pragma unroll
            for (int e = 0; e < 4; ++e) {
                float diff = fmaxf(e2r + p2p[e] - 2.0f * vp[e], 1e-10f);
                float den  = fmaxf(der * dpp[e], 1e-6f);
                float num  = fmaf(2.0f, diff, den);
                float dist;
                if (diff >= 32.0f * den) {
                    // acosh(num/den) ~= ln(2*num/den), rel err < 6e-5
                    dist = plog(num) - plog(den) + 0.69314718055994531f;
                } else {
                    float arg = fmaxf(__fdividef(num, den), 1.0f + 1e-6f);
                    dist = acoshf(arg);
                }
                vp[e] = -inv2sc * dist;
            }
        } else {
            float4 eb = *(const float4*)&g_eb[gc];
            v.x += eb.x; v.y += eb.y; v.z += eb.z; v.w += eb.w;
        }
        if (ok) *(float4*)(dst + (size_t)grow * NC + gc) = v;
    }
}

// ------------------------------- launch -------------------------------------
extern "C" void kernel_launch(void* const* d_in, const int* in_sizes, int n_in,
                              void* d_out, int out_size)
{
    const float* x      = (const float*)d_in[0];
    const float* W1     = (const float*)d_in[1];
    const float* b1     = (const float*)d_in[2];
    const float* W2     = (const float*)d_in[3];
    const float* b2     = (const float*)d_in[4];
    const float* in_w   = (const float*)d_in[5];
    const float* in_b   = (const float*)d_in[6];
    const float* out_w  = (const float*)d_in[7];
    const float* out_b  = (const float*)d_in[8];
    const float* fw1    = (const float*)d_in[9];
    const float* fb1    = (const float*)d_in[10];
    const float* fw2    = (const float*)d_in[11];
    const float* fb2    = (const float*)d_in[12];
    const float* g1     = (const float*)d_in[13];
    const float* bt1    = (const float*)d_in[14];
    const float* g2     = (const float*)d_in[15];
    const float* bt2    = (const float*)d_in[16];
    const float* logc   = (const float*)d_in[17];
    const float* protos = (const float*)d_in[18];
    const float* euc_w  = (const float*)d_in[19];
    const float* euc_b  = (const float*)d_in[20];

    float *t1, *t, *v, *ao, *xs, *h, *f, *e2, *de;
    cudaGetSymbolAddress((void**)&t1, g_t1);
    cudaGetSymbolAddress((void**)&t,  g_t);
    cudaGetSymbolAddress((void**)&v,  g_v);
    cudaGetSymbolAddress((void**)&ao, g_ao);
    cudaGetSymbolAddress((void**)&xs, g_xs);
    cudaGetSymbolAddress((void**)&h,  g_h);
    cudaGetSymbolAddress((void**)&f,  g_f);
    cudaGetSymbolAddress((void**)&e2, g_e2);
    cudaGetSymbolAddress((void**)&de, g_de);

    float* out = (float*)d_out;
    float* hyp = out;
    float* euc = out + (size_t)NB * NC;
    float* emb = out + (size_t)NB * NC * 2;

    static int smem_set = 0;
    if (!smem_set) {
        cudaFuncSetAttribute(dual_mma, cudaFuncAttributeMaxDynamicSharedMemorySize, SMEM_BYTES);
        smem_set = 1;
    }

    // prototype / euc_w preps (independent of front-end)
    proto_prep<<<NC2, 128>>>(protos, logc);
    euc_prep <<<NC2, 128>>>(euc_w, euc_b);

    // MLP front-end
    sgemm_bias<1><<<dim3(256 / 64, NB / 64), 256>>>(x, NIN, W1, 256, b1, t1, 256, NIN);
    sgemm_bias<0><<<dim3(ND / 64, NB / 64), 256>>>(t1, 256, W2, ND, b2, t, ND, 256);

    // Attention (seq_len 1 -> attn == v)
    sgemm_bias<0><<<dim3(ND / 64, NB / 64), 256>>>(t, ND, in_w + 2 * ND, 3 * ND,
                                                   in_b + 2 * ND, v, ND, ND);
    sgemm_bias<0><<<dim3(ND / 64, NB / 64), 256>>>(v, ND, out_w, ND, out_b, ao, ND, ND);
    ln_res<<<NB, 128>>>(t, ao, g1, bt1, xs);

    // FFN
    sgemm_bias<1><<<dim3(512 / 64, NB / 64), 256>>>(xs, ND, fw1, 512, fb1, h, 512, ND);
    sgemm_bias<0><<<dim3(ND / 64, NB / 64), 256>>>(h, 512, fw2, ND, fb2, f, ND, 512);

    // LN2 + hyperbolic embedding + A splits
    ln2_emb<<<NB, 128>>>(xs, f, g2, bt2, logc, emb, e2, de);

    // mma.sync dual GEMM + fused epilogues
    dual_mma<<<dim3(NC2 / 128, NB / 128, 2), 256, SMEM_BYTES>>>(e2, de, logc, hyp, euc);
}

// round 4
// speedup vs baseline: 2.1720x; 1.1073x over previous
#include <cuda_runtime.h>
#include <cuda_bf16.h>
#include <cuda_fp16.h>
#include <math.h>
#include <stdint.h>

// ---------------------------------------------------------------------------
// B=4096, IN_DIM=1024, D=128, C=10000. seq_len==1 -> attn == v (q,k dead),
// and v/out_w projections fold into ONE GEMM (linear chain).
// Output: (hyp_logits[B,C], euc_logits[B,C], emb[B,D]) concatenated.
// Big head (2x [4096x128]@[128x10000]) on mma.sync fp16, 2-pass hi/lo (K=256).
// ---------------------------------------------------------------------------

#define NB   4096
#define NIN  1024
#define ND   128
#define NC   10000
#define NC2  10112          // padded to 79*128
#define KEXP 256            // 2 * 128 (hi|lo split, fp16)

// ------------------------- device scratch (no allocs) ----------------------
__device__ float g_t1[NB * 256];
__device__ float g_t [NB * ND];
__device__ float g_ao[NB * ND];
__device__ float g_xs[NB * ND];
__device__ float g_h [NB * 512];
__device__ float g_f [NB * ND];
__device__ float g_e2[NB];
__device__ float g_de[NB];
__device__ float g_Wp[ND * ND];   // Wv @ out_w
__device__ float g_bp[ND];        // bv @ out_w + out_b
__device__ uint4 g_A1e[NB  * KEXP / 8];   // emb split, fp16 [NB][KEXP]
__device__ uint4 g_A2e[NB  * KEXP / 8];   // t2  split
__device__ uint4 g_B1e[NC2 * KEXP / 8];   // protos split [NC2][KEXP]
__device__ uint4 g_B2e[NC2 * KEXP / 8];   // euc_w^T split
__device__ float g_p2[NC2];
__device__ float g_dp[NC2];
__device__ float g_eb[NC2];

// ------------------------------ helpers ------------------------------------
static __device__ __forceinline__ uint32_t smem_u32(const void* p) {
    uint32_t a;
    asm("{ .reg .u64 t; cvta.to.shared.u64 t, %1; cvt.u32.u64 %0, t; }" : "=r"(a) : "l"(p));
    return a;
}
static __device__ __forceinline__ void cp_async16(uint32_t s, const void* g) {
    asm volatile("cp.async.cg.shared.global [%0], [%1], 16;" :: "r"(s), "l"(g) : "memory");
}
static __device__ __forceinline__ void ldmx4(uint32_t a, uint32_t& r0, uint32_t& r1,
                                             uint32_t& r2, uint32_t& r3) {
    asm volatile("ldmatrix.sync.aligned.m8n8.x4.shared.b16 {%0,%1,%2,%3}, [%4];"
                 : "=r"(r0), "=r"(r1), "=r"(r2), "=r"(r3) : "r"(a));
}
static __device__ __forceinline__ void mma_fp16(float* d, const uint32_t* a,
                                                uint32_t b0, uint32_t b1) {
    asm volatile("mma.sync.aligned.m16n8k16.row.col.f32.f16.f16.f32 "
                 "{%0,%1,%2,%3}, {%4,%5,%6,%7}, {%8,%9}, {%0,%1,%2,%3};"
                 : "+f"(d[0]), "+f"(d[1]), "+f"(d[2]), "+f"(d[3])
                 : "r"(a[0]), "r"(a[1]), "r"(a[2]), "r"(a[3]), "r"(b0), "r"(b1));
}
static __device__ __forceinline__ float gelu_exact(float x) {
    return 0.5f * x * (1.0f + erff(x * 0.70710678118654752440f));
}
static __device__ __forceinline__ float block_sum_128(float v) {
    __shared__ float sh[4];
    int lane = threadIdx.x & 31, wid = threadIdx.x >> 5;
#pragma unroll
    for (int o = 16; o > 0; o >>= 1) v += __shfl_down_sync(0xffffffffu, v, o);
    __syncthreads();
    if (lane == 0) sh[wid] = v;
    __syncthreads();
    return sh[0] + sh[1] + sh[2] + sh[3];
}
static __device__ __forceinline__ void curvature(const float* logc, float& c, float& sc) {
    float cc = expf(logc[0]);
    cc = fminf(fmaxf(cc, 1e-4f), 10.0f);
    cc = fmaxf(fabsf(cc), 1e-6f);
    c = cc; sc = sqrtf(cc);
}
static __device__ __forceinline__ void split_hl(float x, __half& h, __half& l) {
    h = __float2half_rn(x);
    l = __float2half_rn(x - __half2float(h));
}
// natural log via FMA-pipe polynomial (no MUFU/div). x > 0, normal range.
static __device__ __forceinline__ float plog(float x) {
    int i = __float_as_int(x);
    int e = (i - 0x3f3504f3) >> 23;
    float m = __int_as_float(i - (e << 23));
    float t = m - 1.0f;
    float p = 0.14285715f;
    p = fmaf(p, t, -0.16666667f);
    p = fmaf(p, t, 0.20000000f);
    p = fmaf(p, t, -0.25000000f);
    p = fmaf(p, t, 0.33333334f);
    p = fmaf(p, t, -0.50000000f);
    p = fmaf(p, t, 1.00000000f);
    p = p * t;
    return fmaf((float)e, 0.69314718055994531f, p);
}

// ----------------------- fp32 SGEMM front-end ------------------------------
template <int ACT>
__global__ void __launch_bounds__(256) sgemm_bias(
    const float* __restrict__ A, int lda, const float* __restrict__ Bm, int ldb,
    const float* __restrict__ bias, float* __restrict__ C, int ldc, int K)
{
    __shared__ float As[32][68];
    __shared__ float Bs[32][68];
    const int tid = threadIdx.x;
    const int tx = tid & 15, ty = tid >> 4;
    const int m0 = blockIdx.y * 64, n0 = blockIdx.x * 64;
    const int ar = tid >> 3, ac = tid & 7;
    const int bk = tid >> 4, bc = tid & 15;
    float acc[4][4] = {};
    for (int k0 = 0; k0 < K; k0 += 32) {
#pragma unroll
        for (int it = 0; it < 2; ++it) {
            int row = ar + it * 32;
            float4 va = *(const float4*)(A + (size_t)(m0 + row) * lda + k0 + ac * 4);
            As[ac*4+0][row] = va.x; As[ac*4+1][row] = va.y;
            As[ac*4+2][row] = va.z; As[ac*4+3][row] = va.w;
        }
#pragma unroll
        for (int it = 0; it < 2; ++it) {
            int kk = bk + it * 16;
            float4 vb = *(const float4*)(Bm + (size_t)(k0 + kk) * ldb + n0 + bc * 4);
            *(float4*)&Bs[kk][bc * 4] = vb;
        }
        __syncthreads();
#pragma unroll
        for (int kk = 0; kk < 32; ++kk) {
            float4 a = *(const float4*)&As[kk][ty * 4];
            float4 b = *(const float4*)&Bs[kk][tx * 4];
            float av[4] = {a.x,a.y,a.z,a.w}, bv[4] = {b.x,b.y,b.z,b.w};
#pragma unroll
            for (int i = 0; i < 4; ++i)
#pragma unroll
                for (int j = 0; j < 4; ++j)
                    acc[i][j] = fmaf(av[i], bv[j], acc[i][j]);
        }
        __syncthreads();
    }
#pragma unroll
    for (int i = 0; i < 4; ++i) {
        int row = m0 + ty * 4 + i;
        float4 o; float* op = &o.x;
#pragma unroll
        for (int j = 0; j < 4; ++j) {
            float v = acc[i][j] + bias[n0 + tx * 4 + j];
            if (ACT == 1) v = gelu_exact(v);
            op[j] = v;
        }
        *(float4*)(C + (size_t)row * ldc + n0 + tx * 4) = o;
    }
}

// ------------------- attention weight fold: W' = Wv @ out_w ----------------
__global__ void fold_w(const float* __restrict__ in_w, const float* __restrict__ out_w)
{
    int k = blockIdx.x, j = threadIdx.x;
    float s = 0.f;
#pragma unroll 8
    for (int m = 0; m < ND; ++m)
        s = fmaf(in_w[k * 384 + 256 + m], out_w[m * ND + j], s);
    g_Wp[k * ND + j] = s;
}
__global__ void fold_b(const float* __restrict__ in_b, const float* __restrict__ out_w,
                       const float* __restrict__ out_b)
{
    int j = threadIdx.x;
    float s = out_b[j];
#pragma unroll 8
    for (int m = 0; m < ND; ++m)
        s = fmaf(in_b[256 + m], out_w[m * ND + j], s);
    g_bp[j] = s;
}

// ------------------------- LayerNorm(residual) ------------------------------
__global__ void ln_res(const float* __restrict__ X, const float* __restrict__ R,
                       const float* __restrict__ g, const float* __restrict__ b,
                       float* __restrict__ out)
{
    int row = blockIdx.x, tid = threadIdx.x;
    float x = X[row * ND + tid] + R[row * ND + tid];
    float m = block_sum_128(x) * (1.0f / 128.0f);
    float d = x - m;
    float v = block_sum_128(d * d) * (1.0f / 128.0f);
    out[row * ND + tid] = d * rsqrtf(v + 1e-5f) * g[tid] + b[tid];
}

// ------- LN2 + hyperbolic embedding + fp16-split operand emission ----------
__global__ void ln2_emb(const float* __restrict__ xs, const float* __restrict__ f,
                        const float* __restrict__ g, const float* __restrict__ b,
                        const float* __restrict__ logc,
                        float* __restrict__ emb,
                        float* __restrict__ e2o, float* __restrict__ deo)
{
    int row = blockIdx.x, tid = threadIdx.x;
    float x = xs[row * ND + tid] + f[row * ND + tid];
    float m = block_sum_128(x) * (1.0f / 128.0f);
    float d = x - m;
    float v = block_sum_128(d * d) * (1.0f / 128.0f);
    float y = d * rsqrtf(v + 1e-5f) * g[tid] + b[tid];

    float c, sc; curvature(logc, c, sc);
    float n2 = block_sum_128(y * y);
    float vn = fmaxf(sqrtf(n2), 1e-10f);
    float e = tanhf(sc * vn * 0.5f) * y / (sc * vn);
    float en2 = block_sum_128(e * e);
    float en = sqrtf(en2);
    float maxn = (1.0f - 1e-5f) / sc;
    float scl = fminf(maxn / fmaxf(en, 1e-6f), 1.0f);
    e *= scl;
    emb[row * ND + tid] = e;

    __half *A1 = (__half*)g_A1e, *A2 = (__half*)g_A2e;
    __half hh, ll;
    split_hl(e, hh, ll);
    A1[(size_t)row * KEXP + tid] = hh;
    A1[(size_t)row * KEXP + 128 + tid] = ll;
    split_hl(y, hh, ll);
    A2[(size_t)row * KEXP + tid] = hh;
    A2[(size_t)row * KEXP + 128 + tid] = ll;

    if (tid == 0) {
        float e2 = en2 * scl * scl;
        e2o[row] = e2;
        deo[row] = 1.0f - c * fminf(e2, 1.0f - 1e-5f);
    }
}

// --------------- prototype scaling + split (padded to NC2) -----------------
__global__ void proto_prep(const float* __restrict__ P, const float* __restrict__ logc)
{
    int row = blockIdx.x, tid = threadIdx.x;
    float p = (row < NC) ? P[(size_t)row * ND + tid] : 0.0f;
    float n2 = block_sum_128(p * p);
    float c, sc; curvature(logc, c, sc);
    float maxn = (1.0f - 1e-5f) / sc;
    float scl = fminf(maxn / fmaxf(sqrtf(n2), 1e-6f), 1.0f);
    p *= scl;
    __half* B1 = (__half*)g_B1e;
    __half hh = __float2half_rn(p);
    B1[(size_t)row * KEXP + tid] = hh;
    B1[(size_t)row * KEXP + 128 + tid] = hh;
    if (tid == 0) {
        float p2 = n2 * scl * scl;
        g_p2[row] = p2;
        g_dp[row] = 1.0f - c * fminf(p2, 1.0f - 1e-5f);
    }
}

// --------- euc_w transpose + split, coalesced via smem tile ----------------
__global__ void __launch_bounds__(256) euc_prep(const float* __restrict__ W,
                                                const float* __restrict__ bias)
{
    __shared__ float tile[128 * 65];
    const int tid = threadIdx.x;
    const int c0 = blockIdx.x * 64;
#pragma unroll
    for (int it = 0; it < 32; ++it) {
        int idx = it * 256 + tid;
        int k = idx >> 6, cc = idx & 63;
        int cls = c0 + cc;
        tile[k * 65 + cc] = (cls < NC) ? W[(size_t)k * NC + cls] : 0.0f;
    }
    __syncthreads();
    const int cc = tid >> 2, q = tid & 3;
    __half* B2 = (__half*)g_B2e;
    const size_t base = (size_t)(c0 + cc) * KEXP;
#pragma unroll
    for (int j = q * 32; j < q * 32 + 32; ++j) {
        __half hh = __float2half_rn(tile[j * 65 + cc]);
        B2[base + j] = hh;
        B2[base + 128 + j] = hh;
    }
    if (tid < 64) {
        int cls = c0 + tid;
        g_eb[cls] = (cls < NC) ? bias[cls] : 0.0f;
    }
}

// ---------------- mma.sync dual GEMM + fused epilogue ----------------------
// grid (NC2/128, NB/128, 2); z=0: hyp (emb@protos^T), z=1: euc (t2@eucw^T)
#define STAGE_BYTES 32768                  // A 16KB + B 16KB per stage
#define NSTAGE 4                           // KEXP*2B / 128B
#define SMEM_BYTES (128 * 132 * 4)         // 67584 >= 2*STAGE_BYTES

__global__ void __launch_bounds__(256, 2) dual_mma(
    const float* __restrict__ e2v, const float* __restrict__ dev,
    const float* __restrict__ logc,
    float* __restrict__ hyp, float* __restrict__ euc)
{
    extern __shared__ char smem[];
    float* smf = (float*)smem;
    const int tid = threadIdx.x, wid = tid >> 5, lane = tid & 31;
    const int z = blockIdx.z;
    const int m0 = blockIdx.y * 128, n0 = blockIdx.x * 128;
    const char* Ag = (const char*)(z ? g_A2e : g_A1e);
    const char* Bg = (const char*)(z ? g_B2e : g_B1e);
    const uint32_t sbase = smem_u32(smem);

    const int warp_m = wid & 1, warp_n = wid >> 1;
    const int quad = lane >> 3, l8 = lane & 7;

    float acc[4][4][4] = {};

    auto load_stage = [&](int s) {
        const uint32_t sA = sbase + (uint32_t)(s & 1) * STAGE_BYTES;
        const uint32_t sB = sA + 16384;
        const size_t kb = (size_t)s * 128;
#pragma unroll
        for (int j = 0; j < 4; ++j) {
            int idx = tid + 256 * j;
            int row = idx >> 3, ch = idx & 7;
            uint32_t so = row * 128 + ((ch ^ (row & 7)) << 4);
            cp_async16(sA + so, Ag + (size_t)(m0 + row) * (KEXP * 2) + kb + ch * 16);
            cp_async16(sB + so, Bg + (size_t)(n0 + row) * (KEXP * 2) + kb + ch * 16);
        }
        asm volatile("cp.async.commit_group;" ::: "memory");
    };

    load_stage(0);
#pragma unroll 1
    for (int s = 0; s < NSTAGE; ++s) {
        if (s + 1 < NSTAGE) {
            load_stage(s + 1);
            asm volatile("cp.async.wait_group 1;" ::: "memory");
        } else {
            asm volatile("cp.async.wait_group 0;" ::: "memory");
        }
        __syncthreads();

        const uint32_t aB = sbase + (uint32_t)(s & 1) * STAGE_BYTES;
        const uint32_t bB = aB + 16384;
#pragma unroll
        for (int ks = 0; ks < 4; ++ks) {
            uint32_t a[4][4];
#pragma unroll
            for (int mf = 0; mf < 4; ++mf) {
                int mr = warp_m * 64 + mf * 16 + (quad & 1) * 8 + l8;
                int kc = ks * 2 + (quad >> 1);
                ldmx4(aB + mr * 128 + ((kc ^ (mr & 7)) << 4),
                      a[mf][0], a[mf][1], a[mf][2], a[mf][3]);
            }
            uint32_t b[2][4];
#pragma unroll
            for (int nh = 0; nh < 2; ++nh) {
                int nr = warp_n * 32 + nh * 16 + (quad >> 1) * 8 + l8;
                int kc = ks * 2 + (quad & 1);
                ldmx4(bB + nr * 128 + ((kc ^ (nr & 7)) << 4),
                      b[nh][0], b[nh][1], b[nh][2], b[nh][3]);
            }
#pragma unroll
            for (int mf = 0; mf < 4; ++mf)
#pragma unroll
                for (int nf = 0; nf < 4; ++nf)
                    mma_fp16(acc[mf][nf], a[mf], b[nf >> 1][(nf & 1) * 2],
                             b[nf >> 1][(nf & 1) * 2 + 1]);
        }
        __syncthreads();
    }

    // ---- transpose through smem (padded rows of 132 floats) ----
    const int g = lane >> 2, tg = lane & 3;
#pragma unroll
    for (int mf = 0; mf < 4; ++mf)
#pragma unroll
        for (int nf = 0; nf < 4; ++nf) {
            int r0 = warp_m * 64 + mf * 16 + g;
            int col = warp_n * 32 + nf * 8 + tg * 2;
            *(float2*)&smf[r0 * 132 + col]       = make_float2(acc[mf][nf][0], acc[mf][nf][1]);
            *(float2*)&smf[(r0 + 8) * 132 + col] = make_float2(acc[mf][nf][2], acc[mf][nf][3]);
        }
    __syncthreads();

    // ---- epilogue math + coalesced global stores ----
    float inv2sc = 0.f;
    if (z == 0) {
        float c_, sc_; curvature(logc, c_, sc_);
        inv2sc = 2.0f / sc_;
    }
    float* dst = z ? euc : hyp;
    const int gc = n0 + lane * 4;
    const bool ok = gc < NC;

#pragma unroll 1
    for (int it = 0; it < 16; ++it) {
        int r = wid * 16 + it;
        int grow = m0 + r;
        float4 v = *(const float4*)&smf[r * 132 + lane * 4];
        float* vp = &v.x;
        if (z == 0) {
            float e2r = e2v[grow], der = dev[grow];
            float4 p2 = *(const float4*)&g_p2[gc];
            float4 dp = *(const float4*)&g_dp[gc];
            const float* p2p = &p2.x; const float* dpp = &dp.x;
#pragma unroll
            for (int e = 0; e < 4; ++e) {
                float diff = fmaxf(e2r + p2p[e] - 2.0f * vp[e], 1e-10f);
                float den  = fmaxf(der * dpp[e], 1e-6f);
                float num  = fmaf(2.0f, diff, den);
                float dist;
                if (diff >= 32.0f * den) {
                    dist = plog(num) - plog(den) + 0.69314718055994531f;
                } else {
                    float arg = fmaxf(__fdividef(num, den), 1.0f + 1e-6f);
                    dist = acoshf(arg);
                }
                vp[e] = -inv2sc * dist;
            }
        } else {
            float4 eb = *(const float4*)&g_eb[gc];
            v.x += eb.x; v.y += eb.y; v.z += eb.z; v.w += eb.w;
        }
        if (ok) *(float4*)(dst + (size_t)grow * NC + gc) = v;
    }
}

// ------------------------------- launch -------------------------------------
extern "C" void kernel_launch(void* const* d_in, const int* in_sizes, int n_in,
                              void* d_out, int out_size)
{
    const float* x      = (const float*)d_in[0];
    const float* W1     = (const float*)d_in[1];
    const float* b1     = (const float*)d_in[2];
    const float* W2     = (const float*)d_in[3];
    const float* b2     = (const float*)d_in[4];
    const float* in_w   = (const float*)d_in[5];
    const float* in_b   = (const float*)d_in[6];
    const float* out_w  = (const float*)d_in[7];
    const float* out_b  = (const float*)d_in[8];
    const float* fw1    = (const float*)d_in[9];
    const float* fb1    = (const float*)d_in[10];
    const float* fw2    = (const float*)d_in[11];
    const float* fb2    = (const float*)d_in[12];
    const float* g1     = (const float*)d_in[13];
    const float* bt1    = (const float*)d_in[14];
    const float* g2     = (const float*)d_in[15];
    const float* bt2    = (const float*)d_in[16];
    const float* logc   = (const float*)d_in[17];
    const float* protos = (const float*)d_in[18];
    const float* euc_w  = (const float*)d_in[19];
    const float* euc_b  = (const float*)d_in[20];

    float *t1, *t, *ao, *xs, *h, *f, *e2, *de, *Wp, *bp;
    cudaGetSymbolAddress((void**)&t1, g_t1);
    cudaGetSymbolAddress((void**)&t,  g_t);
    cudaGetSymbolAddress((void**)&ao, g_ao);
    cudaGetSymbolAddress((void**)&xs, g_xs);
    cudaGetSymbolAddress((void**)&h,  g_h);
    cudaGetSymbolAddress((void**)&f,  g_f);
    cudaGetSymbolAddress((void**)&e2, g_e2);
    cudaGetSymbolAddress((void**)&de, g_de);
    cudaGetSymbolAddress((void**)&Wp, g_Wp);
    cudaGetSymbolAddress((void**)&bp, g_bp);

    float* out = (float*)d_out;
    float* hyp = out;
    float* euc = out + (size_t)NB * NC;
    float* emb = out + (size_t)NB * NC * 2;

    static int smem_set = 0;
    if (!smem_set) {
        cudaFuncSetAttribute(dual_mma, cudaFuncAttributeMaxDynamicSharedMemorySize, SMEM_BYTES);
        smem_set = 1;
    }

    // preps (independent of front-end)
    proto_prep<<<NC2, 128>>>(protos, logc);
    euc_prep <<<NC2 / 64, 256>>>(euc_w, euc_b);
    fold_w<<<ND, ND>>>(in_w, out_w);
    fold_b<<<1, ND>>>(in_b, out_w, out_b);

    // MLP front-end
    sgemm_bias<1><<<dim3(256 / 64, NB / 64), 256>>>(x, NIN, W1, 256, b1, t1, 256, NIN);
    sgemm_bias<0><<<dim3(ND / 64, NB / 64), 256>>>(t1, 256, W2, ND, b2, t, ND, 256);

    // Attention (seq_len 1, v/out folded): ao = t @ W' + b'
    sgemm_bias<0><<<dim3(ND / 64, NB / 64), 256>>>(t, ND, Wp, ND, bp, ao, ND, ND);
    ln_res<<<NB, 128>>>(t, ao, g1, bt1, xs);

    // FFN
    sgemm_bias<1><<<dim3(512 / 64, NB / 64), 256>>>(xs, ND, fw1, 512, fb1, h, 512, ND);
    sgemm_bias<0><<<dim3(ND / 64, NB / 64), 256>>>(h, 512, fw2, ND, fb2, f, ND, 512);

    // LN2 + hyperbolic embedding + A splits
    ln2_emb<<<NB, 128>>>(xs, f, g2, bt2, logc, emb, e2, de);

    // mma.sync dual GEMM + fused epilogues
    dual_mma<<<dim3(NC2 / 128, NB / 128, 2), 256, SMEM_BYTES>>>(e2, de, logc, hyp, euc);
}

// round 5
// speedup vs baseline: 2.6094x; 1.2014x over previous
#include <cuda_runtime.h>
#include <cuda_fp16.h>
#include <math.h>
#include <stdint.h>

// ---------------------------------------------------------------------------
// B=4096, IN_DIM=1024, D=128, C=10000. seq_len==1 -> attn == v (q,k dead),
// v/out_w fold into one GEMM. Entire network on mma.sync fp16:
//   front-end: 3-term hi/lo split (error ~2^-24, fp32-quality)
//   head:      2-term split (validated 2e-4)
// Output: (hyp_logits[B,C], euc_logits[B,C], emb[B,D]) concatenated.
// ---------------------------------------------------------------------------

#define NB   4096
#define NIN  1024
#define ND   128
#define NC   10000
#define NC2  10112
#define KHEAD 256            // head: 2*128 fp16 split

// ------------------------- device scratch (no allocs) ----------------------
__device__ float g_t [NB * ND];
__device__ float g_ao[NB * ND];
__device__ float g_xs[NB * ND];
__device__ float g_f [NB * ND];
__device__ float g_e2[NB];
__device__ float g_de[NB];
__device__ float g_Wp[ND * ND];
__device__ float g_bp[ND];
// fp16 split activations (A-side, layout [hi(K), lo(K), hi(K)])
__device__ uint4 g_xsp [NB * 3072 / 8];
__device__ uint4 g_t1sp[NB * 768  / 8];
__device__ uint4 g_tsp [NB * 384  / 8];
__device__ uint4 g_xssp[NB * 384  / 8];
__device__ uint4 g_hsp [NB * 1536 / 8];
// fp16 split weights (B-side, layout [hi(K), hi(K), lo(K)] per out-column row)
__device__ uint4 g_W1p [256 * 3072 / 8];
__device__ uint4 g_W2p [128 * 768  / 8];
__device__ uint4 g_fw1p[512 * 384  / 8];
__device__ uint4 g_fw2p[128 * 1536 / 8];
__device__ uint4 g_Wpp [128 * 384  / 8];
// head operands (2-term)
__device__ uint4 g_A1e[NB  * KHEAD / 8];
__device__ uint4 g_A2e[NB  * KHEAD / 8];
__device__ uint4 g_B1e[NC2 * KHEAD / 8];
__device__ uint4 g_B2e[NC2 * KHEAD / 8];
__device__ float g_p2[NC2];
__device__ float g_dp[NC2];
__device__ float g_eb[NC2];

// ------------------------------ helpers ------------------------------------
static __device__ __forceinline__ uint32_t smem_u32(const void* p) {
    uint32_t a;
    asm("{ .reg .u64 t; cvta.to.shared.u64 t, %1; cvt.u32.u64 %0, t; }" : "=r"(a) : "l"(p));
    return a;
}
static __device__ __forceinline__ void cp_async16(uint32_t s, const void* g) {
    asm volatile("cp.async.cg.shared.global [%0], [%1], 16;" :: "r"(s), "l"(g) : "memory");
}
static __device__ __forceinline__ void ldmx4(uint32_t a, uint32_t& r0, uint32_t& r1,
                                             uint32_t& r2, uint32_t& r3) {
    asm volatile("ldmatrix.sync.aligned.m8n8.x4.shared.b16 {%0,%1,%2,%3}, [%4];"
                 : "=r"(r0), "=r"(r1), "=r"(r2), "=r"(r3) : "r"(a));
}
static __device__ __forceinline__ void mma_fp16(float* d, const uint32_t* a,
                                                uint32_t b0, uint32_t b1) {
    asm volatile("mma.sync.aligned.m16n8k16.row.col.f32.f16.f16.f32 "
                 "{%0,%1,%2,%3}, {%4,%5,%6,%7}, {%8,%9}, {%0,%1,%2,%3};"
                 : "+f"(d[0]), "+f"(d[1]), "+f"(d[2]), "+f"(d[3])
                 : "r"(a[0]), "r"(a[1]), "r"(a[2]), "r"(a[3]), "r"(b0), "r"(b1));
}
static __device__ __forceinline__ float gelu_exact(float x) {
    return 0.5f * x * (1.0f + erff(x * 0.70710678118654752440f));
}
static __device__ __forceinline__ float block_sum_128(float v) {
    __shared__ float sh[4];
    int lane = threadIdx.x & 31, wid = threadIdx.x >> 5;
#pragma unroll
    for (int o = 16; o > 0; o >>= 1) v += __shfl_down_sync(0xffffffffu, v, o);
    __syncthreads();
    if (lane == 0) sh[wid] = v;
    __syncthreads();
    return sh[0] + sh[1] + sh[2] + sh[3];
}
static __device__ __forceinline__ void curvature(const float* logc, float& c, float& sc) {
    float cc = expf(logc[0]);
    cc = fminf(fmaxf(cc, 1e-4f), 10.0f);
    cc = fmaxf(fabsf(cc), 1e-6f);
    c = cc; sc = sqrtf(cc);
}
static __device__ __forceinline__ void split_hl(float x, __half& h, __half& l) {
    h = __float2half_rn(x);
    l = __float2half_rn(x - __half2float(h));
}
static __device__ __forceinline__ float plog(float x) {
    int i = __float_as_int(x);
    int e = (i - 0x3f3504f3) >> 23;
    float m = __int_as_float(i - (e << 23));
    float t = m - 1.0f;
    float p = 0.14285715f;
    p = fmaf(p, t, -0.16666667f);
    p = fmaf(p, t, 0.20000000f);
    p = fmaf(p, t, -0.25000000f);
    p = fmaf(p, t, 0.33333334f);
    p = fmaf(p, t, -0.50000000f);
    p = fmaf(p, t, 1.00000000f);
    p = p * t;
    return fmaf((float)e, 0.69314718055994531f, p);
}

// ------------------- preps: splits, transposes, folds -----------------------
// x [rows][K] fp32 -> [rows][3K] fp16 (hi|lo|hi)
__global__ void asplit(const float* __restrict__ X, __half* __restrict__ out, int K)
{
    int row = blockIdx.x;
    const float* xr = X + (size_t)row * K;
    __half* o = out + (size_t)row * 3 * K;
    for (int k = threadIdx.x; k < K; k += 256) {
        __half h, l; split_hl(xr[k], h, l);
        o[k] = h; o[K + k] = l; o[2 * K + k] = h;
    }
}
// W [K][N] fp32 -> out [N][3K] fp16 (hi|hi|lo), transposed via smem
__global__ void __launch_bounds__(256) wprep(const float* __restrict__ W,
                                             __half* __restrict__ out, int K, int N)
{
    __shared__ float t[32][33];
    const int k0 = blockIdx.x * 32, n0 = blockIdx.y * 32;
    const int tx = threadIdx.x & 31, ty = threadIdx.x >> 5;
#pragma unroll
    for (int i = ty; i < 32; i += 8)
        t[i][tx] = W[(size_t)(k0 + i) * N + n0 + tx];
    __syncthreads();
#pragma unroll
    for (int i = ty; i < 32; i += 8) {
        int n = n0 + i, k = k0 + tx;
        __half h, l; split_hl(t[tx][i], h, l);
        size_t base = (size_t)n * 3 * K;
        out[base + k] = h; out[base + K + k] = h; out[base + 2 * K + k] = l;
    }
}
// fold: W' = Wv@out_w (blocks 0..ND-1), b' = bv@out_w + out_b (block ND)
__global__ void fold_w(const float* __restrict__ in_w, const float* __restrict__ out_w,
                       const float* __restrict__ in_b, const float* __restrict__ out_b)
{
    int j = threadIdx.x;
    if (blockIdx.x < ND) {
        int k = blockIdx.x;
        float s = 0.f;
#pragma unroll 8
        for (int m = 0; m < ND; ++m)
            s = fmaf(in_w[k * 384 + 256 + m], out_w[m * ND + j], s);
        g_Wp[k * ND + j] = s;
    } else {
        float s = out_b[j];
#pragma unroll 8
        for (int m = 0; m < ND; ++m)
            s = fmaf(in_b[256 + m], out_w[m * ND + j], s);
        g_bp[j] = s;
    }
}

// ---------------- generic tensor GEMM: 64x128 tile, 3-term split ------------
// A [M][KE] fp16 rows, Bt [N][KE] fp16 rows. C = act(A@Bt^T + bias).
// Optionally writes fp32 C and/or fp16 split of C (next GEMM's A, layout hi|lo|hi).
#define HSTAGE 24576                         // A 8KB + B 16KB
#define HSMEM  49152

template <int ACT, int WF32, int WSP>
__global__ void __launch_bounds__(256, 2) hgemm(
    const __half* __restrict__ A, const __half* __restrict__ Bt,
    const float* __restrict__ bias,
    float* __restrict__ C, __half* __restrict__ Asp,
    int KE, int N)
{
    extern __shared__ char smem[];
    float* smf = (float*)smem;
    const int tid = threadIdx.x, wid = tid >> 5, lane = tid & 31;
    const int m0 = blockIdx.y * 64, n0 = blockIdx.x * 128;
    const uint32_t sbase = smem_u32(smem);
    const int warp_m = wid & 1, warp_n = wid >> 1;
    const int quad = lane >> 3, l8 = lane & 7;
    const int nstage = KE >> 6;

    float acc[2][4][4] = {};

    auto load_stage = [&](int s) {
        const uint32_t sA = sbase + (uint32_t)(s & 1) * HSTAGE;
        const uint32_t sB = sA + 8192;
        const size_t kb = (size_t)s * 128;
#pragma unroll
        for (int j = 0; j < 2; ++j) {
            int idx = tid + 256 * j;
            int row = idx >> 3, ch = idx & 7;
            uint32_t so = row * 128 + ((ch ^ (row & 7)) << 4);
            cp_async16(sA + so, (const char*)A + (size_t)(m0 + row) * (KE * 2) + kb + ch * 16);
        }
#pragma unroll
        for (int j = 0; j < 4; ++j) {
            int idx = tid + 256 * j;
            int row = idx >> 3, ch = idx & 7;
            uint32_t so = row * 128 + ((ch ^ (row & 7)) << 4);
            cp_async16(sB + so, (const char*)Bt + (size_t)(n0 + row) * (KE * 2) + kb + ch * 16);
        }
        asm volatile("cp.async.commit_group;" ::: "memory");
    };

    load_stage(0);
#pragma unroll 1
    for (int s = 0; s < nstage; ++s) {
        if (s + 1 < nstage) {
            load_stage(s + 1);
            asm volatile("cp.async.wait_group 1;" ::: "memory");
        } else {
            asm volatile("cp.async.wait_group 0;" ::: "memory");
        }
        __syncthreads();
        const uint32_t aB = sbase + (uint32_t)(s & 1) * HSTAGE;
        const uint32_t bB = aB + 8192;
#pragma unroll
        for (int ks = 0; ks < 4; ++ks) {
            uint32_t a[2][4];
#pragma unroll
            for (int mf = 0; mf < 2; ++mf) {
                int mr = warp_m * 32 + mf * 16 + (quad & 1) * 8 + l8;
                int kc = ks * 2 + (quad >> 1);
                ldmx4(aB + mr * 128 + ((kc ^ (mr & 7)) << 4),
                      a[mf][0], a[mf][1], a[mf][2], a[mf][3]);
            }
            uint32_t b[2][4];
#pragma unroll
            for (int nh = 0; nh < 2; ++nh) {
                int nr = warp_n * 32 + nh * 16 + (quad >> 1) * 8 + l8;
                int kc = ks * 2 + (quad & 1);
                ldmx4(bB + nr * 128 + ((kc ^ (nr & 7)) << 4),
                      b[nh][0], b[nh][1], b[nh][2], b[nh][3]);
            }
#pragma unroll
            for (int mf = 0; mf < 2; ++mf)
#pragma unroll
                for (int nf = 0; nf < 4; ++nf)
                    mma_fp16(acc[mf][nf], a[mf], b[nf >> 1][(nf & 1) * 2],
                             b[nf >> 1][(nf & 1) * 2 + 1]);
        }
        __syncthreads();
    }

    // transpose through smem (64 x 132 floats)
    const int g = lane >> 2, tg = lane & 3;
#pragma unroll
    for (int mf = 0; mf < 2; ++mf)
#pragma unroll
        for (int nf = 0; nf < 4; ++nf) {
            int r0 = warp_m * 32 + mf * 16 + g;
            int col = warp_n * 32 + nf * 8 + tg * 2;
            *(float2*)&smf[r0 * 132 + col]       = make_float2(acc[mf][nf][0], acc[mf][nf][1]);
            *(float2*)&smf[(r0 + 8) * 132 + col] = make_float2(acc[mf][nf][2], acc[mf][nf][3]);
        }
    __syncthreads();

    float4 b4 = *(const float4*)&bias[n0 + lane * 4];
    const float* b4p = &b4.x;
#pragma unroll
    for (int it = 0; it < 8; ++it) {
        int r = wid * 8 + it;
        int grow = m0 + r;
        float4 v = *(const float4*)&smf[r * 132 + lane * 4];
        float* vp = &v.x;
#pragma unroll
        for (int e = 0; e < 4; ++e) {
            float vv = vp[e] + b4p[e];
            if (ACT == 1) vv = gelu_exact(vv);
            vp[e] = vv;
        }
        if (WF32)
            *(float4*)(C + (size_t)grow * N + n0 + lane * 4) = v;
        if (WSP) {
            __half h[4], l[4];
#pragma unroll
            for (int e = 0; e < 4; ++e) split_hl(vp[e], h[e], l[e]);
            uint2 ph, pl;
            __half2* php = (__half2*)&ph; __half2* plp = (__half2*)&pl;
            php[0] = __halves2half2(h[0], h[1]); php[1] = __halves2half2(h[2], h[3]);
            plp[0] = __halves2half2(l[0], l[1]); plp[1] = __halves2half2(l[2], l[3]);
            size_t base = (size_t)grow * 3 * N;
            int cc = n0 + lane * 4;
            *(uint2*)((__half*)Asp + base + cc)         = ph;
            *(uint2*)((__half*)Asp + base + N + cc)     = pl;
            *(uint2*)((__half*)Asp + base + 2 * N + cc) = ph;
        }
    }
}

// ------------------------- LayerNorm(residual) + split ----------------------
__global__ void ln_res(const float* __restrict__ X, const float* __restrict__ R,
                       const float* __restrict__ g, const float* __restrict__ b,
                       float* __restrict__ out, __half* __restrict__ osp)
{
    int row = blockIdx.x, tid = threadIdx.x;
    float x = X[row * ND + tid] + R[row * ND + tid];
    float m = block_sum_128(x) * (1.0f / 128.0f);
    float d = x - m;
    float v = block_sum_128(d * d) * (1.0f / 128.0f);
    float y = d * rsqrtf(v + 1e-5f) * g[tid] + b[tid];
    out[row * ND + tid] = y;
    __half h, l; split_hl(y, h, l);
    __half* o = osp + (size_t)row * 384;
    o[tid] = h; o[128 + tid] = l; o[256 + tid] = h;
}

// ------- LN2 + hyperbolic embedding + head operand emission -----------------
__global__ void ln2_emb(const float* __restrict__ xs, const float* __restrict__ f,
                        const float* __restrict__ g, const float* __restrict__ b,
                        const float* __restrict__ logc,
                        float* __restrict__ emb,
                        float* __restrict__ e2o, float* __restrict__ deo)
{
    int row = blockIdx.x, tid = threadIdx.x;
    float x = xs[row * ND + tid] + f[row * ND + tid];
    float m = block_sum_128(x) * (1.0f / 128.0f);
    float d = x - m;
    float v = block_sum_128(d * d) * (1.0f / 128.0f);
    float y = d * rsqrtf(v + 1e-5f) * g[tid] + b[tid];

    float c, sc; curvature(logc, c, sc);
    float n2 = block_sum_128(y * y);
    float vn = fmaxf(sqrtf(n2), 1e-10f);
    float e = tanhf(sc * vn * 0.5f) * y / (sc * vn);
    float en2 = block_sum_128(e * e);
    float en = sqrtf(en2);
    float maxn = (1.0f - 1e-5f) / sc;
    float scl = fminf(maxn / fmaxf(en, 1e-6f), 1.0f);
    e *= scl;
    emb[row * ND + tid] = e;

    __half *A1 = (__half*)g_A1e, *A2 = (__half*)g_A2e;
    __half hh, ll;
    split_hl(e, hh, ll);
    A1[(size_t)row * KHEAD + tid] = hh;
    A1[(size_t)row * KHEAD + 128 + tid] = ll;
    split_hl(y, hh, ll);
    A2[(size_t)row * KHEAD + tid] = hh;
    A2[(size_t)row * KHEAD + 128 + tid] = ll;

    if (tid == 0) {
        float e2 = en2 * scl * scl;
        e2o[row] = e2;
        deo[row] = 1.0f - c * fminf(e2, 1.0f - 1e-5f);
    }
}

// --------------- prototype scaling + split (padded to NC2) -----------------
__global__ void proto_prep(const float* __restrict__ P, const float* __restrict__ logc)
{
    int row = blockIdx.x, tid = threadIdx.x;
    float p = (row < NC) ? P[(size_t)row * ND + tid] : 0.0f;
    float n2 = block_sum_128(p * p);
    float c, sc; curvature(logc, c, sc);
    float maxn = (1.0f - 1e-5f) / sc;
    float scl = fminf(maxn / fmaxf(sqrtf(n2), 1e-6f), 1.0f);
    p *= scl;
    __half* B1 = (__half*)g_B1e;
    __half hh = __float2half_rn(p);
    B1[(size_t)row * KHEAD + tid] = hh;
    B1[(size_t)row * KHEAD + 128 + tid] = hh;
    if (tid == 0) {
        float p2 = n2 * scl * scl;
        g_p2[row] = p2;
        g_dp[row] = 1.0f - c * fminf(p2, 1.0f - 1e-5f);
    }
}

// --------- euc_w transpose + split, coalesced via smem tile ----------------
__global__ void __launch_bounds__(256) euc_prep(const float* __restrict__ W,
                                                const float* __restrict__ bias)
{
    __shared__ float tile[128 * 65];
    const int tid = threadIdx.x;
    const int c0 = blockIdx.x * 64;
#pragma unroll
    for (int it = 0; it < 32; ++it) {
        int idx = it * 256 + tid;
        int k = idx >> 6, cc = idx & 63;
        int cls = c0 + cc;
        tile[k * 65 + cc] = (cls < NC) ? W[(size_t)k * NC + cls] : 0.0f;
    }
    __syncthreads();
    const int cc = tid >> 2, q = tid & 3;
    __half* B2 = (__half*)g_B2e;
    const size_t base = (size_t)(c0 + cc) * KHEAD;
#pragma unroll
    for (int j = q * 32; j < q * 32 + 32; ++j) {
        __half hh = __float2half_rn(tile[j * 65 + cc]);
        B2[base + j] = hh;
        B2[base + 128 + j] = hh;
    }
    if (tid < 64) {
        int cls = c0 + tid;
        g_eb[cls] = (cls < NC) ? bias[cls] : 0.0f;
    }
}

// ---------------- mma.sync dual GEMM + fused epilogue (head) ---------------
#define STAGE_BYTES 32768
#define NSTAGE 4
#define SMEM_BYTES (128 * 132 * 4)

__global__ void __launch_bounds__(256, 2) dual_mma(
    const float* __restrict__ e2v, const float* __restrict__ dev,
    const float* __restrict__ logc,
    float* __restrict__ hyp, float* __restrict__ euc)
{
    extern __shared__ char smem[];
    float* smf = (float*)smem;
    const int tid = threadIdx.x, wid = tid >> 5, lane = tid & 31;
    const int z = blockIdx.z;
    const int m0 = blockIdx.y * 128, n0 = blockIdx.x * 128;
    const char* Ag = (const char*)(z ? g_A2e : g_A1e);
    const char* Bg = (const char*)(z ? g_B2e : g_B1e);
    const uint32_t sbase = smem_u32(smem);
    const int warp_m = wid & 1, warp_n = wid >> 1;
    const int quad = lane >> 3, l8 = lane & 7;

    float acc[4][4][4] = {};

    auto load_stage = [&](int s) {
        const uint32_t sA = sbase + (uint32_t)(s & 1) * STAGE_BYTES;
        const uint32_t sB = sA + 16384;
        const size_t kb = (size_t)s * 128;
#pragma unroll
        for (int j = 0; j < 4; ++j) {
            int idx = tid + 256 * j;
            int row = idx >> 3, ch = idx & 7;
            uint32_t so = row * 128 + ((ch ^ (row & 7)) << 4);
            cp_async16(sA + so, Ag + (size_t)(m0 + row) * (KHEAD * 2) + kb + ch * 16);
            cp_async16(sB + so, Bg + (size_t)(n0 + row) * (KHEAD * 2) + kb + ch * 16);
        }
        asm volatile("cp.async.commit_group;" ::: "memory");
    };

    load_stage(0);
#pragma unroll 1
    for (int s = 0; s < NSTAGE; ++s) {
        if (s + 1 < NSTAGE) {
            load_stage(s + 1);
            asm volatile("cp.async.wait_group 1;" ::: "memory");
        } else {
            asm volatile("cp.async.wait_group 0;" ::: "memory");
        }
        __syncthreads();
        const uint32_t aB = sbase + (uint32_t)(s & 1) * STAGE_BYTES;
        const uint32_t bB = aB + 16384;
#pragma unroll
        for (int ks = 0; ks < 4; ++ks) {
            uint32_t a[4][4];
#pragma unroll
            for (int mf = 0; mf < 4; ++mf) {
                int mr = warp_m * 64 + mf * 16 + (quad & 1) * 8 + l8;
                int kc = ks * 2 + (quad >> 1);
                ldmx4(aB + mr * 128 + ((kc ^ (mr & 7)) << 4),
                      a[mf][0], a[mf][1], a[mf][2], a[mf][3]);
            }
            uint32_t b[2][4];
#pragma unroll
            for (int nh = 0; nh < 2; ++nh) {
                int nr = warp_n * 32 + nh * 16 + (quad >> 1) * 8 + l8;
                int kc = ks * 2 + (quad & 1);
                ldmx4(bB + nr * 128 + ((kc ^ (nr & 7)) << 4),
                      b[nh][0], b[nh][1], b[nh][2], b[nh][3]);
            }
#pragma unroll
            for (int mf = 0; mf < 4; ++mf)
#pragma unroll
                for (int nf = 0; nf < 4; ++nf)
                    mma_fp16(acc[mf][nf], a[mf], b[nf >> 1][(nf & 1) * 2],
                             b[nf >> 1][(nf & 1) * 2 + 1]);
        }
        __syncthreads();
    }

    const int g = lane >> 2, tg = lane & 3;
#pragma unroll
    for (int mf = 0; mf < 4; ++mf)
#pragma unroll
        for (int nf = 0; nf < 4; ++nf) {
            int r0 = warp_m * 64 + mf * 16 + g;
            int col = warp_n * 32 + nf * 8 + tg * 2;
            *(float2*)&smf[r0 * 132 + col]       = make_float2(acc[mf][nf][0], acc[mf][nf][1]);
            *(float2*)&smf[(r0 + 8) * 132 + col] = make_float2(acc[mf][nf][2], acc[mf][nf][3]);
        }
    __syncthreads();

    float inv2sc = 0.f;
    if (z == 0) {
        float c_, sc_; curvature(logc, c_, sc_);
        inv2sc = 2.0f / sc_;
    }
    float* dst = z ? euc : hyp;
    const int gc = n0 + lane * 4;
    const bool ok = gc < NC;

#pragma unroll 1
    for (int it = 0; it < 16; ++it) {
        int r = wid * 16 + it;
        int grow = m0 + r;
        float4 v = *(const float4*)&smf[r * 132 + lane * 4];
        float* vp = &v.x;
        if (z == 0) {
            float e2r = e2v[grow], der = dev[grow];
            float4 p2 = *(const float4*)&g_p2[gc];
            float4 dp = *(const float4*)&g_dp[gc];
            const float* p2p = &p2.x; const float* dpp = &dp.x;
#pragma unroll
            for (int e = 0; e < 4; ++e) {
                float diff = fmaxf(e2r + p2p[e] - 2.0f * vp[e], 1e-10f);
                float den  = fmaxf(der * dpp[e], 1e-6f);
                float num  = fmaf(2.0f, diff, den);
                float dist;
                if (diff >= 32.0f * den) {
                    dist = plog(num) - plog(den) + 0.69314718055994531f;
                } else {
                    float arg = fmaxf(__fdividef(num, den), 1.0f + 1e-6f);
                    dist = acoshf(arg);
                }
                vp[e] = -inv2sc * dist;
            }
        } else {
            float4 eb = *(const float4*)&g_eb[gc];
            v.x += eb.x; v.y += eb.y; v.z += eb.z; v.w += eb.w;
        }
        if (ok) *(float4*)(dst + (size_t)grow * NC + gc) = v;
    }
}

// ------------------------------- launch -------------------------------------
extern "C" void kernel_launch(void* const* d_in, const int* in_sizes, int n_in,
                              void* d_out, int out_size)
{
    const float* x      = (const float*)d_in[0];
    const float* W1     = (const float*)d_in[1];
    const float* b1     = (const float*)d_in[2];
    const float* W2     = (const float*)d_in[3];
    const float* b2     = (const float*)d_in[4];
    const float* in_w   = (const float*)d_in[5];
    const float* in_b   = (const float*)d_in[6];
    const float* out_w  = (const float*)d_in[7];
    const float* out_b  = (const float*)d_in[8];
    const float* fw1    = (const float*)d_in[9];
    const float* fb1    = (const float*)d_in[10];
    const float* fw2    = (const float*)d_in[11];
    const float* fb2    = (const float*)d_in[12];
    const float* g1     = (const float*)d_in[13];
    const float* bt1    = (const float*)d_in[14];
    const float* g2     = (const float*)d_in[15];
    const float* bt2    = (const float*)d_in[16];
    const float* logc   = (const float*)d_in[17];
    const float* protos = (const float*)d_in[18];
    const float* euc_w  = (const float*)d_in[19];
    const float* euc_b  = (const float*)d_in[20];

    float *t, *ao, *xs, *f, *e2, *de, *Wp, *bp;
    __half *xsp, *t1sp, *tsp, *xssp, *hsp, *W1p, *W2p, *fw1p, *fw2p, *Wpp;
    cudaGetSymbolAddress((void**)&t,    g_t);
    cudaGetSymbolAddress((void**)&ao,   g_ao);
    cudaGetSymbolAddress((void**)&xs,   g_xs);
    cudaGetSymbolAddress((void**)&f,    g_f);
    cudaGetSymbolAddress((void**)&e2,   g_e2);
    cudaGetSymbolAddress((void**)&de,   g_de);
    cudaGetSymbolAddress((void**)&Wp,   g_Wp);
    cudaGetSymbolAddress((void**)&bp,   g_bp);
    cudaGetSymbolAddress((void**)&xsp,  g_xsp);
    cudaGetSymbolAddress((void**)&t1sp, g_t1sp);
    cudaGetSymbolAddress((void**)&tsp,  g_tsp);
    cudaGetSymbolAddress((void**)&xssp, g_xssp);
    cudaGetSymbolAddress((void**)&hsp,  g_hsp);
    cudaGetSymbolAddress((void**)&W1p,  g_W1p);
    cudaGetSymbolAddress((void**)&W2p,  g_W2p);
    cudaGetSymbolAddress((void**)&fw1p, g_fw1p);
    cudaGetSymbolAddress((void**)&fw2p, g_fw2p);
    cudaGetSymbolAddress((void**)&Wpp,  g_Wpp);

    float* out = (float*)d_out;
    float* hyp = out;
    float* euc = out + (size_t)NB * NC;
    float* emb = out + (size_t)NB * NC * 2;

    cudaFuncSetAttribute(dual_mma, cudaFuncAttributeMaxDynamicSharedMemorySize, SMEM_BYTES);
    cudaFuncSetAttribute(hgemm<1,0,1>, cudaFuncAttributeMaxDynamicSharedMemorySize, HSMEM);
    cudaFuncSetAttribute(hgemm<0,1,1>, cudaFuncAttributeMaxDynamicSharedMemorySize, HSMEM);
    cudaFuncSetAttribute(hgemm<0,1,0>, cudaFuncAttributeMaxDynamicSharedMemorySize, HSMEM);

    // preps
    proto_prep<<<NC2, 128>>>(protos, logc);
    euc_prep <<<NC2 / 64, 256>>>(euc_w, euc_b);
    fold_w<<<ND + 1, 128>>>(in_w, out_w, in_b, out_b);
    asplit<<<NB, 256>>>(x, xsp, NIN);
    wprep<<<dim3(NIN / 32, 256 / 32), 256>>>(W1, W1p, NIN, 256);
    wprep<<<dim3(256 / 32, 128 / 32), 256>>>(W2, W2p, 256, 128);
    wprep<<<dim3(128 / 32, 512 / 32), 256>>>(fw1, fw1p, 128, 512);
    wprep<<<dim3(512 / 32, 128 / 32), 256>>>(fw2, fw2p, 512, 128);
    wprep<<<dim3(128 / 32, 128 / 32), 256>>>(Wp, Wpp, 128, 128);

    // front-end on tensor path
    hgemm<1,0,1><<<dim3(2, NB / 64), 256, HSMEM>>>(xsp,  W1p,  b1, nullptr, t1sp, 3072, 256);
    hgemm<0,1,1><<<dim3(1, NB / 64), 256, HSMEM>>>(t1sp, W2p,  b2, t,       tsp,  768,  128);
    hgemm<0,1,0><<<dim3(1, NB / 64), 256, HSMEM>>>(tsp,  Wpp,  bp, ao,      nullptr, 384, 128);
    ln_res<<<NB, 128>>>(t, ao, g1, bt1, xs, xssp);
    hgemm<1,0,1><<<dim3(4, NB / 64), 256, HSMEM>>>(xssp, fw1p, fb1, nullptr, hsp, 384,  512);
    hgemm<0,1,0><<<dim3(1, NB / 64), 256, HSMEM>>>(hsp,  fw2p, fb2, f,      nullptr, 1536, 128);

    // LN2 + hyperbolic embedding + head A operands
    ln2_emb<<<NB, 128>>>(xs, f, g2, bt2, logc, emb, e2, de);

    // head: dual GEMM + fused epilogues
    dual_mma<<<dim3(NC2 / 128, NB / 128, 2), 256, SMEM_BYTES>>>(e2, de, logc, hyp, euc);
}

// round 6
// speedup vs baseline: 2.6372x; 1.0107x over previous
#include <cuda_runtime.h>
#include <cuda_fp16.h>
#include <math.h>
#include <stdint.h>

// ---------------------------------------------------------------------------
// B=4096, IN_DIM=1024, D=128, C=10000. seq_len==1 -> attn == v (q,k dead),
// v/out_w fold into one GEMM. Whole net on mma.sync fp16:
//   front-end: 3-term hi/lo split (fp32-quality); head: 2-term (2e-4).
// LN1 and LN2+hyperbolic-embedding are fused into GEMM epilogues.
// proto/euc preps overlap the front-end on a second stream.
// ---------------------------------------------------------------------------

#define NB   4096
#define NIN  1024
#define ND   128
#define NC   10000
#define NC2  10112
#define KHEAD 256

// ------------------------- device scratch (no allocs) ----------------------
__device__ float g_t [NB * ND];
__device__ float g_xs[NB * ND];
__device__ float g_e2[NB];
__device__ float g_de[NB];
__device__ float g_Wp[ND * ND];
__device__ float g_bp[ND];
__device__ uint4 g_xsp [NB * 3072 / 8];
__device__ uint4 g_t1sp[NB * 768  / 8];
__device__ uint4 g_tsp [NB * 384  / 8];
__device__ uint4 g_xssp[NB * 384  / 8];
__device__ uint4 g_hsp [NB * 1536 / 8];
__device__ uint4 g_W1p [256 * 3072 / 8];
__device__ uint4 g_W2p [128 * 768  / 8];
__device__ uint4 g_fw1p[512 * 384  / 8];
__device__ uint4 g_fw2p[128 * 1536 / 8];
__device__ uint4 g_Wpp [128 * 384  / 8];
__device__ uint4 g_A1e[NB  * KHEAD / 8];
__device__ uint4 g_A2e[NB  * KHEAD / 8];
__device__ uint4 g_B1e[NC2 * KHEAD / 8];
__device__ uint4 g_B2e[NC2 * KHEAD / 8];
__device__ float g_p2[NC2];
__device__ float g_dp[NC2];
__device__ float g_eb[NC2];

// ------------------------------ helpers ------------------------------------
static __device__ __forceinline__ uint32_t smem_u32(const void* p) {
    uint32_t a;
    asm("{ .reg .u64 t; cvta.to.shared.u64 t, %1; cvt.u32.u64 %0, t; }" : "=r"(a) : "l"(p));
    return a;
}
static __device__ __forceinline__ void cp_async16(uint32_t s, const void* g) {
    asm volatile("cp.async.cg.shared.global [%0], [%1], 16;" :: "r"(s), "l"(g) : "memory");
}
static __device__ __forceinline__ void ldmx4(uint32_t a, uint32_t& r0, uint32_t& r1,
                                             uint32_t& r2, uint32_t& r3) {
    asm volatile("ldmatrix.sync.aligned.m8n8.x4.shared.b16 {%0,%1,%2,%3}, [%4];"
                 : "=r"(r0), "=r"(r1), "=r"(r2), "=r"(r3) : "r"(a));
}
static __device__ __forceinline__ void mma_fp16(float* d, const uint32_t* a,
                                                uint32_t b0, uint32_t b1) {
    asm volatile("mma.sync.aligned.m16n8k16.row.col.f32.f16.f16.f32 "
                 "{%0,%1,%2,%3}, {%4,%5,%6,%7}, {%8,%9}, {%0,%1,%2,%3};"
                 : "+f"(d[0]), "+f"(d[1]), "+f"(d[2]), "+f"(d[3])
                 : "r"(a[0]), "r"(a[1]), "r"(a[2]), "r"(a[3]), "r"(b0), "r"(b1));
}
static __device__ __forceinline__ float gelu_exact(float x) {
    return 0.5f * x * (1.0f + erff(x * 0.70710678118654752440f));
}
static __device__ __forceinline__ float warp_sum(float v) {
#pragma unroll
    for (int o = 16; o > 0; o >>= 1) v += __shfl_xor_sync(0xffffffffu, v, o);
    return v;
}
static __device__ __forceinline__ float block_sum_128(float v) {
    __shared__ float sh[4];
    int lane = threadIdx.x & 31, wid = threadIdx.x >> 5;
    v = warp_sum(v);
    __syncthreads();
    if (lane == 0) sh[wid] = v;
    __syncthreads();
    return sh[0] + sh[1] + sh[2] + sh[3];
}
static __device__ __forceinline__ void curvature(const float* logc, float& c, float& sc) {
    float cc = expf(logc[0]);
    cc = fminf(fmaxf(cc, 1e-4f), 10.0f);
    cc = fmaxf(fabsf(cc), 1e-6f);
    c = cc; sc = sqrtf(cc);
}
static __device__ __forceinline__ void split_hl(float x, __half& h, __half& l) {
    h = __float2half_rn(x);
    l = __float2half_rn(x - __half2float(h));
}
// pack 4 floats' hi/lo halves; store as uint2 each
static __device__ __forceinline__ void split4_store(const float* v, __half* hip, __half* lop) {
    __half h[4], l[4];
#pragma unroll
    for (int e = 0; e < 4; ++e) split_hl(v[e], h[e], l[e]);
    __half2 h01 = __halves2half2(h[0], h[1]), h23 = __halves2half2(h[2], h[3]);
    __half2 l01 = __halves2half2(l[0], l[1]), l23 = __halves2half2(l[2], l[3]);
    uint2 ph, pl;
    ph.x = *(uint32_t*)&h01; ph.y = *(uint32_t*)&h23;
    pl.x = *(uint32_t*)&l01; pl.y = *(uint32_t*)&l23;
    *(uint2*)hip = ph;
    *(uint2*)lop = pl;
}
static __device__ __forceinline__ void pack4_store(const float* v, __half* hip) {
    __half h[4];
#pragma unroll
    for (int e = 0; e < 4; ++e) h[e] = __float2half_rn(v[e]);
    __half2 h01 = __halves2half2(h[0], h[1]), h23 = __halves2half2(h[2], h[3]);
    uint2 ph; ph.x = *(uint32_t*)&h01; ph.y = *(uint32_t*)&h23;
    *(uint2*)hip = ph;
}
static __device__ __forceinline__ float plog(float x) {
    int i = __float_as_int(x);
    int e = (i - 0x3f3504f3) >> 23;
    float m = __int_as_float(i - (e << 23));
    float t = m - 1.0f;
    float p = 0.14285715f;
    p = fmaf(p, t, -0.16666667f);
    p = fmaf(p, t, 0.20000000f);
    p = fmaf(p, t, -0.25000000f);
    p = fmaf(p, t, 0.33333334f);
    p = fmaf(p, t, -0.50000000f);
    p = fmaf(p, t, 1.00000000f);
    p = p * t;
    return fmaf((float)e, 0.69314718055994531f, p);
}

// ------------------- preps -------------------------------------------------
// x [rows][K] fp32 -> [rows][3K] fp16 (hi|lo|hi), vectorized
__global__ void asplit(const float* __restrict__ X, __half* __restrict__ out, int K)
{
    int row = blockIdx.x;
    const float4* xr = (const float4*)(X + (size_t)row * K);
    __half* o = out + (size_t)row * 3 * K;
    for (int k4 = threadIdx.x; k4 < (K >> 2); k4 += 256) {
        float4 v = xr[k4];
        float* vp = &v.x;
        int k = k4 * 4;
        __half h[4], l[4];
#pragma unroll
        for (int e = 0; e < 4; ++e) split_hl(vp[e], h[e], l[e]);
        __half2 h01 = __halves2half2(h[0], h[1]), h23 = __halves2half2(h[2], h[3]);
        __half2 l01 = __halves2half2(l[0], l[1]), l23 = __halves2half2(l[2], l[3]);
        uint2 ph, pl;
        ph.x = *(uint32_t*)&h01; ph.y = *(uint32_t*)&h23;
        pl.x = *(uint32_t*)&l01; pl.y = *(uint32_t*)&l23;
        *(uint2*)(o + k) = ph;
        *(uint2*)(o + K + k) = pl;
        *(uint2*)(o + 2 * K + k) = ph;
    }
}
// W [K][N] fp32 -> out [N][3K] fp16 (hi|hi|lo), transposed via smem
__global__ void __launch_bounds__(256) wprep(const float* __restrict__ W,
                                             __half* __restrict__ out, int K, int N)
{
    __shared__ float t[32][33];
    const int k0 = blockIdx.x * 32, n0 = blockIdx.y * 32;
    const int tx = threadIdx.x & 31, ty = threadIdx.x >> 5;
#pragma unroll
    for (int i = ty; i < 32; i += 8)
        t[i][tx] = W[(size_t)(k0 + i) * N + n0 + tx];
    __syncthreads();
#pragma unroll
    for (int i = ty; i < 32; i += 8) {
        int n = n0 + i, k = k0 + tx;
        __half h, l; split_hl(t[tx][i], h, l);
        size_t base = (size_t)n * 3 * K;
        out[base + k] = h; out[base + K + k] = h; out[base + 2 * K + k] = l;
    }
}
__global__ void fold_w(const float* __restrict__ in_w, const float* __restrict__ out_w,
                       const float* __restrict__ in_b, const float* __restrict__ out_b)
{
    int j = threadIdx.x;
    if (blockIdx.x < ND) {
        int k = blockIdx.x;
        float s = 0.f;
#pragma unroll 8
        for (int m = 0; m < ND; ++m)
            s = fmaf(in_w[k * 384 + 256 + m], out_w[m * ND + j], s);
        g_Wp[k * ND + j] = s;
    } else {
        float s = out_b[j];
#pragma unroll 8
        for (int m = 0; m < ND; ++m)
            s = fmaf(in_b[256 + m], out_w[m * ND + j], s);
        g_bp[j] = s;
    }
}
// prototype scaling + split (padded to NC2)
__global__ void proto_prep(const float* __restrict__ P, const float* __restrict__ logc)
{
    int row = blockIdx.x, tid = threadIdx.x;
    float p = (row < NC) ? P[(size_t)row * ND + tid] : 0.0f;
    float n2 = block_sum_128(p * p);
    float c, sc; curvature(logc, c, sc);
    float maxn = (1.0f - 1e-5f) / sc;
    float scl = fminf(maxn / fmaxf(sqrtf(n2), 1e-6f), 1.0f);
    p *= scl;
    __half* B1 = (__half*)g_B1e;
    __half hh = __float2half_rn(p);
    B1[(size_t)row * KHEAD + tid] = hh;
    B1[(size_t)row * KHEAD + 128 + tid] = hh;
    if (tid == 0) {
        float p2 = n2 * scl * scl;
        g_p2[row] = p2;
        g_dp[row] = 1.0f - c * fminf(p2, 1.0f - 1e-5f);
    }
}
// euc_w transpose + split, vectorized stores
__global__ void __launch_bounds__(256) euc_prep(const float* __restrict__ W,
                                                const float* __restrict__ bias)
{
    __shared__ float tile[128 * 65];
    const int tid = threadIdx.x;
    const int c0 = blockIdx.x * 64;
#pragma unroll
    for (int it = 0; it < 32; ++it) {
        int idx = it * 256 + tid;
        int k = idx >> 6, cc = idx & 63;
        int cls = c0 + cc;
        tile[k * 65 + cc] = (cls < NC) ? W[(size_t)k * NC + cls] : 0.0f;
    }
    __syncthreads();
    const int cc = tid & 63, q = tid >> 6;
    __half* B2 = (__half*)g_B2e;
    const size_t base = (size_t)(c0 + cc) * KHEAD;
#pragma unroll
    for (int j8 = 0; j8 < 4; ++j8) {
        int k = q * 32 + j8 * 8;
        __half2 hp[4];
#pragma unroll
        for (int e = 0; e < 4; ++e)
            hp[e] = __halves2half2(__float2half_rn(tile[(k + 2 * e) * 65 + cc]),
                                   __float2half_rn(tile[(k + 2 * e + 1) * 65 + cc]));
        uint4 pk;
        pk.x = *(uint32_t*)&hp[0]; pk.y = *(uint32_t*)&hp[1];
        pk.z = *(uint32_t*)&hp[2]; pk.w = *(uint32_t*)&hp[3];
        *(uint4*)(B2 + base + k) = pk;
        *(uint4*)(B2 + base + 128 + k) = pk;
    }
    if (tid < 64) {
        int cls = c0 + tid;
        g_eb[cls] = (cls < NC) ? bias[cls] : 0.0f;
    }
}

// ---------------- tensor GEMM 64x128 tile, fused epilogues ------------------
// EPI 0: C = act(A@Bt^T + bias); optional fp32 out (WF32) and 3-term split (WSP)
// EPI 1: ln_res fused:  xs = LN(R + gemm+bias); writes C=xs fp32 + Asp=3-term split
// EPI 2: ln2+emb fused: y = LN(R + gemm+bias); hyperbolic emb; writes C=emb,
//        Asp=A1 (2-term emb split), Asp2=A2 (2-term y split), e2o, deo
#define HSTAGE 24576
#define HSMEM  49152

template <int ACT, int EPI, int WF32, int WSP>
__global__ void __launch_bounds__(256, 2) hgemm(
    const __half* __restrict__ A, const __half* __restrict__ Bt,
    const float* __restrict__ bias,
    float* __restrict__ C, __half* __restrict__ Asp, __half* __restrict__ Asp2,
    const float* __restrict__ R, const float* __restrict__ gg,
    const float* __restrict__ bb, const float* __restrict__ logc,
    float* __restrict__ e2o, float* __restrict__ deo,
    int KE, int N)
{
    extern __shared__ char smem[];
    float* smf = (float*)smem;
    const int tid = threadIdx.x, wid = tid >> 5, lane = tid & 31;
    const int m0 = blockIdx.y * 64, n0 = blockIdx.x * 128;
    const uint32_t sbase = smem_u32(smem);
    const int warp_m = wid & 1, warp_n = wid >> 1;
    const int quad = lane >> 3, l8 = lane & 7;
    const int nstage = KE >> 6;

    float acc[2][4][4] = {};

    auto load_stage = [&](int s) {
        const uint32_t sA = sbase + (uint32_t)(s & 1) * HSTAGE;
        const uint32_t sB = sA + 8192;
        const size_t kb = (size_t)s * 128;
#pragma unroll
        for (int j = 0; j < 2; ++j) {
            int idx = tid + 256 * j;
            int row = idx >> 3, ch = idx & 7;
            uint32_t so = row * 128 + ((ch ^ (row & 7)) << 4);
            cp_async16(sA + so, (const char*)A + (size_t)(m0 + row) * (KE * 2) + kb + ch * 16);
        }
#pragma unroll
        for (int j = 0; j < 4; ++j) {
            int idx = tid + 256 * j;
            int row = idx >> 3, ch = idx & 7;
            uint32_t so = row * 128 + ((ch ^ (row & 7)) << 4);
            cp_async16(sB + so, (const char*)Bt + (size_t)(n0 + row) * (KE * 2) + kb + ch * 16);
        }
        asm volatile("cp.async.commit_group;" ::: "memory");
    };

    load_stage(0);
#pragma unroll 1
    for (int s = 0; s < nstage; ++s) {
        if (s + 1 < nstage) {
            load_stage(s + 1);
            asm volatile("cp.async.wait_group 1;" ::: "memory");
        } else {
            asm volatile("cp.async.wait_group 0;" ::: "memory");
        }
        __syncthreads();
        const uint32_t aB = sbase + (uint32_t)(s & 1) * HSTAGE;
        const uint32_t bB = aB + 8192;
#pragma unroll
        for (int ks = 0; ks < 4; ++ks) {
            uint32_t a[2][4];
#pragma unroll
            for (int mf = 0; mf < 2; ++mf) {
                int mr = warp_m * 32 + mf * 16 + (quad & 1) * 8 + l8;
                int kc = ks * 2 + (quad >> 1);
                ldmx4(aB + mr * 128 + ((kc ^ (mr & 7)) << 4),
                      a[mf][0], a[mf][1], a[mf][2], a[mf][3]);
            }
            uint32_t b[2][4];
#pragma unroll
            for (int nh = 0; nh < 2; ++nh) {
                int nr = warp_n * 32 + nh * 16 + (quad >> 1) * 8 + l8;
                int kc = ks * 2 + (quad & 1);
                ldmx4(bB + nr * 128 + ((kc ^ (nr & 7)) << 4),
                      b[nh][0], b[nh][1], b[nh][2], b[nh][3]);
            }
#pragma unroll
            for (int mf = 0; mf < 2; ++mf)
#pragma unroll
                for (int nf = 0; nf < 4; ++nf)
                    mma_fp16(acc[mf][nf], a[mf], b[nf >> 1][(nf & 1) * 2],
                             b[nf >> 1][(nf & 1) * 2 + 1]);
        }
        __syncthreads();
    }

    // transpose through smem (64 x 132 floats)
    const int g = lane >> 2, tg = lane & 3;
#pragma unroll
    for (int mf = 0; mf < 2; ++mf)
#pragma unroll
        for (int nf = 0; nf < 4; ++nf) {
            int r0 = warp_m * 32 + mf * 16 + g;
            int col = warp_n * 32 + nf * 8 + tg * 2;
            *(float2*)&smf[r0 * 132 + col]       = make_float2(acc[mf][nf][0], acc[mf][nf][1]);
            *(float2*)&smf[(r0 + 8) * 132 + col] = make_float2(acc[mf][nf][2], acc[mf][nf][3]);
        }
    __syncthreads();

    float4 b4 = *(const float4*)&bias[n0 + lane * 4];
    const float* b4p = &b4.x;

    if (EPI == 0) {
#pragma unroll
        for (int it = 0; it < 8; ++it) {
            int r = wid * 8 + it;
            int grow = m0 + r;
            float4 v = *(const float4*)&smf[r * 132 + lane * 4];
            float* vp = &v.x;
#pragma unroll
            for (int e = 0; e < 4; ++e) {
                float vv = vp[e] + b4p[e];
                if (ACT == 1) vv = gelu_exact(vv);
                vp[e] = vv;
            }
            if (WF32)
                *(float4*)(C + (size_t)grow * N + n0 + lane * 4) = v;
            if (WSP) {
                size_t base = (size_t)grow * 3 * N;
                int cc = n0 + lane * 4;
                __half* hp = Asp + base + cc;
                split4_store(vp, hp, hp + N);
                pack4_store(vp, hp + 2 * N);
            }
        }
    } else {
        float c_ = 0.f, sc_ = 0.f, maxn = 0.f;
        if (EPI == 2) { curvature(logc, c_, sc_); maxn = (1.0f - 1e-5f) / sc_; }
        float4 g4 = *(const float4*)&gg[lane * 4];
        float4 bt4 = *(const float4*)&bb[lane * 4];
        const float* g4p = &g4.x; const float* bt4p = &bt4.x;
#pragma unroll 1
        for (int it = 0; it < 8; ++it) {
            int r = wid * 8 + it;
            int grow = m0 + r;
            float4 v = *(const float4*)&smf[r * 132 + lane * 4];
            float* vp = &v.x;
            float4 rr = *(const float4*)&R[(size_t)grow * ND + lane * 4];
            const float* rrp = &rr.x;
            float x[4];
#pragma unroll
            for (int e = 0; e < 4; ++e) x[e] = vp[e] + b4p[e] + rrp[e];
            float m = warp_sum(x[0] + x[1] + x[2] + x[3]) * (1.0f / 128.0f);
            float q = 0.f;
#pragma unroll
            for (int e = 0; e < 4; ++e) { x[e] -= m; q += x[e] * x[e]; }
            float var = warp_sum(q) * (1.0f / 128.0f);
            float rstd = rsqrtf(var + 1e-5f);
            float y[4];
#pragma unroll
            for (int e = 0; e < 4; ++e) y[e] = x[e] * rstd * g4p[e] + bt4p[e];

            if (EPI == 1) {
                *(float4*)(C + (size_t)grow * ND + lane * 4) = *(float4*)y;
                size_t base = (size_t)grow * 384;
                __half* hp = Asp + base + lane * 4;
                split4_store(y, hp, hp + 128);
                pack4_store(y, hp + 256);
            } else {
                float n2 = warp_sum(y[0]*y[0] + y[1]*y[1] + y[2]*y[2] + y[3]*y[3]);
                float vn = fmaxf(sqrtf(n2), 1e-10f);
                float kk = tanhf(sc_ * vn * 0.5f) / (sc_ * vn);
                float en = kk * vn;
                float scl = fminf(maxn / fmaxf(en, 1e-6f), 1.0f);
                float ke = kk * scl;
                float ee[4];
#pragma unroll
                for (int e = 0; e < 4; ++e) ee[e] = ke * y[e];
                *(float4*)(C + (size_t)grow * ND + lane * 4) = *(float4*)ee;
                size_t base = (size_t)grow * KHEAD;
                __half* a1 = Asp + base + lane * 4;
                split4_store(ee, a1, a1 + 128);
                __half* a2 = Asp2 + base + lane * 4;
                split4_store(y, a2, a2 + 128);
                if (lane == 0) {
                    float e2 = en * en * scl * scl;
                    e2o[grow] = e2;
                    deo[grow] = 1.0f - c_ * fminf(e2, 1.0f - 1e-5f);
                }
            }
        }
    }
}

// ---------------- mma.sync dual GEMM + fused epilogue (head) ---------------
#define STAGE_BYTES 32768
#define NSTAGE 4
#define SMEM_BYTES (128 * 132 * 4)

__global__ void __launch_bounds__(256, 2) dual_mma(
    const float* __restrict__ e2v, const float* __restrict__ dev,
    const float* __restrict__ logc,
    float* __restrict__ hyp, float* __restrict__ euc)
{
    extern __shared__ char smem[];
    float* smf = (float*)smem;
    const int tid = threadIdx.x, wid = tid >> 5, lane = tid & 31;
    const int z = blockIdx.z;
    const int m0 = blockIdx.y * 128, n0 = blockIdx.x * 128;
    const char* Ag = (const char*)(z ? g_A2e : g_A1e);
    const char* Bg = (const char*)(z ? g_B2e : g_B1e);
    const uint32_t sbase = smem_u32(smem);
    const int warp_m = wid & 1, warp_n = wid >> 1;
    const int quad = lane >> 3, l8 = lane & 7;

    float acc[4][4][4] = {};

    auto load_stage = [&](int s) {
        const uint32_t sA = sbase + (uint32_t)(s & 1) * STAGE_BYTES;
        const uint32_t sB = sA + 16384;
        const size_t kb = (size_t)s * 128;
#pragma unroll
        for (int j = 0; j < 4; ++j) {
            int idx = tid + 256 * j;
            int row = idx >> 3, ch = idx & 7;
            uint32_t so = row * 128 + ((ch ^ (row & 7)) << 4);
            cp_async16(sA + so, Ag + (size_t)(m0 + row) * (KHEAD * 2) + kb + ch * 16);
            cp_async16(sB + so, Bg + (size_t)(n0 + row) * (KHEAD * 2) + kb + ch * 16);
        }
        asm volatile("cp.async.commit_group;" ::: "memory");
    };

    load_stage(0);
#pragma unroll 1
    for (int s = 0; s < NSTAGE; ++s) {
        if (s + 1 < NSTAGE) {
            load_stage(s + 1);
            asm volatile("cp.async.wait_group 1;" ::: "memory");
        } else {
            asm volatile("cp.async.wait_group 0;" ::: "memory");
        }
        __syncthreads();
        const uint32_t aB = sbase + (uint32_t)(s & 1) * STAGE_BYTES;
        const uint32_t bB = aB + 16384;
#pragma unroll
        for (int ks = 0; ks < 4; ++ks) {
            uint32_t a[4][4];
#pragma unroll
            for (int mf = 0; mf < 4; ++mf) {
                int mr = warp_m * 64 + mf * 16 + (quad & 1) * 8 + l8;
                int kc = ks * 2 + (quad >> 1);
                ldmx4(aB + mr * 128 + ((kc ^ (mr & 7)) << 4),
                      a[mf][0], a[mf][1], a[mf][2], a[mf][3]);
            }
            uint32_t b[2][4];
#pragma unroll
            for (int nh = 0; nh < 2; ++nh) {
                int nr = warp_n * 32 + nh * 16 + (quad >> 1) * 8 + l8;
                int kc = ks * 2 + (quad & 1);
                ldmx4(bB + nr * 128 + ((kc ^ (nr & 7)) << 4),
                      b[nh][0], b[nh][1], b[nh][2], b[nh][3]);
            }
#pragma unroll
            for (int mf = 0; mf < 4; ++mf)
#pragma unroll
                for (int nf = 0; nf < 4; ++nf)
                    mma_fp16(acc[mf][nf], a[mf], b[nf >> 1][(nf & 1) * 2],
                             b[nf >> 1][(nf & 1) * 2 + 1]);
        }
        __syncthreads();
    }

    const int g = lane >> 2, tg = lane & 3;
#pragma unroll
    for (int mf = 0; mf < 4; ++mf)
#pragma unroll
        for (int nf = 0; nf < 4; ++nf) {
            int r0 = warp_m * 64 + mf * 16 + g;
            int col = warp_n * 32 + nf * 8 + tg * 2;
            *(float2*)&smf[r0 * 132 + col]       = make_float2(acc[mf][nf][0], acc[mf][nf][1]);
            *(float2*)&smf[(r0 + 8) * 132 + col] = make_float2(acc[mf][nf][2], acc[mf][nf][3]);
        }
    __syncthreads();

    float inv2sc = 0.f;
    if (z == 0) {
        float c_, sc_; curvature(logc, c_, sc_);
        inv2sc = 2.0f / sc_;
    }
    float* dst = z ? euc : hyp;
    const int gc = n0 + lane * 4;
    const bool ok = gc < NC;

#pragma unroll 1
    for (int it = 0; it < 16; ++it) {
        int r = wid * 16 + it;
        int grow = m0 + r;
        float4 v = *(const float4*)&smf[r * 132 + lane * 4];
        float* vp = &v.x;
        if (z == 0) {
            float e2r = e2v[grow], der = dev[grow];
            float4 p2 = *(const float4*)&g_p2[gc];
            float4 dp = *(const float4*)&g_dp[gc];
            const float* p2p = &p2.x; const float* dpp = &dp.x;
#pragma unroll
            for (int e = 0; e < 4; ++e) {
                float diff = fmaxf(e2r + p2p[e] - 2.0f * vp[e], 1e-10f);
                float den  = fmaxf(der * dpp[e], 1e-6f);
                float num  = fmaf(2.0f, diff, den);
                float dist;
                if (diff >= 32.0f * den) {
                    dist = plog(num) - plog(den) + 0.69314718055994531f;
                } else {
                    float arg = fmaxf(__fdividef(num, den), 1.0f + 1e-6f);
                    dist = acoshf(arg);
                }
                vp[e] = -inv2sc * dist;
            }
        } else {
            float4 eb = *(const float4*)&g_eb[gc];
            v.x += eb.x; v.y += eb.y; v.z += eb.z; v.w += eb.w;
        }
        if (ok) *(float4*)(dst + (size_t)grow * NC + gc) = v;
    }
}

// ------------------------------- launch -------------------------------------
extern "C" void kernel_launch(void* const* d_in, const int* in_sizes, int n_in,
                              void* d_out, int out_size)
{
    const float* x      = (const float*)d_in[0];
    const float* W1     = (const float*)d_in[1];
    const float* b1     = (const float*)d_in[2];
    const float* W2     = (const float*)d_in[3];
    const float* b2     = (const float*)d_in[4];
    const float* in_w   = (const float*)d_in[5];
    const float* in_b   = (const float*)d_in[6];
    const float* out_w  = (const float*)d_in[7];
    const float* out_b  = (const float*)d_in[8];
    const float* fw1    = (const float*)d_in[9];
    const float* fb1    = (const float*)d_in[10];
    const float* fw2    = (const float*)d_in[11];
    const float* fb2    = (const float*)d_in[12];
    const float* g1     = (const float*)d_in[13];
    const float* bt1    = (const float*)d_in[14];
    const float* g2     = (const float*)d_in[15];
    const float* bt2    = (const float*)d_in[16];
    const float* logc   = (const float*)d_in[17];
    const float* protos = (const float*)d_in[18];
    const float* euc_w  = (const float*)d_in[19];
    const float* euc_b  = (const float*)d_in[20];

    float *t, *xs, *e2, *de, *Wp, *bp;
    __half *xsp, *t1sp, *tsp, *xssp, *hsp, *W1p, *W2p, *fw1p, *fw2p, *Wpp, *A1, *A2;
    cudaGetSymbolAddress((void**)&t,    g_t);
    cudaGetSymbolAddress((void**)&xs,   g_xs);
    cudaGetSymbolAddress((void**)&e2,   g_e2);
    cudaGetSymbolAddress((void**)&de,   g_de);
    cudaGetSymbolAddress((void**)&Wp,   g_Wp);
    cudaGetSymbolAddress((void**)&bp,   g_bp);
    cudaGetSymbolAddress((void**)&xsp,  g_xsp);
    cudaGetSymbolAddress((void**)&t1sp, g_t1sp);
    cudaGetSymbolAddress((void**)&tsp,  g_tsp);
    cudaGetSymbolAddress((void**)&xssp, g_xssp);
    cudaGetSymbolAddress((void**)&hsp,  g_hsp);
    cudaGetSymbolAddress((void**)&W1p,  g_W1p);
    cudaGetSymbolAddress((void**)&W2p,  g_W2p);
    cudaGetSymbolAddress((void**)&fw1p, g_fw1p);
    cudaGetSymbolAddress((void**)&fw2p, g_fw2p);
    cudaGetSymbolAddress((void**)&Wpp,  g_Wpp);
    cudaGetSymbolAddress((void**)&A1,   g_A1e);
    cudaGetSymbolAddress((void**)&A2,   g_A2e);

    float* out = (float*)d_out;
    float* hyp = out;
    float* euc = out + (size_t)NB * NC;
    float* emb = out + (size_t)NB * NC * 2;

    static cudaStream_t s2 = nullptr;
    static cudaEvent_t evF = nullptr, evJ = nullptr;
    if (!s2) {
        cudaStreamCreateWithFlags(&s2, cudaStreamNonBlocking);
        cudaEventCreateWithFlags(&evF, cudaEventDisableTiming);
        cudaEventCreateWithFlags(&evJ, cudaEventDisableTiming);
        cudaFuncSetAttribute(dual_mma, cudaFuncAttributeMaxDynamicSharedMemorySize, SMEM_BYTES);
        cudaFuncSetAttribute(hgemm<1,0,0,1>, cudaFuncAttributeMaxDynamicSharedMemorySize, HSMEM);
        cudaFuncSetAttribute(hgemm<0,0,1,1>, cudaFuncAttributeMaxDynamicSharedMemorySize, HSMEM);
        cudaFuncSetAttribute(hgemm<0,1,0,0>, cudaFuncAttributeMaxDynamicSharedMemorySize, HSMEM);
        cudaFuncSetAttribute(hgemm<0,2,0,0>, cudaFuncAttributeMaxDynamicSharedMemorySize, HSMEM);
    }

    // ---- fork: head B-preps on s2, overlapped with the front-end ----
    cudaEventRecord(evF, 0);
    cudaStreamWaitEvent(s2, evF, 0);
    proto_prep<<<NC2, 128, 0, s2>>>(protos, logc);
    euc_prep <<<NC2 / 64, 256, 0, s2>>>(euc_w, euc_b);
    cudaEventRecord(evJ, s2);

    // ---- main stream: weight preps + front-end chain ----
    asplit<<<NB, 256>>>(x, xsp, NIN);
    wprep<<<dim3(NIN / 32, 256 / 32), 256>>>(W1, W1p, NIN, 256);
    wprep<<<dim3(256 / 32, 128 / 32), 256>>>(W2, W2p, 256, 128);
    wprep<<<dim3(128 / 32, 512 / 32), 256>>>(fw1, fw1p, 128, 512);
    wprep<<<dim3(512 / 32, 128 / 32), 256>>>(fw2, fw2p, 512, 128);
    fold_w<<<ND + 1, 128>>>(in_w, out_w, in_b, out_b);
    wprep<<<dim3(128 / 32, 128 / 32), 256>>>(Wp, Wpp, 128, 128);

    hgemm<1,0,0,1><<<dim3(2, NB / 64), 256, HSMEM>>>(
        xsp, W1p, b1, nullptr, t1sp, nullptr, nullptr, nullptr, nullptr, nullptr,
        nullptr, nullptr, 3072, 256);
    hgemm<0,0,1,1><<<dim3(1, NB / 64), 256, HSMEM>>>(
        t1sp, W2p, b2, t, tsp, nullptr, nullptr, nullptr, nullptr, nullptr,
        nullptr, nullptr, 768, 128);
    // attention GEMM + fused residual-LN1 (emits xs + xssp)
    hgemm<0,1,0,0><<<dim3(1, NB / 64), 256, HSMEM>>>(
        tsp, Wpp, bp, xs, xssp, nullptr, t, g1, bt1, nullptr,
        nullptr, nullptr, 384, 128);
    hgemm<1,0,0,1><<<dim3(4, NB / 64), 256, HSMEM>>>(
        xssp, fw1p, fb1, nullptr, hsp, nullptr, nullptr, nullptr, nullptr, nullptr,
        nullptr, nullptr, 384, 512);
    // FFN-down GEMM + fused residual-LN2 + hyperbolic embedding (emits emb, A1, A2)
    hgemm<0,2,0,0><<<dim3(1, NB / 64), 256, HSMEM>>>(
        hsp, fw2p, fb2, emb, A1, A2, xs, g2, bt2, logc,
        e2, de, 1536, 128);

    // ---- join, then head ----
    cudaStreamWaitEvent(0, evJ, 0);
    dual_mma<<<dim3(NC2 / 128, NB / 128, 2), 256, SMEM_BYTES>>>(e2, de, logc, hyp, euc);
}

// round 7
// speedup vs baseline: 3.0028x; 1.1386x over previous
#include <cuda_runtime.h>
#include <cuda_fp16.h>
#include <math.h>
#include <stdint.h>

// ---------------------------------------------------------------------------
// B=4096, IN_DIM=1024, D=128, C=10000. seq_len==1 -> attn == v (q,k dead),
// v/out_w fold into one GEMM. Whole net on mma.sync fp16:
//   front-end: 3-term hi/lo split (fp32-quality); head: 2-term (2e-4).
// LN1 / LN2+hyperbolic-embedding fused into GEMM epilogues.
// Head epilogue: MUFU lg2-based acosh (arg is always >> 1 here).
// Weight/proto preps overlap the front-end on a second stream.
// ---------------------------------------------------------------------------

#define NB   4096
#define NIN  1024
#define ND   128
#define NC   10000
#define NC2  10112
#define KHEAD 256

// ------------------------- device scratch (no allocs) ----------------------
__device__ float g_t [NB * ND];
__device__ float g_xs[NB * ND];
__device__ float g_e2[NB];
__device__ float g_de[NB];
__device__ float g_Wp[ND * ND];
__device__ float g_bp[ND];
__device__ uint4 g_xsp [NB * 3072 / 8];
__device__ uint4 g_t1sp[NB * 768  / 8];
__device__ uint4 g_tsp [NB * 384  / 8];
__device__ uint4 g_xssp[NB * 384  / 8];
__device__ uint4 g_hsp [NB * 1536 / 8];
__device__ uint4 g_W1p [256 * 3072 / 8];
__device__ uint4 g_W2p [128 * 768  / 8];
__device__ uint4 g_fw1p[512 * 384  / 8];
__device__ uint4 g_fw2p[128 * 1536 / 8];
__device__ uint4 g_Wpp [128 * 384  / 8];
__device__ uint4 g_A1e[NB  * KHEAD / 8];
__device__ uint4 g_A2e[NB  * KHEAD / 8];
__device__ uint4 g_B1e[NC2 * KHEAD / 8];
__device__ uint4 g_B2e[NC2 * KHEAD / 8];
__device__ float g_p2[NC2];
__device__ float g_dp[NC2];
__device__ float g_eb[NC2];

// ------------------------------ helpers ------------------------------------
static __device__ __forceinline__ uint32_t smem_u32(const void* p) {
    uint32_t a;
    asm("{ .reg .u64 t; cvta.to.shared.u64 t, %1; cvt.u32.u64 %0, t; }" : "=r"(a) : "l"(p));
    return a;
}
static __device__ __forceinline__ void cp_async16(uint32_t s, const void* g) {
    asm volatile("cp.async.cg.shared.global [%0], [%1], 16;" :: "r"(s), "l"(g) : "memory");
}
static __device__ __forceinline__ void ldmx4(uint32_t a, uint32_t& r0, uint32_t& r1,
                                             uint32_t& r2, uint32_t& r3) {
    asm volatile("ldmatrix.sync.aligned.m8n8.x4.shared.b16 {%0,%1,%2,%3}, [%4];"
                 : "=r"(r0), "=r"(r1), "=r"(r2), "=r"(r3) : "r"(a));
}
static __device__ __forceinline__ void mma_fp16(float* d, const uint32_t* a,
                                                uint32_t b0, uint32_t b1) {
    asm volatile("mma.sync.aligned.m16n8k16.row.col.f32.f16.f16.f32 "
                 "{%0,%1,%2,%3}, {%4,%5,%6,%7}, {%8,%9}, {%0,%1,%2,%3};"
                 : "+f"(d[0]), "+f"(d[1]), "+f"(d[2]), "+f"(d[3])
                 : "r"(a[0]), "r"(a[1]), "r"(a[2]), "r"(a[3]), "r"(b0), "r"(b1));
}
static __device__ __forceinline__ float gelu_exact(float x) {
    return 0.5f * x * (1.0f + erff(x * 0.70710678118654752440f));
}
static __device__ __forceinline__ float warp_sum(float v) {
#pragma unroll
    for (int o = 16; o > 0; o >>= 1) v += __shfl_xor_sync(0xffffffffu, v, o);
    return v;
}
static __device__ __forceinline__ float block_sum_128(float v) {
    __shared__ float sh[4];
    int lane = threadIdx.x & 31, wid = threadIdx.x >> 5;
    v = warp_sum(v);
    __syncthreads();
    if (lane == 0) sh[wid] = v;
    __syncthreads();
    return sh[0] + sh[1] + sh[2] + sh[3];
}
static __device__ __forceinline__ void curvature(const float* logc, float& c, float& sc) {
    float cc = expf(logc[0]);
    cc = fminf(fmaxf(cc, 1e-4f), 10.0f);
    cc = fmaxf(fabsf(cc), 1e-6f);
    c = cc; sc = sqrtf(cc);
}
static __device__ __forceinline__ void split_hl(float x, __half& h, __half& l) {
    h = __float2half_rn(x);
    l = __float2half_rn(x - __half2float(h));
}
static __device__ __forceinline__ void split4_store(const float* v, __half* hip, __half* lop) {
    __half h[4], l[4];
#pragma unroll
    for (int e = 0; e < 4; ++e) split_hl(v[e], h[e], l[e]);
    __half2 h01 = __halves2half2(h[0], h[1]), h23 = __halves2half2(h[2], h[3]);
    __half2 l01 = __halves2half2(l[0], l[1]), l23 = __halves2half2(l[2], l[3]);
    uint2 ph, pl;
    ph.x = *(uint32_t*)&h01; ph.y = *(uint32_t*)&h23;
    pl.x = *(uint32_t*)&l01; pl.y = *(uint32_t*)&l23;
    *(uint2*)hip = ph;
    *(uint2*)lop = pl;
}
static __device__ __forceinline__ void pack4_store(const float* v, __half* hip) {
    __half h[4];
#pragma unroll
    for (int e = 0; e < 4; ++e) h[e] = __float2half_rn(v[e]);
    __half2 h01 = __halves2half2(h[0], h[1]), h23 = __halves2half2(h[2], h[3]);
    uint2 ph; ph.x = *(uint32_t*)&h01; ph.y = *(uint32_t*)&h23;
    *(uint2*)hip = ph;
}

// ------------------- preps -------------------------------------------------
__global__ void asplit(const float* __restrict__ X, __half* __restrict__ out, int K)
{
    int row = blockIdx.x;
    const float4* xr = (const float4*)(X + (size_t)row * K);
    __half* o = out + (size_t)row * 3 * K;
    for (int k4 = threadIdx.x; k4 < (K >> 2); k4 += 256) {
        float4 v = xr[k4];
        float* vp = &v.x;
        int k = k4 * 4;
        __half h[4], l[4];
#pragma unroll
        for (int e = 0; e < 4; ++e) split_hl(vp[e], h[e], l[e]);
        __half2 h01 = __halves2half2(h[0], h[1]), h23 = __halves2half2(h[2], h[3]);
        __half2 l01 = __halves2half2(l[0], l[1]), l23 = __halves2half2(l[2], l[3]);
        uint2 ph, pl;
        ph.x = *(uint32_t*)&h01; ph.y = *(uint32_t*)&h23;
        pl.x = *(uint32_t*)&l01; pl.y = *(uint32_t*)&l23;
        *(uint2*)(o + k) = ph;
        *(uint2*)(o + K + k) = pl;
        *(uint2*)(o + 2 * K + k) = ph;
    }
}
__global__ void __launch_bounds__(256) wprep(const float* __restrict__ W,
                                             __half* __restrict__ out, int K, int N)
{
    __shared__ float t[32][33];
    const int k0 = blockIdx.x * 32, n0 = blockIdx.y * 32;
    const int tx = threadIdx.x & 31, ty = threadIdx.x >> 5;
#pragma unroll
    for (int i = ty; i < 32; i += 8)
        t[i][tx] = W[(size_t)(k0 + i) * N + n0 + tx];
    __syncthreads();
#pragma unroll
    for (int i = ty; i < 32; i += 8) {
        int n = n0 + i, k = k0 + tx;
        __half h, l; split_hl(t[tx][i], h, l);
        size_t base = (size_t)n * 3 * K;
        out[base + k] = h; out[base + K + k] = h; out[base + 2 * K + k] = l;
    }
}
__global__ void fold_w(const float* __restrict__ in_w, const float* __restrict__ out_w,
                       const float* __restrict__ in_b, const float* __restrict__ out_b)
{
    int j = threadIdx.x;
    if (blockIdx.x < ND) {
        int k = blockIdx.x;
        float s = 0.f;
#pragma unroll 8
        for (int m = 0; m < ND; ++m)
            s = fmaf(in_w[k * 384 + 256 + m], out_w[m * ND + j], s);
        g_Wp[k * ND + j] = s;
    } else {
        float s = out_b[j];
#pragma unroll 8
        for (int m = 0; m < ND; ++m)
            s = fmaf(in_b[256 + m], out_w[m * ND + j], s);
        g_bp[j] = s;
    }
}
__global__ void proto_prep(const float* __restrict__ P, const float* __restrict__ logc)
{
    int row = blockIdx.x, tid = threadIdx.x;
    float p = (row < NC) ? P[(size_t)row * ND + tid] : 0.0f;
    float n2 = block_sum_128(p * p);
    float c, sc; curvature(logc, c, sc);
    float maxn = (1.0f - 1e-5f) / sc;
    float scl = fminf(maxn / fmaxf(sqrtf(n2), 1e-6f), 1.0f);
    p *= scl;
    __half* B1 = (__half*)g_B1e;
    __half hh = __float2half_rn(p);
    B1[(size_t)row * KHEAD + tid] = hh;
    B1[(size_t)row * KHEAD + 128 + tid] = hh;
    if (tid == 0) {
        float p2 = n2 * scl * scl;
        g_p2[row] = p2;
        g_dp[row] = 1.0f - c * fminf(p2, 1.0f - 1e-5f);
    }
}
__global__ void __launch_bounds__(256) euc_prep(const float* __restrict__ W,
                                                const float* __restrict__ bias)
{
    __shared__ float tile[128 * 65];
    const int tid = threadIdx.x;
    const int c0 = blockIdx.x * 64;
#pragma unroll
    for (int it = 0; it < 32; ++it) {
        int idx = it * 256 + tid;
        int k = idx >> 6, cc = idx & 63;
        int cls = c0 + cc;
        tile[k * 65 + cc] = (cls < NC) ? W[(size_t)k * NC + cls] : 0.0f;
    }
    __syncthreads();
    const int cc = tid & 63, q = tid >> 6;
    __half* B2 = (__half*)g_B2e;
    const size_t base = (size_t)(c0 + cc) * KHEAD;
#pragma unroll
    for (int j8 = 0; j8 < 4; ++j8) {
        int k = q * 32 + j8 * 8;
        __half2 hp[4];
#pragma unroll
        for (int e = 0; e < 4; ++e)
            hp[e] = __halves2half2(__float2half_rn(tile[(k + 2 * e) * 65 + cc]),
                                   __float2half_rn(tile[(k + 2 * e + 1) * 65 + cc]));
        uint4 pk;
        pk.x = *(uint32_t*)&hp[0]; pk.y = *(uint32_t*)&hp[1];
        pk.z = *(uint32_t*)&hp[2]; pk.w = *(uint32_t*)&hp[3];
        *(uint4*)(B2 + base + k) = pk;
        *(uint4*)(B2 + base + 128 + k) = pk;
    }
    if (tid < 64) {
        int cls = c0 + tid;
        g_eb[cls] = (cls < NC) ? bias[cls] : 0.0f;
    }
}

// ---------------- tensor GEMM 64x128 tile, fused epilogues ------------------
#define HSTAGE 24576
#define HSMEM  49152

template <int ACT, int EPI, int WF32, int WSP>
__global__ void __launch_bounds__(256, 2) hgemm(
    const __half* __restrict__ A, const __half* __restrict__ Bt,
    const float* __restrict__ bias,
    float* __restrict__ C, __half* __restrict__ Asp, __half* __restrict__ Asp2,
    const float* __restrict__ R, const float* __restrict__ gg,
    const float* __restrict__ bb, const float* __restrict__ logc,
    float* __restrict__ e2o, float* __restrict__ deo,
    int KE, int N)
{
    extern __shared__ char smem[];
    float* smf = (float*)smem;
    const int tid = threadIdx.x, wid = tid >> 5, lane = tid & 31;
    const int m0 = blockIdx.y * 64, n0 = blockIdx.x * 128;
    const uint32_t sbase = smem_u32(smem);
    const int warp_m = wid & 1, warp_n = wid >> 1;
    const int quad = lane >> 3, l8 = lane & 7;
    const int nstage = KE >> 6;

    float acc[2][4][4] = {};

    auto load_stage = [&](int s) {
        const uint32_t sA = sbase + (uint32_t)(s & 1) * HSTAGE;
        const uint32_t sB = sA + 8192;
        const size_t kb = (size_t)s * 128;
#pragma unroll
        for (int j = 0; j < 2; ++j) {
            int idx = tid + 256 * j;
            int row = idx >> 3, ch = idx & 7;
            uint32_t so = row * 128 + ((ch ^ (row & 7)) << 4);
            cp_async16(sA + so, (const char*)A + (size_t)(m0 + row) * (KE * 2) + kb + ch * 16);
        }
#pragma unroll
        for (int j = 0; j < 4; ++j) {
            int idx = tid + 256 * j;
            int row = idx >> 3, ch = idx & 7;
            uint32_t so = row * 128 + ((ch ^ (row & 7)) << 4);
            cp_async16(sB + so, (const char*)Bt + (size_t)(n0 + row) * (KE * 2) + kb + ch * 16);
        }
        asm volatile("cp.async.commit_group;" ::: "memory");
    };

    load_stage(0);
#pragma unroll 1
    for (int s = 0; s < nstage; ++s) {
        if (s + 1 < nstage) {
            load_stage(s + 1);
            asm volatile("cp.async.wait_group 1;" ::: "memory");
        } else {
            asm volatile("cp.async.wait_group 0;" ::: "memory");
        }
        __syncthreads();
        const uint32_t aB = sbase + (uint32_t)(s & 1) * HSTAGE;
        const uint32_t bB = aB + 8192;
#pragma unroll
        for (int ks = 0; ks < 4; ++ks) {
            uint32_t a[2][4];
#pragma unroll
            for (int mf = 0; mf < 2; ++mf) {
                int mr = warp_m * 32 + mf * 16 + (quad & 1) * 8 + l8;
                int kc = ks * 2 + (quad >> 1);
                ldmx4(aB + mr * 128 + ((kc ^ (mr & 7)) << 4),
                      a[mf][0], a[mf][1], a[mf][2], a[mf][3]);
            }
            uint32_t b[2][4];
#pragma unroll
            for (int nh = 0; nh < 2; ++nh) {
                int nr = warp_n * 32 + nh * 16 + (quad >> 1) * 8 + l8;
                int kc = ks * 2 + (quad & 1);
                ldmx4(bB + nr * 128 + ((kc ^ (nr & 7)) << 4),
                      b[nh][0], b[nh][1], b[nh][2], b[nh][3]);
            }
#pragma unroll
            for (int mf = 0; mf < 2; ++mf)
#pragma unroll
                for (int nf = 0; nf < 4; ++nf)
                    mma_fp16(acc[mf][nf], a[mf], b[nf >> 1][(nf & 1) * 2],
                             b[nf >> 1][(nf & 1) * 2 + 1]);
        }
        __syncthreads();
    }

    const int g = lane >> 2, tg = lane & 3;
#pragma unroll
    for (int mf = 0; mf < 2; ++mf)
#pragma unroll
        for (int nf = 0; nf < 4; ++nf) {
            int r0 = warp_m * 32 + mf * 16 + g;
            int col = warp_n * 32 + nf * 8 + tg * 2;
            *(float2*)&smf[r0 * 132 + col]       = make_float2(acc[mf][nf][0], acc[mf][nf][1]);
            *(float2*)&smf[(r0 + 8) * 132 + col] = make_float2(acc[mf][nf][2], acc[mf][nf][3]);
        }
    __syncthreads();

    float4 b4 = *(const float4*)&bias[n0 + lane * 4];
    const float* b4p = &b4.x;

    if (EPI == 0) {
#pragma unroll
        for (int it = 0; it < 8; ++it) {
            int r = wid * 8 + it;
            int grow = m0 + r;
            float4 v = *(const float4*)&smf[r * 132 + lane * 4];
            float* vp = &v.x;
#pragma unroll
            for (int e = 0; e < 4; ++e) {
                float vv = vp[e] + b4p[e];
                if (ACT == 1) vv = gelu_exact(vv);
                vp[e] = vv;
            }
            if (WF32)
                *(float4*)(C + (size_t)grow * N + n0 + lane * 4) = v;
            if (WSP) {
                size_t base = (size_t)grow * 3 * N;
                int cc = n0 + lane * 4;
                __half* hp = Asp + base + cc;
                split4_store(vp, hp, hp + N);
                pack4_store(vp, hp + 2 * N);
            }
        }
    } else {
        float c_ = 0.f, sc_ = 0.f, maxn = 0.f;
        if (EPI == 2) { curvature(logc, c_, sc_); maxn = (1.0f - 1e-5f) / sc_; }
        float4 g4 = *(const float4*)&gg[lane * 4];
        float4 bt4 = *(const float4*)&bb[lane * 4];
        const float* g4p = &g4.x; const float* bt4p = &bt4.x;
#pragma unroll 1
        for (int it = 0; it < 8; ++it) {
            int r = wid * 8 + it;
            int grow = m0 + r;
            float4 v = *(const float4*)&smf[r * 132 + lane * 4];
            float* vp = &v.x;
            float4 rr = *(const float4*)&R[(size_t)grow * ND + lane * 4];
            const float* rrp = &rr.x;
            float x[4];
#pragma unroll
            for (int e = 0; e < 4; ++e) x[e] = vp[e] + b4p[e] + rrp[e];
            float m = warp_sum(x[0] + x[1] + x[2] + x[3]) * (1.0f / 128.0f);
            float q = 0.f;
#pragma unroll
            for (int e = 0; e < 4; ++e) { x[e] -= m; q += x[e] * x[e]; }
            float var = warp_sum(q) * (1.0f / 128.0f);
            float rstd = rsqrtf(var + 1e-5f);
            float y[4];
#pragma unroll
            for (int e = 0; e < 4; ++e) y[e] = x[e] * rstd * g4p[e] + bt4p[e];

            if (EPI == 1) {
                *(float4*)(C + (size_t)grow * ND + lane * 4) = *(float4*)y;
                size_t base = (size_t)grow * 384;
                __half* hp = Asp + base + lane * 4;
                split4_store(y, hp, hp + 128);
                pack4_store(y, hp + 256);
            } else {
                float n2 = warp_sum(y[0]*y[0] + y[1]*y[1] + y[2]*y[2] + y[3]*y[3]);
                float vn = fmaxf(sqrtf(n2), 1e-10f);
                float kk = tanhf(sc_ * vn * 0.5f) / (sc_ * vn);
                float en = kk * vn;
                float scl = fminf(maxn / fmaxf(en, 1e-6f), 1.0f);
                float ke = kk * scl;
                float ee[4];
#pragma unroll
                for (int e = 0; e < 4; ++e) ee[e] = ke * y[e];
                *(float4*)(C + (size_t)grow * ND + lane * 4) = *(float4*)ee;
                size_t base = (size_t)grow * KHEAD;
                __half* a1 = Asp + base + lane * 4;
                split4_store(ee, a1, a1 + 128);
                __half* a2 = Asp2 + base + lane * 4;
                split4_store(y, a2, a2 + 128);
                if (lane == 0) {
                    float e2 = en * en * scl * scl;
                    e2o[grow] = e2;
                    deo[grow] = 1.0f - c_ * fminf(e2, 1.0f - 1e-5f);
                }
            }
        }
    }
}

// ---------------- mma.sync dual GEMM + fused epilogue (head) ---------------
#define STAGE_BYTES 32768
#define NSTAGE 4
#define SMEM_BYTES (128 * 132 * 4)

__global__ void __launch_bounds__(256, 2) dual_mma(
    const float* __restrict__ e2v, const float* __restrict__ dev,
    const float* __restrict__ logc,
    float* __restrict__ hyp, float* __restrict__ euc)
{
    extern __shared__ char smem[];
    float* smf = (float*)smem;
    const int tid = threadIdx.x, wid = tid >> 5, lane = tid & 31;
    const int z = blockIdx.z;
    const int m0 = blockIdx.y * 128, n0 = blockIdx.x * 128;
    const char* Ag = (const char*)(z ? g_A2e : g_A1e);
    const char* Bg = (const char*)(z ? g_B2e : g_B1e);
    const uint32_t sbase = smem_u32(smem);
    const int warp_m = wid & 1, warp_n = wid >> 1;
    const int quad = lane >> 3, l8 = lane & 7;

    float acc[4][4][4] = {};

    auto load_stage = [&](int s) {
        const uint32_t sA = sbase + (uint32_t)(s & 1) * STAGE_BYTES;
        const uint32_t sB = sA + 16384;
        const size_t kb = (size_t)s * 128;
#pragma unroll
        for (int j = 0; j < 4; ++j) {
            int idx = tid + 256 * j;
            int row = idx >> 3, ch = idx & 7;
            uint32_t so = row * 128 + ((ch ^ (row & 7)) << 4);
            cp_async16(sA + so, Ag + (size_t)(m0 + row) * (KHEAD * 2) + kb + ch * 16);
            cp_async16(sB + so, Bg + (size_t)(n0 + row) * (KHEAD * 2) + kb + ch * 16);
        }
        asm volatile("cp.async.commit_group;" ::: "memory");
    };

    load_stage(0);
#pragma unroll 1
    for (int s = 0; s < NSTAGE; ++s) {
        if (s + 1 < NSTAGE) {
            load_stage(s + 1);
            asm volatile("cp.async.wait_group 1;" ::: "memory");
        } else {
            asm volatile("cp.async.wait_group 0;" ::: "memory");
        }
        __syncthreads();
        const uint32_t aB = sbase + (uint32_t)(s & 1) * STAGE_BYTES;
        const uint32_t bB = aB + 16384;
#pragma unroll
        for (int ks = 0; ks < 4; ++ks) {
            uint32_t a[4][4];
#pragma unroll
            for (int mf = 0; mf < 4; ++mf) {
                int mr = warp_m * 64 + mf * 16 + (quad & 1) * 8 + l8;
                int kc = ks * 2 + (quad >> 1);
                ldmx4(aB + mr * 128 + ((kc ^ (mr & 7)) << 4),
                      a[mf][0], a[mf][1], a[mf][2], a[mf][3]);
            }
            uint32_t b[2][4];
#pragma unroll
            for (int nh = 0; nh < 2; ++nh) {
                int nr = warp_n * 32 + nh * 16 + (quad >> 1) * 8 + l8;
                int kc = ks * 2 + (quad & 1);
                ldmx4(bB + nr * 128 + ((kc ^ (nr & 7)) << 4),
                      b[nh][0], b[nh][1], b[nh][2], b[nh][3]);
            }
#pragma unroll
            for (int mf = 0; mf < 4; ++mf)
#pragma unroll
                for (int nf = 0; nf < 4; ++nf)
                    mma_fp16(acc[mf][nf], a[mf], b[nf >> 1][(nf & 1) * 2],
                             b[nf >> 1][(nf & 1) * 2 + 1]);
        }
        __syncthreads();
    }

    const int g = lane >> 2, tg = lane & 3;
#pragma unroll
    for (int mf = 0; mf < 4; ++mf)
#pragma unroll
        for (int nf = 0; nf < 4; ++nf) {
            int r0 = warp_m * 64 + mf * 16 + g;
            int col = warp_n * 32 + nf * 8 + tg * 2;
            *(float2*)&smf[r0 * 132 + col]       = make_float2(acc[mf][nf][0], acc[mf][nf][1]);
            *(float2*)&smf[(r0 + 8) * 132 + col] = make_float2(acc[mf][nf][2], acc[mf][nf][3]);
        }
    __syncthreads();

    const int gc = n0 + lane * 4;
    const bool ok = gc < NC;
    float* dst = z ? euc : hyp;

    float inv2sc = 0.f, slg = 0.f;
    float p2c[4], dpc[4], ebc[4];
    if (z == 0) {
        float c_, sc_; curvature(logc, c_, sc_);
        inv2sc = 2.0f / sc_;
        slg = -inv2sc * 0.69314718055994531f;   // -2/sc * ln2
        float4 p2 = *(const float4*)&g_p2[gc];
        float4 dp = *(const float4*)&g_dp[gc];
        p2c[0]=p2.x; p2c[1]=p2.y; p2c[2]=p2.z; p2c[3]=p2.w;
        dpc[0]=dp.x; dpc[1]=dp.y; dpc[2]=dp.z; dpc[3]=dp.w;
    } else {
        float4 eb = *(const float4*)&g_eb[gc];
        ebc[0]=eb.x; ebc[1]=eb.y; ebc[2]=eb.z; ebc[3]=eb.w;
    }

#pragma unroll 2
    for (int it = 0; it < 16; ++it) {
        int r = wid * 16 + it;
        int grow = m0 + r;
        float4 v = *(const float4*)&smf[r * 132 + lane * 4];
        float* vp = &v.x;
        if (z == 0) {
            float e2r = e2v[grow], der = dev[grow];
#pragma unroll
            for (int e = 0; e < 4; ++e) {
                float diff = fmaxf(e2r + p2c[e] - 2.0f * vp[e], 1e-10f);
                float den  = fmaxf(der * dpc[e], 1e-6f);
                float num  = fmaf(2.0f, diff, den);
                float dist;
                if (diff >= 32.0f * den) {
                    // acosh(num/den) ~= ln(2*num/den) = ln2*(lg2(num)-lg2(den)+1)
                    dist = slg * (__log2f(num) - __log2f(den) + 1.0f);
                } else {
                    float arg = fmaxf(__fdividef(num, den), 1.0f + 1e-6f);
                    dist = -inv2sc * acoshf(arg);
                }
                vp[e] = dist;
            }
        } else {
            vp[0] += ebc[0]; vp[1] += ebc[1]; vp[2] += ebc[2]; vp[3] += ebc[3];
        }
        if (ok) __stcs((float4*)(dst + (size_t)grow * NC + gc), v);
    }
}

// ------------------------------- launch -------------------------------------
extern "C" void kernel_launch(void* const* d_in, const int* in_sizes, int n_in,
                              void* d_out, int out_size)
{
    const float* x      = (const float*)d_in[0];
    const float* W1     = (const float*)d_in[1];
    const float* b1     = (const float*)d_in[2];
    const float* W2     = (const float*)d_in[3];
    const float* b2     = (const float*)d_in[4];
    const float* in_w   = (const float*)d_in[5];
    const float* in_b   = (const float*)d_in[6];
    const float* out_w  = (const float*)d_in[7];
    const float* out_b  = (const float*)d_in[8];
    const float* fw1    = (const float*)d_in[9];
    const float* fb1    = (const float*)d_in[10];
    const float* fw2    = (const float*)d_in[11];
    const float* fb2    = (const float*)d_in[12];
    const float* g1     = (const float*)d_in[13];
    const float* bt1    = (const float*)d_in[14];
    const float* g2     = (const float*)d_in[15];
    const float* bt2    = (const float*)d_in[16];
    const float* logc   = (const float*)d_in[17];
    const float* protos = (const float*)d_in[18];
    const float* euc_w  = (const float*)d_in[19];
    const float* euc_b  = (const float*)d_in[20];

    float *t, *xs, *e2, *de, *Wp, *bp;
    __half *xsp, *t1sp, *tsp, *xssp, *hsp, *W1p, *W2p, *fw1p, *fw2p, *Wpp, *A1, *A2;
    cudaGetSymbolAddress((void**)&t,    g_t);
    cudaGetSymbolAddress((void**)&xs,   g_xs);
    cudaGetSymbolAddress((void**)&e2,   g_e2);
    cudaGetSymbolAddress((void**)&de,   g_de);
    cudaGetSymbolAddress((void**)&Wp,   g_Wp);
    cudaGetSymbolAddress((void**)&bp,   g_bp);
    cudaGetSymbolAddress((void**)&xsp,  g_xsp);
    cudaGetSymbolAddress((void**)&t1sp, g_t1sp);
    cudaGetSymbolAddress((void**)&tsp,  g_tsp);
    cudaGetSymbolAddress((void**)&xssp, g_xssp);
    cudaGetSymbolAddress((void**)&hsp,  g_hsp);
    cudaGetSymbolAddress((void**)&W1p,  g_W1p);
    cudaGetSymbolAddress((void**)&W2p,  g_W2p);
    cudaGetSymbolAddress((void**)&fw1p, g_fw1p);
    cudaGetSymbolAddress((void**)&fw2p, g_fw2p);
    cudaGetSymbolAddress((void**)&Wpp,  g_Wpp);
    cudaGetSymbolAddress((void**)&A1,   g_A1e);
    cudaGetSymbolAddress((void**)&A2,   g_A2e);

    float* out = (float*)d_out;
    float* hyp = out;
    float* euc = out + (size_t)NB * NC;
    float* emb = out + (size_t)NB * NC * 2;

    static cudaStream_t s2 = nullptr;
    static cudaEvent_t evF = nullptr, evW1 = nullptr, evW = nullptr, evJ = nullptr;
    if (!s2) {
        cudaStreamCreateWithFlags(&s2, cudaStreamNonBlocking);
        cudaEventCreateWithFlags(&evF, cudaEventDisableTiming);
        cudaEventCreateWithFlags(&evW1, cudaEventDisableTiming);
        cudaEventCreateWithFlags(&evW, cudaEventDisableTiming);
        cudaEventCreateWithFlags(&evJ, cudaEventDisableTiming);
        cudaFuncSetAttribute(dual_mma, cudaFuncAttributeMaxDynamicSharedMemorySize, SMEM_BYTES);
        cudaFuncSetAttribute(hgemm<1,0,0,1>, cudaFuncAttributeMaxDynamicSharedMemorySize, HSMEM);
        cudaFuncSetAttribute(hgemm<0,0,1,1>, cudaFuncAttributeMaxDynamicSharedMemorySize, HSMEM);
        cudaFuncSetAttribute(hgemm<0,1,0,0>, cudaFuncAttributeMaxDynamicSharedMemorySize, HSMEM);
        cudaFuncSetAttribute(hgemm<0,2,0,0>, cudaFuncAttributeMaxDynamicSharedMemorySize, HSMEM);
    }

    // ---- fork: side stream does all weight/proto preps ----
    cudaEventRecord(evF, 0);
    cudaStreamWaitEvent(s2, evF, 0);
    wprep<<<dim3(NIN / 32, 256 / 32), 256, 0, s2>>>(W1, W1p, NIN, 256);
    cudaEventRecord(evW1, s2);
    wprep<<<dim3(256 / 32, 128 / 32), 256, 0, s2>>>(W2, W2p, 256, 128);
    wprep<<<dim3(128 / 32, 512 / 32), 256, 0, s2>>>(fw1, fw1p, 128, 512);
    wprep<<<dim3(512 / 32, 128 / 32), 256, 0, s2>>>(fw2, fw2p, 512, 128);
    fold_w<<<ND + 1, 128, 0, s2>>>(in_w, out_w, in_b, out_b);
    wprep<<<dim3(128 / 32, 128 / 32), 256, 0, s2>>>(Wp, Wpp, 128, 128);
    cudaEventRecord(evW, s2);
    proto_prep<<<NC2, 128, 0, s2>>>(protos, logc);
    euc_prep <<<NC2 / 64, 256, 0, s2>>>(euc_w, euc_b);
    cudaEventRecord(evJ, s2);

    // ---- main stream: activation split + front-end chain ----
    asplit<<<NB, 256>>>(x, xsp, NIN);
    cudaStreamWaitEvent(0, evW1, 0);
    hgemm<1,0,0,1><<<dim3(2, NB / 64), 256, HSMEM>>>(
        xsp, W1p, b1, nullptr, t1sp, nullptr, nullptr, nullptr, nullptr, nullptr,
        nullptr, nullptr, 3072, 256);
    cudaStreamWaitEvent(0, evW, 0);
    hgemm<0,0,1,1><<<dim3(1, NB / 64), 256, HSMEM>>>(
        t1sp, W2p, b2, t, tsp, nullptr, nullptr, nullptr, nullptr, nullptr,
        nullptr, nullptr, 768, 128);
    hgemm<0,1,0,0><<<dim3(1, NB / 64), 256, HSMEM>>>(
        tsp, Wpp, bp, xs, xssp, nullptr, t, g1, bt1, nullptr,
        nullptr, nullptr, 384, 128);
    hgemm<1,0,0,1><<<dim3(4, NB / 64), 256, HSMEM>>>(
        xssp, fw1p, fb1, nullptr, hsp, nullptr, nullptr, nullptr, nullptr, nullptr,
        nullptr, nullptr, 384, 512);
    hgemm<0,2,0,0><<<dim3(1, NB / 64), 256, HSMEM>>>(
        hsp, fw2p, fb2, emb, A1, A2, xs, g2, bt2, logc,
        e2, de, 1536, 128);

    // ---- join, then head ----
    cudaStreamWaitEvent(0, evJ, 0);
    dual_mma<<<dim3(NC2 / 128, NB / 128, 2), 256, SMEM_BYTES>>>(e2, de, logc, hyp, euc);
}

// round 8
// speedup vs baseline: 3.2224x; 1.0731x over previous
#include <cuda_runtime.h>
#include <cuda_fp16.h>
#include <math.h>
#include <stdint.h>

// ---------------------------------------------------------------------------
// B=4096, IN_DIM=1024, D=128, C=10000. seq_len==1 -> attn == v (q,k dead),
// v/out_w fold into one GEMM. Whole net on mma.sync fp16:
//   front-end: 3-term hi/lo split (fp32-quality)
//   head hyp:  1-term fp16 (log compresses error; verified budget ~2e-6)
//   head euc:  2-term split (full-A x fp16-B, ~2e-4 — the binding error)
// LN1 / LN2+hyperbolic-embedding fused into GEMM epilogues.
// Head epilogue: MUFU lg2-based acosh. Preps overlap on a second stream.
// ---------------------------------------------------------------------------

#define NB   4096
#define NIN  1024
#define ND   128
#define NC   10000
#define NC2  10112
#define KEUC 256

// ------------------------- device scratch (no allocs) ----------------------
__device__ float g_t [NB * ND];
__device__ float g_xs[NB * ND];
__device__ float g_e2[NB];
__device__ float g_de[NB];
__device__ float g_Wp[ND * ND];
__device__ float g_bp[ND];
__device__ uint4 g_xsp [NB * 3072 / 8];
__device__ uint4 g_t1sp[NB * 768  / 8];
__device__ uint4 g_tsp [NB * 384  / 8];
__device__ uint4 g_xssp[NB * 384  / 8];
__device__ uint4 g_hsp [NB * 1536 / 8];
__device__ uint4 g_W1p [256 * 3072 / 8];
__device__ uint4 g_W2p [128 * 768  / 8];
__device__ uint4 g_fw1p[512 * 384  / 8];
__device__ uint4 g_fw2p[128 * 1536 / 8];
__device__ uint4 g_Wpp [128 * 384  / 8];
__device__ uint4 g_A1e[NB  * 128  / 8];   // emb fp16 (1-term, hyp A)
__device__ uint4 g_A2e[NB  * KEUC / 8];   // y split   (2-term, euc A)
__device__ uint4 g_B1e[NC2 * 128  / 8];   // protos fp16 (1-term, hyp B)
__device__ uint4 g_B2e[NC2 * KEUC / 8];   // euc_w^T dup (2-term, euc B)
__device__ float g_p2[NC2];
__device__ float g_dp[NC2];
__device__ float g_eb[NC2];

// ------------------------------ helpers ------------------------------------
static __device__ __forceinline__ uint32_t smem_u32(const void* p) {
    uint32_t a;
    asm("{ .reg .u64 t; cvta.to.shared.u64 t, %1; cvt.u32.u64 %0, t; }" : "=r"(a) : "l"(p));
    return a;
}
static __device__ __forceinline__ void cp_async16(uint32_t s, const void* g) {
    asm volatile("cp.async.cg.shared.global [%0], [%1], 16;" :: "r"(s), "l"(g) : "memory");
}
static __device__ __forceinline__ void ldmx4(uint32_t a, uint32_t& r0, uint32_t& r1,
                                             uint32_t& r2, uint32_t& r3) {
    asm volatile("ldmatrix.sync.aligned.m8n8.x4.shared.b16 {%0,%1,%2,%3}, [%4];"
                 : "=r"(r0), "=r"(r1), "=r"(r2), "=r"(r3) : "r"(a));
}
static __device__ __forceinline__ void mma_fp16(float* d, const uint32_t* a,
                                                uint32_t b0, uint32_t b1) {
    asm volatile("mma.sync.aligned.m16n8k16.row.col.f32.f16.f16.f32 "
                 "{%0,%1,%2,%3}, {%4,%5,%6,%7}, {%8,%9}, {%0,%1,%2,%3};"
                 : "+f"(d[0]), "+f"(d[1]), "+f"(d[2]), "+f"(d[3])
                 : "r"(a[0]), "r"(a[1]), "r"(a[2]), "r"(a[3]), "r"(b0), "r"(b1));
}
static __device__ __forceinline__ float gelu_exact(float x) {
    return 0.5f * x * (1.0f + erff(x * 0.70710678118654752440f));
}
static __device__ __forceinline__ float warp_sum(float v) {
#pragma unroll
    for (int o = 16; o > 0; o >>= 1) v += __shfl_xor_sync(0xffffffffu, v, o);
    return v;
}
static __device__ __forceinline__ float block_sum_128(float v) {
    __shared__ float sh[4];
    int lane = threadIdx.x & 31, wid = threadIdx.x >> 5;
    v = warp_sum(v);
    __syncthreads();
    if (lane == 0) sh[wid] = v;
    __syncthreads();
    return sh[0] + sh[1] + sh[2] + sh[3];
}
static __device__ __forceinline__ void curvature(const float* logc, float& c, float& sc) {
    float cc = expf(logc[0]);
    cc = fminf(fmaxf(cc, 1e-4f), 10.0f);
    cc = fmaxf(fabsf(cc), 1e-6f);
    c = cc; sc = sqrtf(cc);
}
static __device__ __forceinline__ void split_hl(float x, __half& h, __half& l) {
    h = __float2half_rn(x);
    l = __float2half_rn(x - __half2float(h));
}
static __device__ __forceinline__ void split4_store(const float* v, __half* hip, __half* lop) {
    __half h[4], l[4];
#pragma unroll
    for (int e = 0; e < 4; ++e) split_hl(v[e], h[e], l[e]);
    __half2 h01 = __halves2half2(h[0], h[1]), h23 = __halves2half2(h[2], h[3]);
    __half2 l01 = __halves2half2(l[0], l[1]), l23 = __halves2half2(l[2], l[3]);
    uint2 ph, pl;
    ph.x = *(uint32_t*)&h01; ph.y = *(uint32_t*)&h23;
    pl.x = *(uint32_t*)&l01; pl.y = *(uint32_t*)&l23;
    *(uint2*)hip = ph;
    *(uint2*)lop = pl;
}
static __device__ __forceinline__ void pack4_store(const float* v, __half* hip) {
    __half h[4];
#pragma unroll
    for (int e = 0; e < 4; ++e) h[e] = __float2half_rn(v[e]);
    __half2 h01 = __halves2half2(h[0], h[1]), h23 = __halves2half2(h[2], h[3]);
    uint2 ph; ph.x = *(uint32_t*)&h01; ph.y = *(uint32_t*)&h23;
    *(uint2*)hip = ph;
}

// ------------------- preps -------------------------------------------------
__global__ void asplit(const float* __restrict__ X, __half* __restrict__ out, int K)
{
    int row = blockIdx.x;
    const float4* xr = (const float4*)(X + (size_t)row * K);
    __half* o = out + (size_t)row * 3 * K;
    for (int k4 = threadIdx.x; k4 < (K >> 2); k4 += 256) {
        float4 v = xr[k4];
        float* vp = &v.x;
        int k = k4 * 4;
        __half h[4], l[4];
#pragma unroll
        for (int e = 0; e < 4; ++e) split_hl(vp[e], h[e], l[e]);
        __half2 h01 = __halves2half2(h[0], h[1]), h23 = __halves2half2(h[2], h[3]);
        __half2 l01 = __halves2half2(l[0], l[1]), l23 = __halves2half2(l[2], l[3]);
        uint2 ph, pl;
        ph.x = *(uint32_t*)&h01; ph.y = *(uint32_t*)&h23;
        pl.x = *(uint32_t*)&l01; pl.y = *(uint32_t*)&l23;
        *(uint2*)(o + k) = ph;
        *(uint2*)(o + K + k) = pl;
        *(uint2*)(o + 2 * K + k) = ph;
    }
}
__global__ void __launch_bounds__(256) wprep(const float* __restrict__ W,
                                             __half* __restrict__ out, int K, int N)
{
    __shared__ float t[32][33];
    const int k0 = blockIdx.x * 32, n0 = blockIdx.y * 32;
    const int tx = threadIdx.x & 31, ty = threadIdx.x >> 5;
#pragma unroll
    for (int i = ty; i < 32; i += 8)
        t[i][tx] = W[(size_t)(k0 + i) * N + n0 + tx];
    __syncthreads();
#pragma unroll
    for (int i = ty; i < 32; i += 8) {
        int n = n0 + i, k = k0 + tx;
        __half h, l; split_hl(t[tx][i], h, l);
        size_t base = (size_t)n * 3 * K;
        out[base + k] = h; out[base + K + k] = h; out[base + 2 * K + k] = l;
    }
}
__global__ void fold_w(const float* __restrict__ in_w, const float* __restrict__ out_w,
                       const float* __restrict__ in_b, const float* __restrict__ out_b)
{
    int j = threadIdx.x;
    if (blockIdx.x < ND) {
        int k = blockIdx.x;
        float s = 0.f;
#pragma unroll 8
        for (int m = 0; m < ND; ++m)
            s = fmaf(in_w[k * 384 + 256 + m], out_w[m * ND + j], s);
        g_Wp[k * ND + j] = s;
    } else {
        float s = out_b[j];
#pragma unroll 8
        for (int m = 0; m < ND; ++m)
            s = fmaf(in_b[256 + m], out_w[m * ND + j], s);
        g_bp[j] = s;
    }
}
__global__ void proto_prep(const float* __restrict__ P, const float* __restrict__ logc)
{
    int row = blockIdx.x, tid = threadIdx.x;
    float p = (row < NC) ? P[(size_t)row * ND + tid] : 0.0f;
    float n2 = block_sum_128(p * p);
    float c, sc; curvature(logc, c, sc);
    float maxn = (1.0f - 1e-5f) / sc;
    float scl = fminf(maxn / fmaxf(sqrtf(n2), 1e-6f), 1.0f);
    p *= scl;
    __half* B1 = (__half*)g_B1e;
    B1[(size_t)row * 128 + tid] = __float2half_rn(p);
    if (tid == 0) {
        float p2 = n2 * scl * scl;
        g_p2[row] = p2;
        g_dp[row] = 1.0f - c * fminf(p2, 1.0f - 1e-5f);
    }
}
__global__ void __launch_bounds__(256) euc_prep(const float* __restrict__ W,
                                                const float* __restrict__ bias)
{
    __shared__ float tile[128 * 65];
    const int tid = threadIdx.x;
    const int c0 = blockIdx.x * 64;
#pragma unroll
    for (int it = 0; it < 32; ++it) {
        int idx = it * 256 + tid;
        int k = idx >> 6, cc = idx & 63;
        int cls = c0 + cc;
        tile[k * 65 + cc] = (cls < NC) ? W[(size_t)k * NC + cls] : 0.0f;
    }
    __syncthreads();
    const int cc = tid & 63, q = tid >> 6;
    __half* B2 = (__half*)g_B2e;
    const size_t base = (size_t)(c0 + cc) * KEUC;
#pragma unroll
    for (int j8 = 0; j8 < 4; ++j8) {
        int k = q * 32 + j8 * 8;
        __half2 hp[4];
#pragma unroll
        for (int e = 0; e < 4; ++e)
            hp[e] = __halves2half2(__float2half_rn(tile[(k + 2 * e) * 65 + cc]),
                                   __float2half_rn(tile[(k + 2 * e + 1) * 65 + cc]));
        uint4 pk;
        pk.x = *(uint32_t*)&hp[0]; pk.y = *(uint32_t*)&hp[1];
        pk.z = *(uint32_t*)&hp[2]; pk.w = *(uint32_t*)&hp[3];
        *(uint4*)(B2 + base + k) = pk;
        *(uint4*)(B2 + base + 128 + k) = pk;
    }
    if (tid < 64) {
        int cls = c0 + tid;
        g_eb[cls] = (cls < NC) ? bias[cls] : 0.0f;
    }
}

// ---------------- tensor GEMM 64x128 tile, fused epilogues ------------------
#define HSTAGE 24576
#define HSMEM  49152

template <int ACT, int EPI, int WF32, int WSP>
__global__ void __launch_bounds__(256, 2) hgemm(
    const __half* __restrict__ A, const __half* __restrict__ Bt,
    const float* __restrict__ bias,
    float* __restrict__ C, __half* __restrict__ Asp, __half* __restrict__ Asp2,
    const float* __restrict__ R, const float* __restrict__ gg,
    const float* __restrict__ bb, const float* __restrict__ logc,
    float* __restrict__ e2o, float* __restrict__ deo,
    int KE, int N)
{
    extern __shared__ char smem[];
    float* smf = (float*)smem;
    const int tid = threadIdx.x, wid = tid >> 5, lane = tid & 31;
    const int m0 = blockIdx.y * 64, n0 = blockIdx.x * 128;
    const uint32_t sbase = smem_u32(smem);
    const int warp_m = wid & 1, warp_n = wid >> 1;
    const int quad = lane >> 3, l8 = lane & 7;
    const int nstage = KE >> 6;

    float acc[2][4][4] = {};

    auto load_stage = [&](int s) {
        const uint32_t sA = sbase + (uint32_t)(s & 1) * HSTAGE;
        const uint32_t sB = sA + 8192;
        const size_t kb = (size_t)s * 128;
#pragma unroll
        for (int j = 0; j < 2; ++j) {
            int idx = tid + 256 * j;
            int row = idx >> 3, ch = idx & 7;
            uint32_t so = row * 128 + ((ch ^ (row & 7)) << 4);
            cp_async16(sA + so, (const char*)A + (size_t)(m0 + row) * (KE * 2) + kb + ch * 16);
        }
#pragma unroll
        for (int j = 0; j < 4; ++j) {
            int idx = tid + 256 * j;
            int row = idx >> 3, ch = idx & 7;
            uint32_t so = row * 128 + ((ch ^ (row & 7)) << 4);
            cp_async16(sB + so, (const char*)Bt + (size_t)(n0 + row) * (KE * 2) + kb + ch * 16);
        }
        asm volatile("cp.async.commit_group;" ::: "memory");
    };

    load_stage(0);
#pragma unroll 1
    for (int s = 0; s < nstage; ++s) {
        if (s + 1 < nstage) {
            load_stage(s + 1);
            asm volatile("cp.async.wait_group 1;" ::: "memory");
        } else {
            asm volatile("cp.async.wait_group 0;" ::: "memory");
        }
        __syncthreads();
        const uint32_t aB = sbase + (uint32_t)(s & 1) * HSTAGE;
        const uint32_t bB = aB + 8192;
#pragma unroll
        for (int ks = 0; ks < 4; ++ks) {
            uint32_t a[2][4];
#pragma unroll
            for (int mf = 0; mf < 2; ++mf) {
                int mr = warp_m * 32 + mf * 16 + (quad & 1) * 8 + l8;
                int kc = ks * 2 + (quad >> 1);
                ldmx4(aB + mr * 128 + ((kc ^ (mr & 7)) << 4),
                      a[mf][0], a[mf][1], a[mf][2], a[mf][3]);
            }
            uint32_t b[2][4];
#pragma unroll
            for (int nh = 0; nh < 2; ++nh) {
                int nr = warp_n * 32 + nh * 16 + (quad >> 1) * 8 + l8;
                int kc = ks * 2 + (quad & 1);
                ldmx4(bB + nr * 128 + ((kc ^ (nr & 7)) << 4),
                      b[nh][0], b[nh][1], b[nh][2], b[nh][3]);
            }
#pragma unroll
            for (int mf = 0; mf < 2; ++mf)
#pragma unroll
                for (int nf = 0; nf < 4; ++nf)
                    mma_fp16(acc[mf][nf], a[mf], b[nf >> 1][(nf & 1) * 2],
                             b[nf >> 1][(nf & 1) * 2 + 1]);
        }
        __syncthreads();
    }

    const int g = lane >> 2, tg = lane & 3;
#pragma unroll
    for (int mf = 0; mf < 2; ++mf)
#pragma unroll
        for (int nf = 0; nf < 4; ++nf) {
            int r0 = warp_m * 32 + mf * 16 + g;
            int col = warp_n * 32 + nf * 8 + tg * 2;
            *(float2*)&smf[r0 * 132 + col]       = make_float2(acc[mf][nf][0], acc[mf][nf][1]);
            *(float2*)&smf[(r0 + 8) * 132 + col] = make_float2(acc[mf][nf][2], acc[mf][nf][3]);
        }
    __syncthreads();

    float4 b4 = *(const float4*)&bias[n0 + lane * 4];
    const float* b4p = &b4.x;

    if (EPI == 0) {
#pragma unroll
        for (int it = 0; it < 8; ++it) {
            int r = wid * 8 + it;
            int grow = m0 + r;
            float4 v = *(const float4*)&smf[r * 132 + lane * 4];
            float* vp = &v.x;
#pragma unroll
            for (int e = 0; e < 4; ++e) {
                float vv = vp[e] + b4p[e];
                if (ACT == 1) vv = gelu_exact(vv);
                vp[e] = vv;
            }
            if (WF32)
                *(float4*)(C + (size_t)grow * N + n0 + lane * 4) = v;
            if (WSP) {
                size_t base = (size_t)grow * 3 * N;
                int cc = n0 + lane * 4;
                __half* hp = Asp + base + cc;
                split4_store(vp, hp, hp + N);
                pack4_store(vp, hp + 2 * N);
            }
        }
    } else {
        float c_ = 0.f, sc_ = 0.f, maxn = 0.f;
        if (EPI == 2) { curvature(logc, c_, sc_); maxn = (1.0f - 1e-5f) / sc_; }
        float4 g4 = *(const float4*)&gg[lane * 4];
        float4 bt4 = *(const float4*)&bb[lane * 4];
        const float* g4p = &g4.x; const float* bt4p = &bt4.x;
#pragma unroll 1
        for (int it = 0; it < 8; ++it) {
            int r = wid * 8 + it;
            int grow = m0 + r;
            float4 v = *(const float4*)&smf[r * 132 + lane * 4];
            float* vp = &v.x;
            float4 rr = *(const float4*)&R[(size_t)grow * ND + lane * 4];
            const float* rrp = &rr.x;
            float x[4];
#pragma unroll
            for (int e = 0; e < 4; ++e) x[e] = vp[e] + b4p[e] + rrp[e];
            float m = warp_sum(x[0] + x[1] + x[2] + x[3]) * (1.0f / 128.0f);
            float q = 0.f;
#pragma unroll
            for (int e = 0; e < 4; ++e) { x[e] -= m; q += x[e] * x[e]; }
            float var = warp_sum(q) * (1.0f / 128.0f);
            float rstd = rsqrtf(var + 1e-5f);
            float y[4];
#pragma unroll
            for (int e = 0; e < 4; ++e) y[e] = x[e] * rstd * g4p[e] + bt4p[e];

            if (EPI == 1) {
                *(float4*)(C + (size_t)grow * ND + lane * 4) = *(float4*)y;
                size_t base = (size_t)grow * 384;
                __half* hp = Asp + base + lane * 4;
                split4_store(y, hp, hp + 128);
                pack4_store(y, hp + 256);
            } else {
                float n2 = warp_sum(y[0]*y[0] + y[1]*y[1] + y[2]*y[2] + y[3]*y[3]);
                float vn = fmaxf(sqrtf(n2), 1e-10f);
                float kk = tanhf(sc_ * vn * 0.5f) / (sc_ * vn);
                float en = kk * vn;
                float scl = fminf(maxn / fmaxf(en, 1e-6f), 1.0f);
                float ke = kk * scl;
                float ee[4];
#pragma unroll
                for (int e = 0; e < 4; ++e) ee[e] = ke * y[e];
                *(float4*)(C + (size_t)grow * ND + lane * 4) = *(float4*)ee;
                // hyp A: plain fp16 emb (1-term)
                pack4_store(ee, Asp + (size_t)grow * 128 + lane * 4);
                // euc A: 2-term split of y
                __half* a2 = Asp2 + (size_t)grow * KEUC + lane * 4;
                split4_store(y, a2, a2 + 128);
                if (lane == 0) {
                    float e2 = en * en * scl * scl;
                    e2o[grow] = e2;
                    deo[grow] = 1.0f - c_ * fminf(e2, 1.0f - 1e-5f);
                }
            }
        }
    }
}

// ---------------- mma.sync dual GEMM + fused epilogue (head) ---------------
// z=0: hyp, K=128 (2 stages, row stride 256B); z=1: euc, K=256 (4 stages, 512B)
#define STAGE_BYTES 32768
#define SMEM_BYTES (128 * 132 * 4)

__global__ void __launch_bounds__(256, 2) dual_mma(
    const float* __restrict__ e2v, const float* __restrict__ dev,
    const float* __restrict__ logc,
    float* __restrict__ hyp, float* __restrict__ euc)
{
    extern __shared__ char smem[];
    float* smf = (float*)smem;
    const int tid = threadIdx.x, wid = tid >> 5, lane = tid & 31;
    const int z = blockIdx.z;
    const int m0 = blockIdx.y * 128, n0 = blockIdx.x * 128;
    const char* Ag = (const char*)(z ? g_A2e : g_A1e);
    const char* Bg = (const char*)(z ? g_B2e : g_B1e);
    const int nst = z ? 4 : 2;           // stages
    const int rstride = z ? 512 : 256;   // row stride in bytes
    const uint32_t sbase = smem_u32(smem);
    const int warp_m = wid & 1, warp_n = wid >> 1;
    const int quad = lane >> 3, l8 = lane & 7;

    float acc[4][4][4] = {};

    auto load_stage = [&](int s) {
        const uint32_t sA = sbase + (uint32_t)(s & 1) * STAGE_BYTES;
        const uint32_t sB = sA + 16384;
        const size_t kb = (size_t)s * 128;
#pragma unroll
        for (int j = 0; j < 4; ++j) {
            int idx = tid + 256 * j;
            int row = idx >> 3, ch = idx & 7;
            uint32_t so = row * 128 + ((ch ^ (row & 7)) << 4);
            cp_async16(sA + so, Ag + (size_t)(m0 + row) * rstride + kb + ch * 16);
            cp_async16(sB + so, Bg + (size_t)(n0 + row) * rstride + kb + ch * 16);
        }
        asm volatile("cp.async.commit_group;" ::: "memory");
    };

    load_stage(0);
#pragma unroll 1
    for (int s = 0; s < nst; ++s) {
        if (s + 1 < nst) {
            load_stage(s + 1);
            asm volatile("cp.async.wait_group 1;" ::: "memory");
        } else {
            asm volatile("cp.async.wait_group 0;" ::: "memory");
        }
        __syncthreads();
        const uint32_t aB = sbase + (uint32_t)(s & 1) * STAGE_BYTES;
        const uint32_t bB = aB + 16384;
#pragma unroll
        for (int ks = 0; ks < 4; ++ks) {
            uint32_t a[4][4];
#pragma unroll
            for (int mf = 0; mf < 4; ++mf) {
                int mr = warp_m * 64 + mf * 16 + (quad & 1) * 8 + l8;
                int kc = ks * 2 + (quad >> 1);
                ldmx4(aB + mr * 128 + ((kc ^ (mr & 7)) << 4),
                      a[mf][0], a[mf][1], a[mf][2], a[mf][3]);
            }
            uint32_t b[2][4];
#pragma unroll
            for (int nh = 0; nh < 2; ++nh) {
                int nr = warp_n * 32 + nh * 16 + (quad >> 1) * 8 + l8;
                int kc = ks * 2 + (quad & 1);
                ldmx4(bB + nr * 128 + ((kc ^ (nr & 7)) << 4),
                      b[nh][0], b[nh][1], b[nh][2], b[nh][3]);
            }
#pragma unroll
            for (int mf = 0; mf < 4; ++mf)
#pragma unroll
                for (int nf = 0; nf < 4; ++nf)
                    mma_fp16(acc[mf][nf], a[mf], b[nf >> 1][(nf & 1) * 2],
                             b[nf >> 1][(nf & 1) * 2 + 1]);
        }
        __syncthreads();
    }

    const int g = lane >> 2, tg = lane & 3;
#pragma unroll
    for (int mf = 0; mf < 4; ++mf)
#pragma unroll
        for (int nf = 0; nf < 4; ++nf) {
            int r0 = warp_m * 64 + mf * 16 + g;
            int col = warp_n * 32 + nf * 8 + tg * 2;
            *(float2*)&smf[r0 * 132 + col]       = make_float2(acc[mf][nf][0], acc[mf][nf][1]);
            *(float2*)&smf[(r0 + 8) * 132 + col] = make_float2(acc[mf][nf][2], acc[mf][nf][3]);
        }
    __syncthreads();

    const int gc = n0 + lane * 4;
    const bool ok = gc < NC;
    float* dst = z ? euc : hyp;

    float inv2sc = 0.f, slg = 0.f;
    float p2c[4], dpc[4], ebc[4];
    if (z == 0) {
        float c_, sc_; curvature(logc, c_, sc_);
        inv2sc = 2.0f / sc_;
        slg = -inv2sc * 0.69314718055994531f;
        float4 p2 = *(const float4*)&g_p2[gc];
        float4 dp = *(const float4*)&g_dp[gc];
        p2c[0]=p2.x; p2c[1]=p2.y; p2c[2]=p2.z; p2c[3]=p2.w;
        dpc[0]=dp.x; dpc[1]=dp.y; dpc[2]=dp.z; dpc[3]=dp.w;
    } else {
        float4 eb = *(const float4*)&g_eb[gc];
        ebc[0]=eb.x; ebc[1]=eb.y; ebc[2]=eb.z; ebc[3]=eb.w;
    }

#pragma unroll 2
    for (int it = 0; it < 16; ++it) {
        int r = wid * 16 + it;
        int grow = m0 + r;
        float4 v = *(const float4*)&smf[r * 132 + lane * 4];
        float* vp = &v.x;
        if (z == 0) {
            float e2r = e2v[grow], der = dev[grow];
#pragma unroll
            for (int e = 0; e < 4; ++e) {
                float diff = fmaxf(e2r + p2c[e] - 2.0f * vp[e], 1e-10f);
                float den  = fmaxf(der * dpc[e], 1e-6f);
                float num  = fmaf(2.0f, diff, den);
                float dist;
                if (diff >= 32.0f * den) {
                    dist = slg * (__log2f(num) - __log2f(den) + 1.0f);
                } else {
                    float arg = fmaxf(__fdividef(num, den), 1.0f + 1e-6f);
                    dist = -inv2sc * acoshf(arg);
                }
                vp[e] = dist;
            }
        } else {
            vp[0] += ebc[0]; vp[1] += ebc[1]; vp[2] += ebc[2]; vp[3] += ebc[3];
        }
        if (ok) __stcs((float4*)(dst + (size_t)grow * NC + gc), v);
    }
}

// ------------------------------- launch -------------------------------------
extern "C" void kernel_launch(void* const* d_in, const int* in_sizes, int n_in,
                              void* d_out, int out_size)
{
    const float* x      = (const float*)d_in[0];
    const float* W1     = (const float*)d_in[1];
    const float* b1     = (const float*)d_in[2];
    const float* W2     = (const float*)d_in[3];
    const float* b2     = (const float*)d_in[4];
    const float* in_w   = (const float*)d_in[5];
    const float* in_b   = (const float*)d_in[6];
    const float* out_w  = (const float*)d_in[7];
    const float* out_b  = (const float*)d_in[8];
    const float* fw1    = (const float*)d_in[9];
    const float* fb1    = (const float*)d_in[10];
    const float* fw2    = (const float*)d_in[11];
    const float* fb2    = (const float*)d_in[12];
    const float* g1     = (const float*)d_in[13];
    const float* bt1    = (const float*)d_in[14];
    const float* g2     = (const float*)d_in[15];
    const float* bt2    = (const float*)d_in[16];
    const float* logc   = (const float*)d_in[17];
    const float* protos = (const float*)d_in[18];
    const float* euc_w  = (const float*)d_in[19];
    const float* euc_b  = (const float*)d_in[20];

    float *t, *xs, *e2, *de, *Wp, *bp;
    __half *xsp, *t1sp, *tsp, *xssp, *hsp, *W1p, *W2p, *fw1p, *fw2p, *Wpp, *A1, *A2;
    cudaGetSymbolAddress((void**)&t,    g_t);
    cudaGetSymbolAddress((void**)&xs,   g_xs);
    cudaGetSymbolAddress((void**)&e2,   g_e2);
    cudaGetSymbolAddress((void**)&de,   g_de);
    cudaGetSymbolAddress((void**)&Wp,   g_Wp);
    cudaGetSymbolAddress((void**)&bp,   g_bp);
    cudaGetSymbolAddress((void**)&xsp,  g_xsp);
    cudaGetSymbolAddress((void**)&t1sp, g_t1sp);
    cudaGetSymbolAddress((void**)&tsp,  g_tsp);
    cudaGetSymbolAddress((void**)&xssp, g_xssp);
    cudaGetSymbolAddress((void**)&hsp,  g_hsp);
    cudaGetSymbolAddress((void**)&W1p,  g_W1p);
    cudaGetSymbolAddress((void**)&W2p,  g_W2p);
    cudaGetSymbolAddress((void**)&fw1p, g_fw1p);
    cudaGetSymbolAddress((void**)&fw2p, g_fw2p);
    cudaGetSymbolAddress((void**)&Wpp,  g_Wpp);
    cudaGetSymbolAddress((void**)&A1,   g_A1e);
    cudaGetSymbolAddress((void**)&A2,   g_A2e);

    float* out = (float*)d_out;
    float* hyp = out;
    float* euc = out + (size_t)NB * NC;
    float* emb = out + (size_t)NB * NC * 2;

    static cudaStream_t s2 = nullptr;
    static cudaEvent_t evF = nullptr, evW1 = nullptr, evW = nullptr, evJ = nullptr;
    if (!s2) {
        cudaStreamCreateWithFlags(&s2, cudaStreamNonBlocking);
        cudaEventCreateWithFlags(&evF, cudaEventDisableTiming);
        cudaEventCreateWithFlags(&evW1, cudaEventDisableTiming);
        cudaEventCreateWithFlags(&evW, cudaEventDisableTiming);
        cudaEventCreateWithFlags(&evJ, cudaEventDisableTiming);
        cudaFuncSetAttribute(dual_mma, cudaFuncAttributeMaxDynamicSharedMemorySize, SMEM_BYTES);
        cudaFuncSetAttribute(hgemm<1,0,0,1>, cudaFuncAttributeMaxDynamicSharedMemorySize, HSMEM);
        cudaFuncSetAttribute(hgemm<0,0,1,1>, cudaFuncAttributeMaxDynamicSharedMemorySize, HSMEM);
        cudaFuncSetAttribute(hgemm<0,1,0,0>, cudaFuncAttributeMaxDynamicSharedMemorySize, HSMEM);
        cudaFuncSetAttribute(hgemm<0,2,0,0>, cudaFuncAttributeMaxDynamicSharedMemorySize, HSMEM);
    }

    // ---- fork: side stream does all weight/proto preps ----
    cudaEventRecord(evF, 0);
    cudaStreamWaitEvent(s2, evF, 0);
    wprep<<<dim3(NIN / 32, 256 / 32), 256, 0, s2>>>(W1, W1p, NIN, 256);
    cudaEventRecord(evW1, s2);
    wprep<<<dim3(256 / 32, 128 / 32), 256, 0, s2>>>(W2, W2p, 256, 128);
    wprep<<<dim3(128 / 32, 512 / 32), 256, 0, s2>>>(fw1, fw1p, 128, 512);
    wprep<<<dim3(512 / 32, 128 / 32), 256, 0, s2>>>(fw2, fw2p, 512, 128);
    fold_w<<<ND + 1, 128, 0, s2>>>(in_w, out_w, in_b, out_b);
    wprep<<<dim3(128 / 32, 128 / 32), 256, 0, s2>>>(Wp, Wpp, 128, 128);
    cudaEventRecord(evW, s2);
    proto_prep<<<NC2, 128, 0, s2>>>(protos, logc);
    euc_prep <<<NC2 / 64, 256, 0, s2>>>(euc_w, euc_b);
    cudaEventRecord(evJ, s2);

    // ---- main stream: activation split + front-end chain ----
    asplit<<<NB, 256>>>(x, xsp, NIN);
    cudaStreamWaitEvent(0, evW1, 0);
    hgemm<1,0,0,1><<<dim3(2, NB / 64), 256, HSMEM>>>(
        xsp, W1p, b1, nullptr, t1sp, nullptr, nullptr, nullptr, nullptr, nullptr,
        nullptr, nullptr, 3072, 256);
    cudaStreamWaitEvent(0, evW, 0);
    hgemm<0,0,1,1><<<dim3(1, NB / 64), 256, HSMEM>>>(
        t1sp, W2p, b2, t, tsp, nullptr, nullptr, nullptr, nullptr, nullptr,
        nullptr, nullptr, 768, 128);
    hgemm<0,1,0,0><<<dim3(1, NB / 64), 256, HSMEM>>>(
        tsp, Wpp, bp, xs, xssp, nullptr, t, g1, bt1, nullptr,
        nullptr, nullptr, 384, 128);
    hgemm<1,0,0,1><<<dim3(4, NB / 64), 256, HSMEM>>>(
        xssp, fw1p, fb1, nullptr, hsp, nullptr, nullptr, nullptr, nullptr, nullptr,
        nullptr, nullptr, 384, 512);
    hgemm<0,2,0,0><<<dim3(1, NB / 64), 256, HSMEM>>>(
        hsp, fw2p, fb2, emb, A1, A2, xs, g2, bt2, logc,
        e2, de, 1536, 128);

    // ---- join, then head ----
    cudaStreamWaitEvent(0, evJ, 0);
    dual_mma<<<dim3(NC2 / 128, NB / 128, 2), 256, SMEM_BYTES>>>(e2, de, logc, hyp, euc);
}

// round 9
// speedup vs baseline: 3.5507x; 1.1019x over previous
#include <cuda_runtime.h>
#include <cuda_fp16.h>
#include <math.h>
#include <stdint.h>

// ---------------------------------------------------------------------------
// B=4096, IN_DIM=1024, D=128, C=10000. seq_len==1 -> attn == v (q,k dead),
// v/out_w fold into one GEMM. Whole net on mma.sync fp16:
//   front-end: 3-term hi/lo split (fp32-quality)
//   head: BOTH planes 1-term fp16, K=128. emb = ke*y (row scalar) so the two
//   GEMMs share A = y(fp16); ke folds into the hyp epilogue in fp32.
// LN1 / LN2+hyperbolic-embedding fused into GEMM epilogues.
// Head epilogue: MUFU lg2-based acosh. Preps overlap on a second stream.
// ---------------------------------------------------------------------------

#define NB   4096
#define NIN  1024
#define ND   128
#define NC   10000
#define NC2  10112

// ------------------------- device scratch (no allocs) ----------------------
__device__ float g_t [NB * ND];
__device__ float g_xs[NB * ND];
__device__ float g_e2[NB];
__device__ float g_de[NB];
__device__ float g_ke[NB];
__device__ float g_Wp[ND * ND];
__device__ float g_bp[ND];
__device__ uint4 g_xsp [NB * 3072 / 8];
__device__ uint4 g_t1sp[NB * 768  / 8];
__device__ uint4 g_tsp [NB * 384  / 8];
__device__ uint4 g_xssp[NB * 384  / 8];
__device__ uint4 g_hsp [NB * 1536 / 8];
__device__ uint4 g_W1p [256 * 3072 / 8];
__device__ uint4 g_W2p [128 * 768  / 8];
__device__ uint4 g_fw1p[512 * 384  / 8];
__device__ uint4 g_fw2p[128 * 1536 / 8];
__device__ uint4 g_Wpp [128 * 384  / 8];
__device__ uint4 g_Ay [NB  * 128 / 8];    // y fp16 (shared head A)
__device__ uint4 g_B1e[NC2 * 128 / 8];    // protos fp16
__device__ uint4 g_B2e[NC2 * 128 / 8];    // euc_w^T fp16
__device__ float g_p2[NC2];
__device__ float g_dp[NC2];
__device__ float g_eb[NC2];

// ------------------------------ helpers ------------------------------------
static __device__ __forceinline__ uint32_t smem_u32(const void* p) {
    uint32_t a;
    asm("{ .reg .u64 t; cvta.to.shared.u64 t, %1; cvt.u32.u64 %0, t; }" : "=r"(a) : "l"(p));
    return a;
}
static __device__ __forceinline__ void cp_async16(uint32_t s, const void* g) {
    asm volatile("cp.async.cg.shared.global [%0], [%1], 16;" :: "r"(s), "l"(g) : "memory");
}
static __device__ __forceinline__ void ldmx4(uint32_t a, uint32_t& r0, uint32_t& r1,
                                             uint32_t& r2, uint32_t& r3) {
    asm volatile("ldmatrix.sync.aligned.m8n8.x4.shared.b16 {%0,%1,%2,%3}, [%4];"
                 : "=r"(r0), "=r"(r1), "=r"(r2), "=r"(r3) : "r"(a));
}
static __device__ __forceinline__ void mma_fp16(float* d, const uint32_t* a,
                                                uint32_t b0, uint32_t b1) {
    asm volatile("mma.sync.aligned.m16n8k16.row.col.f32.f16.f16.f32 "
                 "{%0,%1,%2,%3}, {%4,%5,%6,%7}, {%8,%9}, {%0,%1,%2,%3};"
                 : "+f"(d[0]), "+f"(d[1]), "+f"(d[2]), "+f"(d[3])
                 : "r"(a[0]), "r"(a[1]), "r"(a[2]), "r"(a[3]), "r"(b0), "r"(b1));
}
static __device__ __forceinline__ float gelu_exact(float x) {
    return 0.5f * x * (1.0f + erff(x * 0.70710678118654752440f));
}
static __device__ __forceinline__ float warp_sum(float v) {
#pragma unroll
    for (int o = 16; o > 0; o >>= 1) v += __shfl_xor_sync(0xffffffffu, v, o);
    return v;
}
static __device__ __forceinline__ float block_sum_128(float v) {
    __shared__ float sh[4];
    int lane = threadIdx.x & 31, wid = threadIdx.x >> 5;
    v = warp_sum(v);
    __syncthreads();
    if (lane == 0) sh[wid] = v;
    __syncthreads();
    return sh[0] + sh[1] + sh[2] + sh[3];
}
static __device__ __forceinline__ void curvature(const float* logc, float& c, float& sc) {
    float cc = expf(logc[0]);
    cc = fminf(fmaxf(cc, 1e-4f), 10.0f);
    cc = fmaxf(fabsf(cc), 1e-6f);
    c = cc; sc = sqrtf(cc);
}
static __device__ __forceinline__ void split_hl(float x, __half& h, __half& l) {
    h = __float2half_rn(x);
    l = __float2half_rn(x - __half2float(h));
}
static __device__ __forceinline__ void split4_store(const float* v, __half* hip, __half* lop) {
    __half h[4], l[4];
#pragma unroll
    for (int e = 0; e < 4; ++e) split_hl(v[e], h[e], l[e]);
    __half2 h01 = __halves2half2(h[0], h[1]), h23 = __halves2half2(h[2], h[3]);
    __half2 l01 = __halves2half2(l[0], l[1]), l23 = __halves2half2(l[2], l[3]);
    uint2 ph, pl;
    ph.x = *(uint32_t*)&h01; ph.y = *(uint32_t*)&h23;
    pl.x = *(uint32_t*)&l01; pl.y = *(uint32_t*)&l23;
    *(uint2*)hip = ph;
    *(uint2*)lop = pl;
}
static __device__ __forceinline__ void pack4_store(const float* v, __half* hip) {
    __half h[4];
#pragma unroll
    for (int e = 0; e < 4; ++e) h[e] = __float2half_rn(v[e]);
    __half2 h01 = __halves2half2(h[0], h[1]), h23 = __halves2half2(h[2], h[3]);
    uint2 ph; ph.x = *(uint32_t*)&h01; ph.y = *(uint32_t*)&h23;
    *(uint2*)hip = ph;
}

// ------------------- preps -------------------------------------------------
__global__ void asplit(const float* __restrict__ X, __half* __restrict__ out, int K)
{
    int row = blockIdx.x;
    const float4* xr = (const float4*)(X + (size_t)row * K);
    __half* o = out + (size_t)row * 3 * K;
    for (int k4 = threadIdx.x; k4 < (K >> 2); k4 += 256) {
        float4 v = xr[k4];
        float* vp = &v.x;
        int k = k4 * 4;
        __half h[4], l[4];
#pragma unroll
        for (int e = 0; e < 4; ++e) split_hl(vp[e], h[e], l[e]);
        __half2 h01 = __halves2half2(h[0], h[1]), h23 = __halves2half2(h[2], h[3]);
        __half2 l01 = __halves2half2(l[0], l[1]), l23 = __halves2half2(l[2], l[3]);
        uint2 ph, pl;
        ph.x = *(uint32_t*)&h01; ph.y = *(uint32_t*)&h23;
        pl.x = *(uint32_t*)&l01; pl.y = *(uint32_t*)&l23;
        *(uint2*)(o + k) = ph;
        *(uint2*)(o + K + k) = pl;
        *(uint2*)(o + 2 * K + k) = ph;
    }
}
__global__ void __launch_bounds__(256) wprep(const float* __restrict__ W,
                                             __half* __restrict__ out, int K, int N)
{
    __shared__ float t[32][33];
    const int k0 = blockIdx.x * 32, n0 = blockIdx.y * 32;
    const int tx = threadIdx.x & 31, ty = threadIdx.x >> 5;
#pragma unroll
    for (int i = ty; i < 32; i += 8)
        t[i][tx] = W[(size_t)(k0 + i) * N + n0 + tx];
    __syncthreads();
#pragma unroll
    for (int i = ty; i < 32; i += 8) {
        int n = n0 + i, k = k0 + tx;
        __half h, l; split_hl(t[tx][i], h, l);
        size_t base = (size_t)n * 3 * K;
        out[base + k] = h; out[base + K + k] = h; out[base + 2 * K + k] = l;
    }
}
__global__ void fold_w(const float* __restrict__ in_w, const float* __restrict__ out_w,
                       const float* __restrict__ in_b, const float* __restrict__ out_b)
{
    int j = threadIdx.x;
    if (blockIdx.x < ND) {
        int k = blockIdx.x;
        float s = 0.f;
#pragma unroll 8
        for (int m = 0; m < ND; ++m)
            s = fmaf(in_w[k * 384 + 256 + m], out_w[m * ND + j], s);
        g_Wp[k * ND + j] = s;
    } else {
        float s = out_b[j];
#pragma unroll 8
        for (int m = 0; m < ND; ++m)
            s = fmaf(in_b[256 + m], out_w[m * ND + j], s);
        g_bp[j] = s;
    }
}
__global__ void proto_prep(const float* __restrict__ P, const float* __restrict__ logc)
{
    int row = blockIdx.x, tid = threadIdx.x;
    float p = (row < NC) ? P[(size_t)row * ND + tid] : 0.0f;
    float n2 = block_sum_128(p * p);
    float c, sc; curvature(logc, c, sc);
    float maxn = (1.0f - 1e-5f) / sc;
    float scl = fminf(maxn / fmaxf(sqrtf(n2), 1e-6f), 1.0f);
    p *= scl;
    __half* B1 = (__half*)g_B1e;
    B1[(size_t)row * 128 + tid] = __float2half_rn(p);
    if (tid == 0) {
        float p2 = n2 * scl * scl;
        g_p2[row] = p2;
        g_dp[row] = 1.0f - c * fminf(p2, 1.0f - 1e-5f);
    }
}
__global__ void __launch_bounds__(256) euc_prep(const float* __restrict__ W,
                                                const float* __restrict__ bias)
{
    __shared__ float tile[128 * 65];
    const int tid = threadIdx.x;
    const int c0 = blockIdx.x * 64;
#pragma unroll
    for (int it = 0; it < 32; ++it) {
        int idx = it * 256 + tid;
        int k = idx >> 6, cc = idx & 63;
        int cls = c0 + cc;
        tile[k * 65 + cc] = (cls < NC) ? W[(size_t)k * NC + cls] : 0.0f;
    }
    __syncthreads();
    const int cc = tid & 63, q = tid >> 6;
    __half* B2 = (__half*)g_B2e;
    const size_t base = (size_t)(c0 + cc) * 128;
#pragma unroll
    for (int j8 = 0; j8 < 4; ++j8) {
        int k = q * 32 + j8 * 8;
        __half2 hp[4];
#pragma unroll
        for (int e = 0; e < 4; ++e)
            hp[e] = __halves2half2(__float2half_rn(tile[(k + 2 * e) * 65 + cc]),
                                   __float2half_rn(tile[(k + 2 * e + 1) * 65 + cc]));
        uint4 pk;
        pk.x = *(uint32_t*)&hp[0]; pk.y = *(uint32_t*)&hp[1];
        pk.z = *(uint32_t*)&hp[2]; pk.w = *(uint32_t*)&hp[3];
        *(uint4*)(B2 + base + k) = pk;
    }
    if (tid < 64) {
        int cls = c0 + tid;
        g_eb[cls] = (cls < NC) ? bias[cls] : 0.0f;
    }
}

// ---------------- tensor GEMM 64x128 tile, fused epilogues ------------------
#define HSTAGE 24576
#define HSMEM  49152

template <int ACT, int EPI, int WF32, int WSP>
__global__ void __launch_bounds__(256, 2) hgemm(
    const __half* __restrict__ A, const __half* __restrict__ Bt,
    const float* __restrict__ bias,
    float* __restrict__ C, __half* __restrict__ Asp,
    const float* __restrict__ R, const float* __restrict__ gg,
    const float* __restrict__ bb, const float* __restrict__ logc,
    float* __restrict__ e2o, float* __restrict__ deo, float* __restrict__ keo,
    int KE, int N)
{
    extern __shared__ char smem[];
    float* smf = (float*)smem;
    const int tid = threadIdx.x, wid = tid >> 5, lane = tid & 31;
    const int m0 = blockIdx.y * 64, n0 = blockIdx.x * 128;
    const uint32_t sbase = smem_u32(smem);
    const int warp_m = wid & 1, warp_n = wid >> 1;
    const int quad = lane >> 3, l8 = lane & 7;
    const int nstage = KE >> 6;

    float acc[2][4][4] = {};

    auto load_stage = [&](int s) {
        const uint32_t sA = sbase + (uint32_t)(s & 1) * HSTAGE;
        const uint32_t sB = sA + 8192;
        const size_t kb = (size_t)s * 128;
#pragma unroll
        for (int j = 0; j < 2; ++j) {
            int idx = tid + 256 * j;
            int row = idx >> 3, ch = idx & 7;
            uint32_t so = row * 128 + ((ch ^ (row & 7)) << 4);
            cp_async16(sA + so, (const char*)A + (size_t)(m0 + row) * (KE * 2) + kb + ch * 16);
        }
#pragma unroll
        for (int j = 0; j < 4; ++j) {
            int idx = tid + 256 * j;
            int row = idx >> 3, ch = idx & 7;
            uint32_t so = row * 128 + ((ch ^ (row & 7)) << 4);
            cp_async16(sB + so, (const char*)Bt + (size_t)(n0 + row) * (KE * 2) + kb + ch * 16);
        }
        asm volatile("cp.async.commit_group;" ::: "memory");
    };

    load_stage(0);
#pragma unroll 1
    for (int s = 0; s < nstage; ++s) {
        if (s + 1 < nstage) {
            load_stage(s + 1);
            asm volatile("cp.async.wait_group 1;" ::: "memory");
        } else {
            asm volatile("cp.async.wait_group 0;" ::: "memory");
        }
        __syncthreads();
        const uint32_t aB = sbase + (uint32_t)(s & 1) * HSTAGE;
        const uint32_t bB = aB + 8192;
#pragma unroll
        for (int ks = 0; ks < 4; ++ks) {
            uint32_t a[2][4];
#pragma unroll
            for (int mf = 0; mf < 2; ++mf) {
                int mr = warp_m * 32 + mf * 16 + (quad & 1) * 8 + l8;
                int kc = ks * 2 + (quad >> 1);
                ldmx4(aB + mr * 128 + ((kc ^ (mr & 7)) << 4),
                      a[mf][0], a[mf][1], a[mf][2], a[mf][3]);
            }
            uint32_t b[2][4];
#pragma unroll
            for (int nh = 0; nh < 2; ++nh) {
                int nr = warp_n * 32 + nh * 16 + (quad >> 1) * 8 + l8;
                int kc = ks * 2 + (quad & 1);
                ldmx4(bB + nr * 128 + ((kc ^ (nr & 7)) << 4),
                      b[nh][0], b[nh][1], b[nh][2], b[nh][3]);
            }
#pragma unroll
            for (int mf = 0; mf < 2; ++mf)
#pragma unroll
                for (int nf = 0; nf < 4; ++nf)
                    mma_fp16(acc[mf][nf], a[mf], b[nf >> 1][(nf & 1) * 2],
                             b[nf >> 1][(nf & 1) * 2 + 1]);
        }
        __syncthreads();
    }

    const int g = lane >> 2, tg = lane & 3;
#pragma unroll
    for (int mf = 0; mf < 2; ++mf)
#pragma unroll
        for (int nf = 0; nf < 4; ++nf) {
            int r0 = warp_m * 32 + mf * 16 + g;
            int col = warp_n * 32 + nf * 8 + tg * 2;
            *(float2*)&smf[r0 * 132 + col]       = make_float2(acc[mf][nf][0], acc[mf][nf][1]);
            *(float2*)&smf[(r0 + 8) * 132 + col] = make_float2(acc[mf][nf][2], acc[mf][nf][3]);
        }
    __syncthreads();

    float4 b4 = *(const float4*)&bias[n0 + lane * 4];
    const float* b4p = &b4.x;

    if (EPI == 0) {
#pragma unroll
        for (int it = 0; it < 8; ++it) {
            int r = wid * 8 + it;
            int grow = m0 + r;
            float4 v = *(const float4*)&smf[r * 132 + lane * 4];
            float* vp = &v.x;
#pragma unroll
            for (int e = 0; e < 4; ++e) {
                float vv = vp[e] + b4p[e];
                if (ACT == 1) vv = gelu_exact(vv);
                vp[e] = vv;
            }
            if (WF32)
                *(float4*)(C + (size_t)grow * N + n0 + lane * 4) = v;
            if (WSP) {
                size_t base = (size_t)grow * 3 * N;
                int cc = n0 + lane * 4;
                __half* hp = Asp + base + cc;
                split4_store(vp, hp, hp + N);
                pack4_store(vp, hp + 2 * N);
            }
        }
    } else {
        float c_ = 0.f, sc_ = 0.f, maxn = 0.f;
        if (EPI == 2) { curvature(logc, c_, sc_); maxn = (1.0f - 1e-5f) / sc_; }
        float4 g4 = *(const float4*)&gg[lane * 4];
        float4 bt4 = *(const float4*)&bb[lane * 4];
        const float* g4p = &g4.x; const float* bt4p = &bt4.x;
#pragma unroll 1
        for (int it = 0; it < 8; ++it) {
            int r = wid * 8 + it;
            int grow = m0 + r;
            float4 v = *(const float4*)&smf[r * 132 + lane * 4];
            float* vp = &v.x;
            float4 rr = *(const float4*)&R[(size_t)grow * ND + lane * 4];
            const float* rrp = &rr.x;
            float x[4];
#pragma unroll
            for (int e = 0; e < 4; ++e) x[e] = vp[e] + b4p[e] + rrp[e];
            float m = warp_sum(x[0] + x[1] + x[2] + x[3]) * (1.0f / 128.0f);
            float q = 0.f;
#pragma unroll
            for (int e = 0; e < 4; ++e) { x[e] -= m; q += x[e] * x[e]; }
            float var = warp_sum(q) * (1.0f / 128.0f);
            float rstd = rsqrtf(var + 1e-5f);
            float y[4];
#pragma unroll
            for (int e = 0; e < 4; ++e) y[e] = x[e] * rstd * g4p[e] + bt4p[e];

            if (EPI == 1) {
                *(float4*)(C + (size_t)grow * ND + lane * 4) = *(float4*)y;
                size_t base = (size_t)grow * 384;
                __half* hp = Asp + base + lane * 4;
                split4_store(y, hp, hp + 128);
                pack4_store(y, hp + 256);
            } else {
                float n2 = warp_sum(y[0]*y[0] + y[1]*y[1] + y[2]*y[2] + y[3]*y[3]);
                float vn = fmaxf(sqrtf(n2), 1e-10f);
                float kk = tanhf(sc_ * vn * 0.5f) / (sc_ * vn);
                float en = kk * vn;
                float scl = fminf(maxn / fmaxf(en, 1e-6f), 1.0f);
                float ke = kk * scl;
                float ee[4];
#pragma unroll
                for (int e = 0; e < 4; ++e) ee[e] = ke * y[e];
                *(float4*)(C + (size_t)grow * ND + lane * 4) = *(float4*)ee;
                // shared head A: y in fp16 (ke folds into hyp epilogue)
                pack4_store(y, Asp + (size_t)grow * 128 + lane * 4);
                if (lane == 0) {
                    float e2 = en * en * scl * scl;
                    e2o[grow] = e2;
                    deo[grow] = 1.0f - c_ * fminf(e2, 1.0f - 1e-5f);
                    keo[grow] = ke;
                }
            }
        }
    }
}

// ---------------- mma.sync dual GEMM + fused epilogue (head) ---------------
// Both planes K=128 (2 stages, row stride 256B). A = y fp16 shared.
// z=0: hyp (B=protos, dot scaled by ke in epilogue); z=1: euc (B=eucw^T).
#define STAGE_BYTES 32768
#define SMEM_BYTES (128 * 132 * 4)

__global__ void __launch_bounds__(256, 2) dual_mma(
    const float* __restrict__ e2v, const float* __restrict__ dev,
    const float* __restrict__ kev, const float* __restrict__ logc,
    float* __restrict__ hyp, float* __restrict__ euc)
{
    extern __shared__ char smem[];
    float* smf = (float*)smem;
    const int tid = threadIdx.x, wid = tid >> 5, lane = tid & 31;
    const int z = blockIdx.z;
    const int m0 = blockIdx.y * 128, n0 = blockIdx.x * 128;
    const char* Ag = (const char*)g_Ay;
    const char* Bg = (const char*)(z ? g_B2e : g_B1e);
    const uint32_t sbase = smem_u32(smem);
    const int warp_m = wid & 1, warp_n = wid >> 1;
    const int quad = lane >> 3, l8 = lane & 7;

    float acc[4][4][4] = {};

    auto load_stage = [&](int s) {
        const uint32_t sA = sbase + (uint32_t)(s & 1) * STAGE_BYTES;
        const uint32_t sB = sA + 16384;
        const size_t kb = (size_t)s * 128;
#pragma unroll
        for (int j = 0; j < 4; ++j) {
            int idx = tid + 256 * j;
            int row = idx >> 3, ch = idx & 7;
            uint32_t so = row * 128 + ((ch ^ (row & 7)) << 4);
            cp_async16(sA + so, Ag + (size_t)(m0 + row) * 256 + kb + ch * 16);
            cp_async16(sB + so, Bg + (size_t)(n0 + row) * 256 + kb + ch * 16);
        }
        asm volatile("cp.async.commit_group;" ::: "memory");
    };

    load_stage(0);
#pragma unroll 1
    for (int s = 0; s < 2; ++s) {
        if (s == 0) {
            load_stage(1);
            asm volatile("cp.async.wait_group 1;" ::: "memory");
        } else {
            asm volatile("cp.async.wait_group 0;" ::: "memory");
        }
        __syncthreads();
        const uint32_t aB = sbase + (uint32_t)(s & 1) * STAGE_BYTES;
        const uint32_t bB = aB + 16384;
#pragma unroll
        for (int ks = 0; ks < 4; ++ks) {
            uint32_t a[4][4];
#pragma unroll
            for (int mf = 0; mf < 4; ++mf) {
                int mr = warp_m * 64 + mf * 16 + (quad & 1) * 8 + l8;
                int kc = ks * 2 + (quad >> 1);
                ldmx4(aB + mr * 128 + ((kc ^ (mr & 7)) << 4),
                      a[mf][0], a[mf][1], a[mf][2], a[mf][3]);
            }
            uint32_t b[2][4];
#pragma unroll
            for (int nh = 0; nh < 2; ++nh) {
                int nr = warp_n * 32 + nh * 16 + (quad >> 1) * 8 + l8;
                int kc = ks * 2 + (quad & 1);
                ldmx4(bB + nr * 128 + ((kc ^ (nr & 7)) << 4),
                      b[nh][0], b[nh][1], b[nh][2], b[nh][3]);
            }
#pragma unroll
            for (int mf = 0; mf < 4; ++mf)
#pragma unroll
                for (int nf = 0; nf < 4; ++nf)
                    mma_fp16(acc[mf][nf], a[mf], b[nf >> 1][(nf & 1) * 2],
                             b[nf >> 1][(nf & 1) * 2 + 1]);
        }
        __syncthreads();
    }

    const int g = lane >> 2, tg = lane & 3;
#pragma unroll
    for (int mf = 0; mf < 4; ++mf)
#pragma unroll
        for (int nf = 0; nf < 4; ++nf) {
            int r0 = warp_m * 64 + mf * 16 + g;
            int col = warp_n * 32 + nf * 8 + tg * 2;
            *(float2*)&smf[r0 * 132 + col]       = make_float2(acc[mf][nf][0], acc[mf][nf][1]);
            *(float2*)&smf[(r0 + 8) * 132 + col] = make_float2(acc[mf][nf][2], acc[mf][nf][3]);
        }
    __syncthreads();

    const int gc = n0 + lane * 4;
    const bool ok = gc < NC;
    float* dst = z ? euc : hyp;

    float inv2sc = 0.f, slg = 0.f;
    float p2c[4], dpc[4], ebc[4];
    if (z == 0) {
        float c_, sc_; curvature(logc, c_, sc_);
        inv2sc = 2.0f / sc_;
        slg = -inv2sc * 0.69314718055994531f;
        float4 p2 = *(const float4*)&g_p2[gc];
        float4 dp = *(const float4*)&g_dp[gc];
        p2c[0]=p2.x; p2c[1]=p2.y; p2c[2]=p2.z; p2c[3]=p2.w;
        dpc[0]=dp.x; dpc[1]=dp.y; dpc[2]=dp.z; dpc[3]=dp.w;
    } else {
        float4 eb = *(const float4*)&g_eb[gc];
        ebc[0]=eb.x; ebc[1]=eb.y; ebc[2]=eb.z; ebc[3]=eb.w;
    }

#pragma unroll 2
    for (int it = 0; it < 16; ++it) {
        int r = wid * 16 + it;
        int grow = m0 + r;
        float4 v = *(const float4*)&smf[r * 132 + lane * 4];
        float* vp = &v.x;
        if (z == 0) {
            float e2r = e2v[grow], der = dev[grow];
            float m2ke = -2.0f * kev[grow];
#pragma unroll
            for (int e = 0; e < 4; ++e) {
                float diff = fmaxf(fmaf(m2ke, vp[e], e2r + p2c[e]), 1e-10f);
                float den  = fmaxf(der * dpc[e], 1e-6f);
                float num  = fmaf(2.0f, diff, den);
                float dist;
                if (diff >= 32.0f * den) {
                    dist = slg * (__log2f(num) - __log2f(den) + 1.0f);
                } else {
                    float arg = fmaxf(__fdividef(num, den), 1.0f + 1e-6f);
                    dist = -inv2sc * acoshf(arg);
                }
                vp[e] = dist;
            }
        } else {
            vp[0] += ebc[0]; vp[1] += ebc[1]; vp[2] += ebc[2]; vp[3] += ebc[3];
        }
        if (ok) __stcs((float4*)(dst + (size_t)grow * NC + gc), v);
    }
}

// ------------------------------- launch -------------------------------------
extern "C" void kernel_launch(void* const* d_in, const int* in_sizes, int n_in,
                              void* d_out, int out_size)
{
    const float* x      = (const float*)d_in[0];
    const float* W1     = (const float*)d_in[1];
    const float* b1     = (const float*)d_in[2];
    const float* W2     = (const float*)d_in[3];
    const float* b2     = (const float*)d_in[4];
    const float* in_w   = (const float*)d_in[5];
    const float* in_b   = (const float*)d_in[6];
    const float* out_w  = (const float*)d_in[7];
    const float* out_b  = (const float*)d_in[8];
    const float* fw1    = (const float*)d_in[9];
    const float* fb1    = (const float*)d_in[10];
    const float* fw2    = (const float*)d_in[11];
    const float* fb2    = (const float*)d_in[12];
    const float* g1     = (const float*)d_in[13];
    const float* bt1    = (const float*)d_in[14];
    const float* g2     = (const float*)d_in[15];
    const float* bt2    = (const float*)d_in[16];
    const float* logc   = (const float*)d_in[17];
    const float* protos = (const float*)d_in[18];
    const float* euc_w  = (const float*)d_in[19];
    const float* euc_b  = (const float*)d_in[20];

    float *t, *xs, *e2, *de, *ke, *Wp, *bp;
    __half *xsp, *t1sp, *tsp, *xssp, *hsp, *W1p, *W2p, *fw1p, *fw2p, *Wpp, *Ay;
    cudaGetSymbolAddress((void**)&t,    g_t);
    cudaGetSymbolAddress((void**)&xs,   g_xs);
    cudaGetSymbolAddress((void**)&e2,   g_e2);
    cudaGetSymbolAddress((void**)&de,   g_de);
    cudaGetSymbolAddress((void**)&ke,   g_ke);
    cudaGetSymbolAddress((void**)&Wp,   g_Wp);
    cudaGetSymbolAddress((void**)&bp,   g_bp);
    cudaGetSymbolAddress((void**)&xsp,  g_xsp);
    cudaGetSymbolAddress((void**)&t1sp, g_t1sp);
    cudaGetSymbolAddress((void**)&tsp,  g_tsp);
    cudaGetSymbolAddress((void**)&xssp, g_xssp);
    cudaGetSymbolAddress((void**)&hsp,  g_hsp);
    cudaGetSymbolAddress((void**)&W1p,  g_W1p);
    cudaGetSymbolAddress((void**)&W2p,  g_W2p);
    cudaGetSymbolAddress((void**)&fw1p, g_fw1p);
    cudaGetSymbolAddress((void**)&fw2p, g_fw2p);
    cudaGetSymbolAddress((void**)&Wpp,  g_Wpp);
    cudaGetSymbolAddress((void**)&Ay,   g_Ay);

    float* out = (float*)d_out;
    float* hyp = out;
    float* euc = out + (size_t)NB * NC;
    float* emb = out + (size_t)NB * NC * 2;

    static cudaStream_t s2 = nullptr;
    static cudaEvent_t evF = nullptr, evW1 = nullptr, evW = nullptr, evJ = nullptr;
    if (!s2) {
        cudaStreamCreateWithFlags(&s2, cudaStreamNonBlocking);
        cudaEventCreateWithFlags(&evF, cudaEventDisableTiming);
        cudaEventCreateWithFlags(&evW1, cudaEventDisableTiming);
        cudaEventCreateWithFlags(&evW, cudaEventDisableTiming);
        cudaEventCreateWithFlags(&evJ, cudaEventDisableTiming);
        cudaFuncSetAttribute(dual_mma, cudaFuncAttributeMaxDynamicSharedMemorySize, SMEM_BYTES);
        cudaFuncSetAttribute(hgemm<1,0,0,1>, cudaFuncAttributeMaxDynamicSharedMemorySize, HSMEM);
        cudaFuncSetAttribute(hgemm<0,0,1,1>, cudaFuncAttributeMaxDynamicSharedMemorySize, HSMEM);
        cudaFuncSetAttribute(hgemm<0,1,0,0>, cudaFuncAttributeMaxDynamicSharedMemorySize, HSMEM);
        cudaFuncSetAttribute(hgemm<0,2,0,0>, cudaFuncAttributeMaxDynamicSharedMemorySize, HSMEM);
    }

    // ---- fork: side stream does all weight/proto preps ----
    cudaEventRecord(evF, 0);
    cudaStreamWaitEvent(s2, evF, 0);
    wprep<<<dim3(NIN / 32, 256 / 32), 256, 0, s2>>>(W1, W1p, NIN, 256);
    cudaEventRecord(evW1, s2);
    wprep<<<dim3(256 / 32, 128 / 32), 256, 0, s2>>>(W2, W2p, 256, 128);
    wprep<<<dim3(128 / 32, 512 / 32), 256, 0, s2>>>(fw1, fw1p, 128, 512);
    wprep<<<dim3(512 / 32, 128 / 32), 256, 0, s2>>>(fw2, fw2p, 512, 128);
    fold_w<<<ND + 1, 128, 0, s2>>>(in_w, out_w, in_b, out_b);
    wprep<<<dim3(128 / 32, 128 / 32), 256, 0, s2>>>(Wp, Wpp, 128, 128);
    cudaEventRecord(evW, s2);
    proto_prep<<<NC2, 128, 0, s2>>>(protos, logc);
    euc_prep <<<NC2 / 64, 256, 0, s2>>>(euc_w, euc_b);
    cudaEventRecord(evJ, s2);

    // ---- main stream: activation split + front-end chain ----
    asplit<<<NB, 256>>>(x, xsp, NIN);
    cudaStreamWaitEvent(0, evW1, 0);
    hgemm<1,0,0,1><<<dim3(2, NB / 64), 256, HSMEM>>>(
        xsp, W1p, b1, nullptr, t1sp, nullptr, nullptr, nullptr, nullptr,
        nullptr, nullptr, nullptr, 3072, 256);
    cudaStreamWaitEvent(0, evW, 0);
    hgemm<0,0,1,1><<<dim3(1, NB / 64), 256, HSMEM>>>(
        t1sp, W2p, b2, t, tsp, nullptr, nullptr, nullptr, nullptr,
        nullptr, nullptr, nullptr, 768, 128);
    hgemm<0,1,0,0><<<dim3(1, NB / 64), 256, HSMEM>>>(
        tsp, Wpp, bp, xs, xssp, t, g1, bt1, nullptr,
        nullptr, nullptr, nullptr, 384, 128);
    hgemm<1,0,0,1><<<dim3(4, NB / 64), 256, HSMEM>>>(
        xssp, fw1p, fb1, nullptr, hsp, nullptr, nullptr, nullptr, nullptr,
        nullptr, nullptr, nullptr, 384, 512);
    hgemm<0,2,0,0><<<dim3(1, NB / 64), 256, HSMEM>>>(
        hsp, fw2p, fb2, emb, Ay, xs, g2, bt2, logc,
        e2, de, ke, 1536, 128);

    // ---- join, then head ----
    cudaStreamWaitEvent(0, evJ, 0);
    dual_mma<<<dim3(NC2 / 128, NB / 128, 2), 256, SMEM_BYTES>>>(e2, de, ke, logc, hyp, euc);
}